// round 11
// baseline (speedup 1.0000x reference)
#include <cuda_runtime.h>
#include <math.h>
#include <stdint.h>

// ---------------- problem constants ----------------
#define DIMN   3072
#define HEADS  24
#define HD     128
#define S_HID  3072
#define S_ENC  512
#define SEQ    3584          // S_ENC + S_HID
#define CONDN  1024
#define RANKN  64
#define BLOCKL 2048          // S_HID - CONDN
#define NROWS_C (SEQ - S_ENC - CONDN)   // 2048 fully-masked query rows
#define KSPLIT 16            // split-K for LoRA down-proj
static const float ATTN_SCALE = 0.08838834764831843f; // 1/sqrt(128)

// ---------------- device scratch (no allocs allowed) ----------------
__device__ float g_Pq[(size_t)S_HID * DIMN];
__device__ float g_Pk[(size_t)S_HID * DIMN];
__device__ float g_Pv[(size_t)S_HID * DIMN];
__device__ float g_Eq[(size_t)S_ENC * DIMN];
__device__ float g_Ek[(size_t)S_ENC * DIMN];
__device__ float g_Ev[(size_t)S_ENC * DIMN];
__device__ float g_Dt[(size_t)CONDN * RANKN];
__device__ float g_DtP[(size_t)KSPLIT * CONDN * RANKN];  // split-K partials
__device__ float g_Q [(size_t)HEADS * SEQ * HD];
__device__ float g_K [(size_t)HEADS * SEQ * HD];
__device__ float g_Vt[(size_t)HEADS * HD * SEQ];      // V transposed: [h][d][s]
__device__ float g_SA[(size_t)HEADS * S_ENC * SEQ];   // encoder-query scores
__device__ float g_SB[(size_t)HEADS * CONDN * CONDN]; // cond-block scores
__device__ float g_AO[(size_t)(S_ENC + CONDN) * DIMN];// attention out rows 0..1535
__device__ float g_mean[DIMN];
__device__ float g_vec [DIMN];

// ---------------- helpers ----------------
__device__ __forceinline__ uint32_t f2tf(float f) {
    uint32_t u;
    asm("cvt.rna.tf32.f32 %0, %1;" : "=r"(u) : "f"(f));
    return u;
}

__device__ __forceinline__ void cpasync16(float* dst, const float* src, bool pred) {
    uint32_t d = (uint32_t)__cvta_generic_to_shared(dst);
    int sz = pred ? 16 : 0;   // src-size 0 => zero-fill, no memory access
    asm volatile("cp.async.cg.shared.global [%0], [%1], 16, %2;\n"
                 :: "r"(d), "l"(src), "r"(sz));
}

__device__ __forceinline__ void mma_tf32(float* c, const uint32_t* a, const uint32_t* b) {
    asm volatile(
        "mma.sync.aligned.m16n8k8.row.col.f32.tf32.tf32.f32 "
        "{%0,%1,%2,%3}, {%4,%5,%6,%7}, {%8,%9}, {%0,%1,%2,%3};\n"
        : "+f"(c[0]), "+f"(c[1]), "+f"(c[2]), "+f"(c[3])
        : "r"(a[0]), "r"(a[1]), "r"(a[2]), "r"(a[3]), "r"(b[0]), "r"(b[1]));
}

// ---------------- tf32 tensor-core GEMM ----------------
// C = alpha * A[M,K] * B[N,K]^T (+bias, +beta*C).  A,B row-major, leading dims
// lda/ldb; batch via blockIdx.z with strides sA/sB/sC (also used for split-K).
// Warp grid: WMC m-warps x (THREADS/32/WMC) n-warps; warp tile (MT*16) x (NT*8).
// BIG:   128x64 tile, 256 thr, warp 32x32, 4-stage, OCC=3 (24 warps/SM)
// SMALL:  64x64 tile, 128 thr, warp 32x32, 5-stage, OCC=4 (16 warps/SM)
#define BK 16
#define ASTR 20   // smem row stride (floats)

template <int TBM, int TBN, int THREADS, int NSTAGE, int MT, int NT, int WMC, int OCC>
__global__ __launch_bounds__(THREADS, OCC)
void gemm_tf32(const float* __restrict__ A, const float* __restrict__ B,
               const float* __restrict__ bias, float* __restrict__ C,
               int M, int N, int K, int lda, int ldb, int ldc,
               long long sA, long long sB, long long sC,
               float alpha, const float* __restrict__ alpha_ptr, float beta)
{
    constexpr int PF = NSTAGE - 1;
    extern __shared__ float smem[];
    float* As = smem;                          // [NSTAGE][TBM][ASTR]
    float* Bs = smem + NSTAGE * TBM * ASTR;    // [NSTAGE][TBN][ASTR]

    const float* Ab = A + (long long)blockIdx.z * sA;
    const float* Bb = B + (long long)blockIdx.z * sB;
    float*       Cb = C + (long long)blockIdx.z * sC;

    const int m0 = blockIdx.y * TBM;
    const int n0 = blockIdx.x * TBN;
    const int tid  = threadIdx.x;
    const int lane = tid & 31;
    const int warp = tid >> 5;
    const int wm = (warp % WMC) * (MT * 16);
    const int wn = (warp / WMC) * (NT * 8);
    const int g  = lane >> 2;               // groupID
    const int tg = lane & 3;                // thread-in-group

    float c[MT][NT][4];
#pragma unroll
    for (int i = 0; i < MT; i++)
#pragma unroll
        for (int j = 0; j < NT; j++)
#pragma unroll
            for (int r = 0; r < 4; r++) c[i][j][r] = 0.f;

    const int nk = K / BK;

    const int lrow = tid >> 2;              // 0..THREADS/4-1
    const int lkc  = (tid & 3) << 2;        // 0,4,8,12
    constexpr int RJUMP = THREADS / 4;

    auto load_tile = [&](int k0, int buf) {
        float* Ad = As + buf * TBM * ASTR;
        float* Bd = Bs + buf * TBN * ASTR;
#pragma unroll
        for (int j = 0; j < TBM / RJUMP; j++) {
            const int row = lrow + j * RJUMP;
            cpasync16(Ad + row * ASTR + lkc,
                      Ab + (long long)(m0 + row) * lda + k0 + lkc,
                      (m0 + row) < M);
        }
#pragma unroll
        for (int j = 0; j < TBN / RJUMP; j++) {
            const int row = lrow + j * RJUMP;
            cpasync16(Bd + row * ASTR + lkc,
                      Bb + (long long)(n0 + row) * ldb + k0 + lkc,
                      (n0 + row) < N);
        }
        asm volatile("cp.async.commit_group;\n");
    };

    for (int s = 0; s < PF; s++) {
        if (s < nk) load_tile(s * BK, s);
        else        asm volatile("cp.async.commit_group;\n");
    }

    for (int it = 0; it < nk; it++) {
        if (it + PF < nk) load_tile((it + PF) * BK, (it + PF) % NSTAGE);
        else              asm volatile("cp.async.commit_group;\n");
        asm volatile("cp.async.wait_group %0;\n" :: "n"(PF));
        __syncthreads();

        const int buf = it % NSTAGE;
        const float* Ac = As + buf * TBM * ASTR;
        const float* Bc = Bs + buf * TBN * ASTR;

#pragma unroll
        for (int ks = 0; ks < BK; ks += 8) {
            uint32_t bf[NT][2];
#pragma unroll
            for (int nt = 0; nt < NT; nt++) {
                const float* bp = Bc + (wn + nt * 8 + g) * ASTR + ks + tg;
                bf[nt][0] = f2tf(bp[0]);
                bf[nt][1] = f2tf(bp[4]);
            }
            uint32_t af[MT][4];
#pragma unroll
            for (int mt = 0; mt < MT; mt++) {
                const float* ap = Ac + (wm + mt * 16 + g) * ASTR + ks + tg;
                af[mt][0] = f2tf(ap[0]);
                af[mt][1] = f2tf(ap[8 * ASTR]);
                af[mt][2] = f2tf(ap[4]);
                af[mt][3] = f2tf(ap[8 * ASTR + 4]);
            }
#pragma unroll
            for (int mt = 0; mt < MT; mt++)
#pragma unroll
                for (int nt = 0; nt < NT; nt++)
                    mma_tf32(c[mt][nt], af[mt], bf[nt]);
        }
        __syncthreads();
    }

    float aE = alpha;
    if (alpha_ptr) aE *= *alpha_ptr;

#pragma unroll
    for (int mt = 0; mt < MT; mt++) {
#pragma unroll
        for (int r = 0; r < 2; r++) {
            const int gm = m0 + wm + mt * 16 + g + r * 8;
            if (gm >= M) continue;
            float* crow = Cb + (long long)gm * ldc;
#pragma unroll
            for (int nt = 0; nt < NT; nt++) {
                const int gn = n0 + wn + nt * 8 + tg * 2;
                if (gn >= N) continue;
                float x = c[mt][nt][r * 2 + 0] * aE;
                float y = c[mt][nt][r * 2 + 1] * aE;
                if (bias) { x += bias[gn]; y += bias[gn + 1]; }
                if (beta != 0.f) {
                    float2 p = *(const float2*)(crow + gn);
                    x += beta * p.x; y += beta * p.y;
                }
                *(float2*)(crow + gn) = make_float2(x, y);
            }
        }
    }
}

// BIG:   128x64, 256 thr, 4 stages, MT2 NT4 WMC4, OCC3
// SMALL:  64x64, 128 thr, 5 stages, MT2 NT4 WMC2, OCC4
#define BIG_SMEM   (4 * (128 + 64) * ASTR * 4)
#define SMALL_SMEM (5 * ( 64 + 64) * ASTR * 4)

// ---------------- elementwise kernels ----------------
__global__ void build_qkv(const float* __restrict__ Pq, const float* __restrict__ Pk,
                          const float* __restrict__ Pv, const float* __restrict__ Eq,
                          const float* __restrict__ Ek, const float* __restrict__ Ev,
                          const float* __restrict__ rc, const float* __restrict__ rs,
                          const float* __restrict__ nqw, const float* __restrict__ nkw,
                          const float* __restrict__ naqw, const float* __restrict__ nakw,
                          float* __restrict__ Q, float* __restrict__ K, float* __restrict__ Vt)
{
    const int s = blockIdx.x;
    const int h = blockIdx.y;
    const int d = threadIdx.x;

    const float *sq, *sk, *sv, *wq, *wk;
    if (s < S_ENC) {
        const long long off = (long long)s * DIMN + h * HD;
        sq = Eq + off; sk = Ek + off; sv = Ev + off;
        wq = naqw; wk = nakw;
    } else {
        const long long off = (long long)(s - S_ENC) * DIMN + h * HD;
        sq = Pq + off; sk = Pk + off; sv = Pv + off;
        wq = nqw; wk = nkw;
    }
    float q = sq[d], k = sk[d], v = sv[d];

    float ssq = q * q, ssk = k * k;
#pragma unroll
    for (int o = 16; o; o >>= 1) {
        ssq += __shfl_xor_sync(0xffffffffu, ssq, o);
        ssk += __shfl_xor_sync(0xffffffffu, ssk, o);
    }
    __shared__ float shq[4], shk[4];
    const int w = d >> 5;
    if ((d & 31) == 0) { shq[w] = ssq; shk[w] = ssk; }
    __syncthreads();
    const float tq = shq[0] + shq[1] + shq[2] + shq[3];
    const float tk = shk[0] + shk[1] + shk[2] + shk[3];

    const float qn = q * rsqrtf(tq * (1.0f / HD) + 1e-6f) * wq[d];
    const float kn = k * rsqrtf(tk * (1.0f / HD) + 1e-6f) * wk[d];

    const float qp = __shfl_xor_sync(0xffffffffu, qn, 1);
    const float kp = __shfl_xor_sync(0xffffffffu, kn, 1);
    const float qr = (d & 1) ? qp : -qp;
    const float kr = (d & 1) ? kp : -kp;

    const float cc = rc[(long long)s * HD + d];
    const float sn = rs[(long long)s * HD + d];

    const long long o = ((long long)h * SEQ + s) * HD + d;
    Q[o] = qn * cc + qr * sn;
    K[o] = kn * cc + kr * sn;
    Vt[((long long)h * HD + d) * SEQ + s] = v;
}

__global__ void softmax_k(float* __restrict__ S, int ncols)
{
    float* r = S + (long long)blockIdx.x * ncols;
    const int tid = threadIdx.x;
    __shared__ float sh[8];

    float m = -INFINITY;
    for (int c = tid; c < ncols; c += 256) m = fmaxf(m, r[c]);
#pragma unroll
    for (int o = 16; o; o >>= 1) m = fmaxf(m, __shfl_xor_sync(0xffffffffu, m, o));
    if ((tid & 31) == 0) sh[tid >> 5] = m;
    __syncthreads();
    float bm = sh[0];
#pragma unroll
    for (int i = 1; i < 8; i++) bm = fmaxf(bm, sh[i]);
    __syncthreads();

    float sum = 0.f;
    for (int c = tid; c < ncols; c += 256) {
        float e = expf(r[c] - bm);
        r[c] = e;
        sum += e;
    }
#pragma unroll
    for (int o = 16; o; o >>= 1) sum += __shfl_xor_sync(0xffffffffu, sum, o);
    if ((tid & 31) == 0) sh[tid >> 5] = sum;
    __syncthreads();
    float bs = 0.f;
#pragma unroll
    for (int i = 0; i < 8; i++) bs += sh[i];
    const float inv = 1.0f / bs;
    for (int c = tid; c < ncols; c += 256) r[c] *= inv;
}

__global__ void mean_k(const float* __restrict__ Vt, float* __restrict__ mean)
{
    const int row = blockIdx.x;
    const float* r = Vt + (long long)row * SEQ;
    const int tid = threadIdx.x;
    float s = 0.f;
    for (int c = tid; c < SEQ; c += 256) s += r[c];
#pragma unroll
    for (int o = 16; o; o >>= 1) s += __shfl_xor_sync(0xffffffffu, s, o);
    __shared__ float sh[8];
    if ((tid & 31) == 0) sh[tid >> 5] = s;
    __syncthreads();
    if (tid == 0) {
        float t = 0.f;
#pragma unroll
        for (int i = 0; i < 8; i++) t += sh[i];
        mean[row] = t * (1.0f / SEQ);
    }
}

__global__ void gemv_out(const float* __restrict__ mean, const float* __restrict__ Wo,
                         const float* __restrict__ bo, float* __restrict__ vec)
{
    const int j = blockIdx.x * 8 + (threadIdx.x >> 5);
    const int lane = threadIdx.x & 31;
    const float* w = Wo + (long long)j * DIMN;
    float s = 0.f;
    for (int d = lane; d < DIMN; d += 32) s += mean[d] * w[d];
#pragma unroll
    for (int o = 16; o; o >>= 1) s += __shfl_xor_sync(0xffffffffu, s, o);
    if (lane == 0) vec[j] = s + bo[j];
}

__global__ void fill_rows(const float* __restrict__ vec, float* __restrict__ out)
{
    const long long i = (long long)blockIdx.x * 256 + threadIdx.x;
    const float4 v = ((const float4*)vec)[i % (DIMN / 4)];
    ((float4*)out)[i] = v;
}

__global__ void reduce_splitk(const float* __restrict__ P, float* __restrict__ D)
{
    const int i = blockIdx.x * 256 + threadIdx.x;
    float s = 0.f;
#pragma unroll
    for (int z = 0; z < KSPLIT; z++) s += P[(size_t)z * CONDN * RANKN + i];
    D[i] = s;
}

// ---------------- host-side launch helpers ----------------
static void gemm_big(const float* A, const float* B, const float* bias, float* C,
                     int M, int N, int K, int lda, int ldb, int ldc,
                     long long sA, long long sB, long long sC, int batch,
                     float alpha, const float* aptr, float beta)
{
    dim3 gdim((N + 63) / 64, (M + 127) / 128, batch);
    gemm_tf32<128, 64, 256, 4, 2, 4, 4, 3><<<gdim, 256, BIG_SMEM>>>(
        A, B, bias, C, M, N, K, lda, ldb, ldc, sA, sB, sC, alpha, aptr, beta);
}

static void gemm_small(const float* A, const float* B, const float* bias, float* C,
                       int M, int N, int K, int lda, int ldb, int ldc,
                       long long sA, long long sB, long long sC, int batch,
                       float alpha, const float* aptr, float beta)
{
    dim3 gdim((N + 63) / 64, (M + 63) / 64, batch);
    gemm_tf32<64, 64, 128, 5, 2, 4, 2, 4><<<gdim, 128, SMALL_SMEM>>>(
        A, B, bias, C, M, N, K, lda, ldb, ldc, sA, sB, sC, alpha, aptr, beta);
}

extern "C" void kernel_launch(void* const* d_in, const int* in_sizes, int n_in,
                              void* d_out, int out_size)
{
    const float* hidden = (const float*)d_in[0];
    const float* enc    = (const float*)d_in[1];
    const float* rc     = (const float*)d_in[2];
    const float* rs     = (const float*)d_in[3];
    const float* Wq  = (const float*)d_in[4];
    const float* Wk  = (const float*)d_in[5];
    const float* Wv  = (const float*)d_in[6];
    const float* Wqa = (const float*)d_in[7];
    const float* Wka = (const float*)d_in[8];
    const float* Wva = (const float*)d_in[9];
    const float* Wo  = (const float*)d_in[10];
    const float* Woa = (const float*)d_in[11];
    const float* bq  = (const float*)d_in[12];
    const float* bk  = (const float*)d_in[13];
    const float* bv  = (const float*)d_in[14];
    const float* bqa = (const float*)d_in[15];
    const float* bka = (const float*)d_in[16];
    const float* bva = (const float*)d_in[17];
    const float* bo  = (const float*)d_in[18];
    const float* boa = (const float*)d_in[19];
    const float* nqw  = (const float*)d_in[20];
    const float* nkw  = (const float*)d_in[21];
    const float* naqw = (const float*)d_in[22];
    const float* nakw = (const float*)d_in[23];
    const float* qd = (const float*)d_in[24];
    const float* kd = (const float*)d_in[25];
    const float* vd = (const float*)d_in[26];
    const float* qu = (const float*)d_in[27];
    const float* ku = (const float*)d_in[28];
    const float* vu = (const float*)d_in[29];
    const float* lw = (const float*)d_in[30];

    float *Pq, *Pk, *Pv, *Eq, *Ek, *Ev, *Dt, *DtP, *Q, *K, *Vt, *SA, *SB, *AO, *mean, *vec;
    cudaGetSymbolAddress((void**)&Pq, g_Pq);
    cudaGetSymbolAddress((void**)&Pk, g_Pk);
    cudaGetSymbolAddress((void**)&Pv, g_Pv);
    cudaGetSymbolAddress((void**)&Eq, g_Eq);
    cudaGetSymbolAddress((void**)&Ek, g_Ek);
    cudaGetSymbolAddress((void**)&Ev, g_Ev);
    cudaGetSymbolAddress((void**)&Dt, g_Dt);
    cudaGetSymbolAddress((void**)&DtP, g_DtP);
    cudaGetSymbolAddress((void**)&Q,  g_Q);
    cudaGetSymbolAddress((void**)&K,  g_K);
    cudaGetSymbolAddress((void**)&Vt, g_Vt);
    cudaGetSymbolAddress((void**)&SA, g_SA);
    cudaGetSymbolAddress((void**)&SB, g_SB);
    cudaGetSymbolAddress((void**)&AO, g_AO);
    cudaGetSymbolAddress((void**)&mean, g_mean);
    cudaGetSymbolAddress((void**)&vec,  g_vec);

    float* out = (float*)d_out;

    // opt-in to >48KB dynamic smem (required — launches fail without it)
    cudaFuncSetAttribute(gemm_tf32<128, 64, 256, 4, 2, 4, 4, 3>,
                         cudaFuncAttributeMaxDynamicSharedMemorySize, BIG_SMEM);
    cudaFuncSetAttribute(gemm_tf32<64, 64, 128, 5, 2, 4, 2, 4>,
                         cudaFuncAttributeMaxDynamicSharedMemorySize, SMALL_SMEM);

    // 1) image-side base projections: P = hidden @ W^T + b  (BIG, grid 1152)
    gemm_big(hidden, Wq, bq, Pq, S_HID, DIMN, DIMN, DIMN, DIMN, DIMN, 0, 0, 0, 1, 1.f, nullptr, 0.f);
    gemm_big(hidden, Wk, bk, Pk, S_HID, DIMN, DIMN, DIMN, DIMN, DIMN, 0, 0, 0, 1, 1.f, nullptr, 0.f);
    gemm_big(hidden, Wv, bv, Pv, S_HID, DIMN, DIMN, DIMN, DIMN, DIMN, 0, 0, 0, 1, 1.f, nullptr, 0.f);

    // 2) encoder projections (M=512 -> SMALL, grid 384)
    gemm_small(enc, Wqa, bqa, Eq, S_ENC, DIMN, DIMN, DIMN, DIMN, DIMN, 0, 0, 0, 1, 1.f, nullptr, 0.f);
    gemm_small(enc, Wka, bka, Ek, S_ENC, DIMN, DIMN, DIMN, DIMN, DIMN, 0, 0, 0, 1, 1.f, nullptr, 0.f);
    gemm_small(enc, Wva, bva, Ev, S_ENC, DIMN, DIMN, DIMN, DIMN, DIMN, 0, 0, 0, 1, 1.f, nullptr, 0.f);

    // 3) LoRA: only hidden rows [2048,3072) survive; sc = lora_w[0]*ALPHA/RANK = lora_w[0]
    const float* downs[3] = {qd, kd, vd};
    const float* ups[3]   = {qu, ku, vu};
    float* Ps[3]          = {Pq, Pk, Pv};
    for (int i = 0; i < 3; i++) {
        gemm_small(hidden + (long long)BLOCKL * DIMN, downs[i], nullptr, DtP,
                   CONDN, RANKN, DIMN / KSPLIT, DIMN, DIMN, RANKN,
                   DIMN / KSPLIT, DIMN / KSPLIT, (long long)CONDN * RANKN, KSPLIT,
                   1.f, nullptr, 0.f);
        reduce_splitk<<<(CONDN * RANKN) / 256, 256>>>(DtP, Dt);
        gemm_small(Dt, ups[i], nullptr, Ps[i] + (long long)BLOCKL * DIMN,
                   CONDN, DIMN, RANKN, RANKN, RANKN, DIMN, 0, 0, 0, 1, 1.f, lw, 1.f);
    }

    // 4) heads + RMSNorm + RoPE + concat; V written transposed
    build_qkv<<<dim3(SEQ, HEADS), HD>>>(Pq, Pk, Pv, Eq, Ek, Ev, rc, rs,
                                        nqw, nkw, naqw, nakw, Q, K, Vt);

    // 5) block A: encoder queries vs full keys (BIG, grid 56x4x24)
    gemm_big(Q, K, nullptr, SA, S_ENC, SEQ, HD, HD, HD, SEQ,
             (long long)SEQ * HD, (long long)SEQ * HD, (long long)S_ENC * SEQ, HEADS,
             ATTN_SCALE, nullptr, 0.f);
    softmax_k<<<HEADS * S_ENC, 256>>>(SA, SEQ);
    gemm_small(SA, Vt, nullptr, AO, S_ENC, HD, SEQ, SEQ, SEQ, DIMN,
               (long long)S_ENC * SEQ, (long long)HD * SEQ, HD, HEADS, 1.f, nullptr, 0.f);

    // 6) block B: cond queries vs cond keys
    gemm_big(Q + (long long)S_ENC * HD, K + (long long)S_ENC * HD, nullptr, SB,
             CONDN, CONDN, HD, HD, HD, CONDN,
             (long long)SEQ * HD, (long long)SEQ * HD, (long long)CONDN * CONDN, HEADS,
             ATTN_SCALE, nullptr, 0.f);
    softmax_k<<<HEADS * CONDN, 256>>>(SB, CONDN);
    gemm_small(SB, Vt + S_ENC, nullptr, AO + (long long)S_ENC * DIMN,
               CONDN, HD, CONDN, CONDN, SEQ, DIMN,
               (long long)CONDN * CONDN, (long long)HD * SEQ, HD, HEADS, 1.f, nullptr, 0.f);

    // 7) fully-masked rows -> uniform softmax -> mean of V; one out-proj row
    mean_k<<<DIMN, 256>>>(Vt, mean);
    gemv_out<<<DIMN / 8, 256>>>(mean, Wo, bo, vec);

    // 8) output projections
    gemm_big(AO + (long long)S_ENC * DIMN, Wo, bo, out,
             CONDN, DIMN, DIMN, DIMN, DIMN, DIMN, 0, 0, 0, 1, 1.f, nullptr, 0.f);
    fill_rows<<<(NROWS_C * (DIMN / 4)) / 256, 256>>>(vec, out + (long long)CONDN * DIMN);
    gemm_small(AO, Woa, boa, out + (long long)S_HID * DIMN,
               S_ENC, DIMN, DIMN, DIMN, DIMN, DIMN, 0, 0, 0, 1, 1.f, nullptr, 0.f);
}

// round 12
// speedup vs baseline: 1.0629x; 1.0629x over previous
#include <cuda_runtime.h>
#include <math.h>
#include <stdint.h>

// ---------------- problem constants ----------------
#define DIMN   3072
#define HEADS  24
#define HD     128
#define S_HID  3072
#define S_ENC  512
#define SEQ    3584          // S_ENC + S_HID
#define CONDN  1024
#define RANKN  64
#define BLOCKL 2048          // S_HID - CONDN
#define NROWS_C (SEQ - S_ENC - CONDN)   // 2048 fully-masked query rows
#define KSPLIT 16            // split-K for LoRA down-proj
static const float ATTN_SCALE = 0.08838834764831843f; // 1/sqrt(128)

// ---------------- device scratch (no allocs allowed) ----------------
__device__ float g_Pq[(size_t)S_HID * DIMN];
__device__ float g_Pk[(size_t)S_HID * DIMN];
__device__ float g_Pv[(size_t)S_HID * DIMN];
__device__ float g_Eq[(size_t)S_ENC * DIMN];
__device__ float g_Ek[(size_t)S_ENC * DIMN];
__device__ float g_Ev[(size_t)S_ENC * DIMN];
__device__ float g_Dt [(size_t)3 * CONDN * RANKN];
__device__ float g_DtP[(size_t)3 * KSPLIT * CONDN * RANKN];
__device__ float g_Q [(size_t)HEADS * SEQ * HD];
__device__ float g_K [(size_t)HEADS * SEQ * HD];
__device__ float g_Vt[(size_t)HEADS * HD * SEQ];      // V transposed: [h][d][s]
__device__ float g_SA[(size_t)HEADS * S_ENC * SEQ];   // encoder-query scores
__device__ float g_SB[(size_t)HEADS * CONDN * CONDN]; // cond-block scores
__device__ float g_AO[(size_t)(S_ENC + CONDN) * DIMN];// attention out rows 0..1535
__device__ float g_mean[DIMN];
__device__ float g_vec [DIMN];

// pointer tables for batched GEMM groups: [0..2]=qkv-proj, [3..5]=enc-proj,
// [6..8]=lora-down, [9..11]=lora-up
__device__ const float* g_tA[12];
__device__ const float* g_tB[12];
__device__ const float* g_tbias[12];
__device__ float*       g_tC[12];

// ---------------- helpers ----------------
__device__ __forceinline__ uint32_t f2tf(float f) {
    uint32_t u;
    asm("cvt.rna.tf32.f32 %0, %1;" : "=r"(u) : "f"(f));
    return u;
}

__device__ __forceinline__ void cpasync16(float* dst, const float* src, bool pred) {
    uint32_t d = (uint32_t)__cvta_generic_to_shared(dst);
    int sz = pred ? 16 : 0;   // src-size 0 => zero-fill, no memory access
    asm volatile("cp.async.cg.shared.global [%0], [%1], 16, %2;\n"
                 :: "r"(d), "l"(src), "r"(sz));
}

__device__ __forceinline__ void mma_tf32(float* c, const uint32_t* a, const uint32_t* b) {
    asm volatile(
        "mma.sync.aligned.m16n8k8.row.col.f32.tf32.tf32.f32 "
        "{%0,%1,%2,%3}, {%4,%5,%6,%7}, {%8,%9}, {%0,%1,%2,%3};\n"
        : "+f"(c[0]), "+f"(c[1]), "+f"(c[2]), "+f"(c[3])
        : "r"(a[0]), "r"(a[1]), "r"(a[2]), "r"(a[3]), "r"(b[0]), "r"(b[1]));
}

// ---------------- tf32 tensor-core GEMM ----------------
// C = alpha * A[M,K] * B[N,K]^T (+bias, +beta*C).  A,B row-major.
// TAB=false: operands from plain pointers with blockIdx.z * stride (batch / split-K).
// TAB=true : operands from pointer tables indexed by zi=blockIdx.z/zdiv, with the
//            remainder zr applying the elem strides (split-K within each table entry).
#define BK 16
#define ASTR 20   // smem row stride (floats) — conflict-free fragment reads

template <int TBM, int TBN, int THREADS, int NSTAGE, int MT, int NT, int WMC, int OCC, bool TAB>
__global__ __launch_bounds__(THREADS, OCC)
void gemm_tf32(const float* __restrict__ A, const float* __restrict__ B,
               const float* __restrict__ bias, float* __restrict__ C,
               const float* const* __restrict__ Aarr,
               const float* const* __restrict__ Barr,
               const float* const* __restrict__ biasarr,
               float* const* __restrict__ Carr, int zdiv,
               int M, int N, int K, int lda, int ldb, int ldc,
               long long sA, long long sB, long long sC,
               float alpha, const float* __restrict__ alpha_ptr, float beta)
{
    constexpr int PF = NSTAGE - 1;
    extern __shared__ float smem[];
    float* As = smem;                          // [NSTAGE][TBM][ASTR]
    float* Bs = smem + NSTAGE * TBM * ASTR;    // [NSTAGE][TBN][ASTR]

    const float* Ab;
    const float* Bb;
    float*       Cb;
    const float* biasb;
    if (TAB) {
        const int zi = blockIdx.z / zdiv;
        const int zr = blockIdx.z - zi * zdiv;
        Ab = Aarr[zi] + (long long)zr * sA;
        Bb = Barr[zi] + (long long)zr * sB;
        Cb = Carr[zi] + (long long)zr * sC;
        biasb = biasarr[zi];
    } else {
        Ab = A + (long long)blockIdx.z * sA;
        Bb = B + (long long)blockIdx.z * sB;
        Cb = C + (long long)blockIdx.z * sC;
        biasb = bias;
    }

    const int m0 = blockIdx.y * TBM;
    const int n0 = blockIdx.x * TBN;
    const int tid  = threadIdx.x;
    const int lane = tid & 31;
    const int warp = tid >> 5;
    const int wm = (warp % WMC) * (MT * 16);
    const int wn = (warp / WMC) * (NT * 8);
    const int g  = lane >> 2;               // groupID
    const int tg = lane & 3;                // thread-in-group

    float c[MT][NT][4];
#pragma unroll
    for (int i = 0; i < MT; i++)
#pragma unroll
        for (int j = 0; j < NT; j++)
#pragma unroll
            for (int r = 0; r < 4; r++) c[i][j][r] = 0.f;

    const int nk = K / BK;

    const int lrow = tid >> 2;              // 0..THREADS/4-1
    const int lkc  = (tid & 3) << 2;        // 0,4,8,12
    constexpr int RJUMP = THREADS / 4;

    auto load_tile = [&](int k0, int buf) {
        float* Ad = As + buf * TBM * ASTR;
        float* Bd = Bs + buf * TBN * ASTR;
#pragma unroll
        for (int j = 0; j < TBM / RJUMP; j++) {
            const int row = lrow + j * RJUMP;
            cpasync16(Ad + row * ASTR + lkc,
                      Ab + (long long)(m0 + row) * lda + k0 + lkc,
                      (m0 + row) < M);
        }
#pragma unroll
        for (int j = 0; j < TBN / RJUMP; j++) {
            const int row = lrow + j * RJUMP;
            cpasync16(Bd + row * ASTR + lkc,
                      Bb + (long long)(n0 + row) * ldb + k0 + lkc,
                      (n0 + row) < N);
        }
        asm volatile("cp.async.commit_group;\n");
    };

    for (int s = 0; s < PF; s++) {
        if (s < nk) load_tile(s * BK, s);
        else        asm volatile("cp.async.commit_group;\n");
    }

    for (int it = 0; it < nk; it++) {
        if (it + PF < nk) load_tile((it + PF) * BK, (it + PF) & (NSTAGE - 1));
        else              asm volatile("cp.async.commit_group;\n");
        asm volatile("cp.async.wait_group %0;\n" :: "n"(PF));
        __syncthreads();

        const int buf = it & (NSTAGE - 1);
        const float* Ac = As + buf * TBM * ASTR;
        const float* Bc = Bs + buf * TBN * ASTR;

#pragma unroll
        for (int ks = 0; ks < BK; ks += 8) {
            uint32_t bf[NT][2];
#pragma unroll
            for (int nt = 0; nt < NT; nt++) {
                const float* bp = Bc + (wn + nt * 8 + g) * ASTR + ks + tg;
                bf[nt][0] = f2tf(bp[0]);
                bf[nt][1] = f2tf(bp[4]);
            }
            uint32_t af[MT][4];
#pragma unroll
            for (int mt = 0; mt < MT; mt++) {
                const float* ap = Ac + (wm + mt * 16 + g) * ASTR + ks + tg;
                af[mt][0] = f2tf(ap[0]);
                af[mt][1] = f2tf(ap[8 * ASTR]);
                af[mt][2] = f2tf(ap[4]);
                af[mt][3] = f2tf(ap[8 * ASTR + 4]);
            }
#pragma unroll
            for (int mt = 0; mt < MT; mt++)
#pragma unroll
                for (int nt = 0; nt < NT; nt++)
                    mma_tf32(c[mt][nt], af[mt], bf[nt]);
        }
        __syncthreads();
    }

    float aE = alpha;
    if (alpha_ptr) aE *= *alpha_ptr;

#pragma unroll
    for (int mt = 0; mt < MT; mt++) {
#pragma unroll
        for (int r = 0; r < 2; r++) {
            const int gm = m0 + wm + mt * 16 + g + r * 8;
            if (gm >= M) continue;
            float* crow = Cb + (long long)gm * ldc;
#pragma unroll
            for (int nt = 0; nt < NT; nt++) {
                const int gn = n0 + wn + nt * 8 + tg * 2;
                if (gn >= N) continue;
                float x = c[mt][nt][r * 2 + 0] * aE;
                float y = c[mt][nt][r * 2 + 1] * aE;
                if (biasb) { x += biasb[gn]; y += biasb[gn + 1]; }
                if (beta != 0.f) {
                    float2 p = *(const float2*)(crow + gn);
                    x += beta * p.x; y += beta * p.y;
                }
                *(float2*)(crow + gn) = make_float2(x, y);
            }
        }
    }
}

// BIG:   128x64, 256 thr, 4 stages, MT2 NT4 WMC4, OCC3
// SMALL:  64x64, 128 thr, 4 stages, MT2 NT4 WMC2, OCC4
#define BIG_SMEM   (4 * (128 + 64) * ASTR * 4)
#define SMALL_SMEM (4 * ( 64 + 64) * ASTR * 4)

// ---------------- setup kernel: fill the pointer tables ----------------
__global__ void setup_tabs(const float* hidden, const float* enc,
                           const float* Wq, const float* Wk, const float* Wv,
                           const float* Wqa, const float* Wka, const float* Wva,
                           const float* bq, const float* bk, const float* bv,
                           const float* bqa, const float* bka, const float* bva,
                           const float* qd, const float* kd, const float* vd,
                           const float* qu, const float* ku, const float* vu)
{
    // group 0: image q/k/v projections
    g_tA[0] = hidden; g_tA[1] = hidden; g_tA[2] = hidden;
    g_tB[0] = Wq; g_tB[1] = Wk; g_tB[2] = Wv;
    g_tC[0] = g_Pq; g_tC[1] = g_Pk; g_tC[2] = g_Pv;
    g_tbias[0] = bq; g_tbias[1] = bk; g_tbias[2] = bv;
    // group 1: encoder projections
    g_tA[3] = enc; g_tA[4] = enc; g_tA[5] = enc;
    g_tB[3] = Wqa; g_tB[4] = Wka; g_tB[5] = Wva;
    g_tC[3] = g_Eq; g_tC[4] = g_Ek; g_tC[5] = g_Ev;
    g_tbias[3] = bqa; g_tbias[4] = bka; g_tbias[5] = bva;
    // group 2: LoRA down (A = masked hidden rows, split-K via zr)
    const float* hm = hidden + (long long)BLOCKL * DIMN;
    g_tA[6] = hm; g_tA[7] = hm; g_tA[8] = hm;
    g_tB[6] = qd; g_tB[7] = kd; g_tB[8] = vd;
    g_tC[6] = g_DtP + 0 * (size_t)KSPLIT * CONDN * RANKN;
    g_tC[7] = g_DtP + 1 * (size_t)KSPLIT * CONDN * RANKN;
    g_tC[8] = g_DtP + 2 * (size_t)KSPLIT * CONDN * RANKN;
    g_tbias[6] = nullptr; g_tbias[7] = nullptr; g_tbias[8] = nullptr;
    // group 3: LoRA up
    g_tA[9]  = g_Dt + 0 * (size_t)CONDN * RANKN;
    g_tA[10] = g_Dt + 1 * (size_t)CONDN * RANKN;
    g_tA[11] = g_Dt + 2 * (size_t)CONDN * RANKN;
    g_tB[9] = qu; g_tB[10] = ku; g_tB[11] = vu;
    g_tC[9]  = g_Pq + (long long)BLOCKL * DIMN;
    g_tC[10] = g_Pk + (long long)BLOCKL * DIMN;
    g_tC[11] = g_Pv + (long long)BLOCKL * DIMN;
    g_tbias[9] = nullptr; g_tbias[10] = nullptr; g_tbias[11] = nullptr;
}

// ---------------- elementwise kernels ----------------
__global__ void build_qkv(const float* __restrict__ Pq, const float* __restrict__ Pk,
                          const float* __restrict__ Pv, const float* __restrict__ Eq,
                          const float* __restrict__ Ek, const float* __restrict__ Ev,
                          const float* __restrict__ rc, const float* __restrict__ rs,
                          const float* __restrict__ nqw, const float* __restrict__ nkw,
                          const float* __restrict__ naqw, const float* __restrict__ nakw,
                          float* __restrict__ Q, float* __restrict__ K, float* __restrict__ Vt)
{
    const int s = blockIdx.x;
    const int h = blockIdx.y;
    const int d = threadIdx.x;

    const float *sq, *sk, *sv, *wq, *wk;
    if (s < S_ENC) {
        const long long off = (long long)s * DIMN + h * HD;
        sq = Eq + off; sk = Ek + off; sv = Ev + off;
        wq = naqw; wk = nakw;
    } else {
        const long long off = (long long)(s - S_ENC) * DIMN + h * HD;
        sq = Pq + off; sk = Pk + off; sv = Pv + off;
        wq = nqw; wk = nkw;
    }
    float q = sq[d], k = sk[d], v = sv[d];

    float ssq = q * q, ssk = k * k;
#pragma unroll
    for (int o = 16; o; o >>= 1) {
        ssq += __shfl_xor_sync(0xffffffffu, ssq, o);
        ssk += __shfl_xor_sync(0xffffffffu, ssk, o);
    }
    __shared__ float shq[4], shk[4];
    const int w = d >> 5;
    if ((d & 31) == 0) { shq[w] = ssq; shk[w] = ssk; }
    __syncthreads();
    const float tq = shq[0] + shq[1] + shq[2] + shq[3];
    const float tk = shk[0] + shk[1] + shk[2] + shk[3];

    const float qn = q * rsqrtf(tq * (1.0f / HD) + 1e-6f) * wq[d];
    const float kn = k * rsqrtf(tk * (1.0f / HD) + 1e-6f) * wk[d];

    const float qp = __shfl_xor_sync(0xffffffffu, qn, 1);
    const float kp = __shfl_xor_sync(0xffffffffu, kn, 1);
    const float qr = (d & 1) ? qp : -qp;
    const float kr = (d & 1) ? kp : -kp;

    const float cc = rc[(long long)s * HD + d];
    const float sn = rs[(long long)s * HD + d];

    const long long o = ((long long)h * SEQ + s) * HD + d;
    Q[o] = qn * cc + qr * sn;
    K[o] = kn * cc + kr * sn;
    Vt[((long long)h * HD + d) * SEQ + s] = v;
}

__global__ void softmax_k(float* __restrict__ S, int ncols)
{
    float* r = S + (long long)blockIdx.x * ncols;
    const int tid = threadIdx.x;
    __shared__ float sh[8];

    float m = -INFINITY;
    for (int c = tid; c < ncols; c += 256) m = fmaxf(m, r[c]);
#pragma unroll
    for (int o = 16; o; o >>= 1) m = fmaxf(m, __shfl_xor_sync(0xffffffffu, m, o));
    if ((tid & 31) == 0) sh[tid >> 5] = m;
    __syncthreads();
    float bm = sh[0];
#pragma unroll
    for (int i = 1; i < 8; i++) bm = fmaxf(bm, sh[i]);
    __syncthreads();

    float sum = 0.f;
    for (int c = tid; c < ncols; c += 256) {
        float e = expf(r[c] - bm);
        r[c] = e;
        sum += e;
    }
#pragma unroll
    for (int o = 16; o; o >>= 1) sum += __shfl_xor_sync(0xffffffffu, sum, o);
    if ((tid & 31) == 0) sh[tid >> 5] = sum;
    __syncthreads();
    float bs = 0.f;
#pragma unroll
    for (int i = 0; i < 8; i++) bs += sh[i];
    const float inv = 1.0f / bs;
    for (int c = tid; c < ncols; c += 256) r[c] *= inv;
}

__global__ void mean_k(const float* __restrict__ Vt, float* __restrict__ mean)
{
    const int row = blockIdx.x;
    const float* r = Vt + (long long)row * SEQ;
    const int tid = threadIdx.x;
    float s = 0.f;
    for (int c = tid; c < SEQ; c += 256) s += r[c];
#pragma unroll
    for (int o = 16; o; o >>= 1) s += __shfl_xor_sync(0xffffffffu, s, o);
    __shared__ float sh[8];
    if ((tid & 31) == 0) sh[tid >> 5] = s;
    __syncthreads();
    if (tid == 0) {
        float t = 0.f;
#pragma unroll
        for (int i = 0; i < 8; i++) t += sh[i];
        mean[row] = t * (1.0f / SEQ);
    }
}

__global__ void gemv_out(const float* __restrict__ mean, const float* __restrict__ Wo,
                         const float* __restrict__ bo, float* __restrict__ vec)
{
    const int j = blockIdx.x * 8 + (threadIdx.x >> 5);
    const int lane = threadIdx.x & 31;
    const float* w = Wo + (long long)j * DIMN;
    float s = 0.f;
    for (int d = lane; d < DIMN; d += 32) s += mean[d] * w[d];
#pragma unroll
    for (int o = 16; o; o >>= 1) s += __shfl_xor_sync(0xffffffffu, s, o);
    if (lane == 0) vec[j] = s + bo[j];
}

__global__ void fill_rows(const float* __restrict__ vec, float* __restrict__ out)
{
    const long long i = (long long)blockIdx.x * 256 + threadIdx.x;
    const float4 v = ((const float4*)vec)[i % (DIMN / 4)];
    ((float4*)out)[i] = v;
}

// sum split-K partials for all 3 LoRA branches
__global__ void reduce_splitk3(const float* __restrict__ P, float* __restrict__ D)
{
    const int i = blockIdx.y;   // lora branch
    const int j = blockIdx.x * 256 + threadIdx.x;
    const float* base = P + (size_t)i * KSPLIT * CONDN * RANKN + j;
    float s = 0.f;
#pragma unroll
    for (int z = 0; z < KSPLIT; z++) s += base[(size_t)z * CONDN * RANKN];
    D[(size_t)i * CONDN * RANKN + j] = s;
}

// ---------------- host-side launch helpers ----------------
#define GEMM_ARGS_NULLTAB nullptr, nullptr, nullptr, nullptr, 1

static void gemm_big(const float* A, const float* B, const float* bias, float* C,
                     int M, int N, int K, int lda, int ldb, int ldc,
                     long long sA, long long sB, long long sC, int batch,
                     float alpha, const float* aptr, float beta)
{
    dim3 gdim((N + 63) / 64, (M + 127) / 128, batch);
    gemm_tf32<128, 64, 256, 4, 2, 4, 4, 3, false><<<gdim, 256, BIG_SMEM>>>(
        A, B, bias, C, GEMM_ARGS_NULLTAB,
        M, N, K, lda, ldb, ldc, sA, sB, sC, alpha, aptr, beta);
}

static void gemm_small(const float* A, const float* B, const float* bias, float* C,
                       int M, int N, int K, int lda, int ldb, int ldc,
                       long long sA, long long sB, long long sC, int batch,
                       float alpha, const float* aptr, float beta)
{
    dim3 gdim((N + 63) / 64, (M + 63) / 64, batch);
    gemm_tf32<64, 64, 128, 4, 2, 4, 2, 4, false><<<gdim, 128, SMALL_SMEM>>>(
        A, B, bias, C, GEMM_ARGS_NULLTAB,
        M, N, K, lda, ldb, ldc, sA, sB, sC, alpha, aptr, beta);
}

static void gemm_big_tab(const float* const* tA, const float* const* tB,
                         const float* const* tbias, float* const* tC,
                         int zcnt, int zdiv,
                         int M, int N, int K, int lda, int ldb, int ldc,
                         long long sA, long long sB, long long sC,
                         float alpha, const float* aptr, float beta)
{
    dim3 gdim((N + 63) / 64, (M + 127) / 128, zcnt);
    gemm_tf32<128, 64, 256, 4, 2, 4, 4, 3, true><<<gdim, 256, BIG_SMEM>>>(
        nullptr, nullptr, nullptr, nullptr, tA, tB, tbias, tC, zdiv,
        M, N, K, lda, ldb, ldc, sA, sB, sC, alpha, aptr, beta);
}

static void gemm_small_tab(const float* const* tA, const float* const* tB,
                           const float* const* tbias, float* const* tC,
                           int zcnt, int zdiv,
                           int M, int N, int K, int lda, int ldb, int ldc,
                           long long sA, long long sB, long long sC,
                           float alpha, const float* aptr, float beta)
{
    dim3 gdim((N + 63) / 64, (M + 63) / 64, zcnt);
    gemm_tf32<64, 64, 128, 4, 2, 4, 2, 4, true><<<gdim, 128, SMALL_SMEM>>>(
        nullptr, nullptr, nullptr, nullptr, tA, tB, tbias, tC, zdiv,
        M, N, K, lda, ldb, ldc, sA, sB, sC, alpha, aptr, beta);
}

extern "C" void kernel_launch(void* const* d_in, const int* in_sizes, int n_in,
                              void* d_out, int out_size)
{
    const float* hidden = (const float*)d_in[0];
    const float* enc    = (const float*)d_in[1];
    const float* rc     = (const float*)d_in[2];
    const float* rs     = (const float*)d_in[3];
    const float* Wq  = (const float*)d_in[4];
    const float* Wk  = (const float*)d_in[5];
    const float* Wv  = (const float*)d_in[6];
    const float* Wqa = (const float*)d_in[7];
    const float* Wka = (const float*)d_in[8];
    const float* Wva = (const float*)d_in[9];
    const float* Wo  = (const float*)d_in[10];
    const float* Woa = (const float*)d_in[11];
    const float* bq  = (const float*)d_in[12];
    const float* bk  = (const float*)d_in[13];
    const float* bv  = (const float*)d_in[14];
    const float* bqa = (const float*)d_in[15];
    const float* bka = (const float*)d_in[16];
    const float* bva = (const float*)d_in[17];
    const float* bo  = (const float*)d_in[18];
    const float* boa = (const float*)d_in[19];
    const float* nqw  = (const float*)d_in[20];
    const float* nkw  = (const float*)d_in[21];
    const float* naqw = (const float*)d_in[22];
    const float* nakw = (const float*)d_in[23];
    const float* qd = (const float*)d_in[24];
    const float* kd = (const float*)d_in[25];
    const float* vd = (const float*)d_in[26];
    const float* qu = (const float*)d_in[27];
    const float* ku = (const float*)d_in[28];
    const float* vu = (const float*)d_in[29];
    const float* lw = (const float*)d_in[30];

    float *Pq, *Pk, *Pv, *Eq, *Ek, *Ev, *Q, *K, *Vt, *SA, *SB, *AO, *mean, *vec;
    cudaGetSymbolAddress((void**)&Pq, g_Pq);
    cudaGetSymbolAddress((void**)&Pk, g_Pk);
    cudaGetSymbolAddress((void**)&Pv, g_Pv);
    cudaGetSymbolAddress((void**)&Eq, g_Eq);
    cudaGetSymbolAddress((void**)&Ek, g_Ek);
    cudaGetSymbolAddress((void**)&Ev, g_Ev);
    cudaGetSymbolAddress((void**)&Q,  g_Q);
    cudaGetSymbolAddress((void**)&K,  g_K);
    cudaGetSymbolAddress((void**)&Vt, g_Vt);
    cudaGetSymbolAddress((void**)&SA, g_SA);
    cudaGetSymbolAddress((void**)&SB, g_SB);
    cudaGetSymbolAddress((void**)&AO, g_AO);
    cudaGetSymbolAddress((void**)&mean, g_mean);
    cudaGetSymbolAddress((void**)&vec,  g_vec);

    const float* const* tA;
    const float* const* tB;
    const float* const* tbias;
    float* const* tC;
    {
        void *pA, *pB, *pb, *pC;
        cudaGetSymbolAddress(&pA, g_tA);
        cudaGetSymbolAddress(&pB, g_tB);
        cudaGetSymbolAddress(&pb, g_tbias);
        cudaGetSymbolAddress(&pC, g_tC);
        tA = (const float* const*)pA;
        tB = (const float* const*)pB;
        tbias = (const float* const*)pb;
        tC = (float* const*)pC;
    }

    float* out = (float*)d_out;

    // opt-in to >48KB dynamic smem (required for BIG — launches fail without it)
    cudaFuncSetAttribute(gemm_tf32<128, 64, 256, 4, 2, 4, 4, 3, false>,
                         cudaFuncAttributeMaxDynamicSharedMemorySize, BIG_SMEM);
    cudaFuncSetAttribute(gemm_tf32<128, 64, 256, 4, 2, 4, 4, 3, true>,
                         cudaFuncAttributeMaxDynamicSharedMemorySize, BIG_SMEM);
    cudaFuncSetAttribute(gemm_tf32<64, 64, 128, 4, 2, 4, 2, 4, false>,
                         cudaFuncAttributeMaxDynamicSharedMemorySize, SMALL_SMEM);
    cudaFuncSetAttribute(gemm_tf32<64, 64, 128, 4, 2, 4, 2, 4, true>,
                         cudaFuncAttributeMaxDynamicSharedMemorySize, SMALL_SMEM);

    // 0) fill pointer tables
    setup_tabs<<<1, 1>>>(hidden, enc, Wq, Wk, Wv, Wqa, Wka, Wva,
                         bq, bk, bv, bqa, bka, bva, qd, kd, vd, qu, ku, vu);

    // 1) image q/k/v projections — ONE batched launch (grid 48x24x3)
    gemm_big_tab(tA + 0, tB + 0, tbias + 0, tC + 0, 3, 1,
                 S_HID, DIMN, DIMN, DIMN, DIMN, DIMN, 0, 0, 0, 1.f, nullptr, 0.f);

    // 2) encoder projections — ONE batched launch (grid 48x8x3 = 1152)
    gemm_small_tab(tA + 3, tB + 3, tbias + 3, tC + 3, 3, 1,
                   S_ENC, DIMN, DIMN, DIMN, DIMN, DIMN, 0, 0, 0, 1.f, nullptr, 0.f);

    // 3) LoRA down: all 3 branches x split-K 16 in one launch (z = 48)
    gemm_small_tab(tA + 6, tB + 6, tbias + 6, tC + 6, 3 * KSPLIT, KSPLIT,
                   CONDN, RANKN, DIMN / KSPLIT, DIMN, DIMN, RANKN,
                   DIMN / KSPLIT, DIMN / KSPLIT, (long long)CONDN * RANKN,
                   1.f, nullptr, 0.f);
    {
        float* DtP;
        float* Dt;
        cudaGetSymbolAddress((void**)&DtP, g_DtP);
        cudaGetSymbolAddress((void**)&Dt,  g_Dt);
        dim3 rg((CONDN * RANKN) / 256, 3);
        reduce_splitk3<<<rg, 256>>>(DtP, Dt);
    }
    // LoRA up: all 3 branches in one launch (grid 48x16x3); sc = lora_w[0]
    gemm_small_tab(tA + 9, tB + 9, tbias + 9, tC + 9, 3, 1,
                   CONDN, DIMN, RANKN, RANKN, RANKN, DIMN, 0, 0, 0, 1.f, lw, 1.f);

    // 4) heads + RMSNorm + RoPE + concat; V written transposed
    build_qkv<<<dim3(SEQ, HEADS), HD>>>(Pq, Pk, Pv, Eq, Ek, Ev, rc, rs,
                                        nqw, nkw, naqw, nakw, Q, K, Vt);

    // 5) block A: encoder queries vs full keys
    gemm_big(Q, K, nullptr, SA, S_ENC, SEQ, HD, HD, HD, SEQ,
             (long long)SEQ * HD, (long long)SEQ * HD, (long long)S_ENC * SEQ, HEADS,
             ATTN_SCALE, nullptr, 0.f);
    softmax_k<<<HEADS * S_ENC, 256>>>(SA, SEQ);
    gemm_small(SA, Vt, nullptr, AO, S_ENC, HD, SEQ, SEQ, SEQ, DIMN,
               (long long)S_ENC * SEQ, (long long)HD * SEQ, HD, HEADS, 1.f, nullptr, 0.f);

    // 6) block B: cond queries vs cond keys
    gemm_big(Q + (long long)S_ENC * HD, K + (long long)S_ENC * HD, nullptr, SB,
             CONDN, CONDN, HD, HD, HD, CONDN,
             (long long)SEQ * HD, (long long)SEQ * HD, (long long)CONDN * CONDN, HEADS,
             ATTN_SCALE, nullptr, 0.f);
    softmax_k<<<HEADS * CONDN, 256>>>(SB, CONDN);
    gemm_small(SB, Vt + S_ENC, nullptr, AO + (long long)S_ENC * DIMN,
               CONDN, HD, CONDN, CONDN, SEQ, DIMN,
               (long long)CONDN * CONDN, (long long)HD * SEQ, HD, HEADS, 1.f, nullptr, 0.f);

    // 7) fully-masked rows -> uniform softmax -> mean of V; one out-proj row
    mean_k<<<DIMN, 256>>>(Vt, mean);
    gemv_out<<<DIMN / 8, 256>>>(mean, Wo, bo, vec);

    // 8) output projections
    gemm_big(AO + (long long)S_ENC * DIMN, Wo, bo, out,
             CONDN, DIMN, DIMN, DIMN, DIMN, DIMN, 0, 0, 0, 1, 1.f, nullptr, 0.f);
    fill_rows<<<(NROWS_C * (DIMN / 4)) / 256, 256>>>(vec, out + (long long)CONDN * DIMN);
    gemm_small(AO, Woa, boa, out + (long long)S_HID * DIMN,
               S_ENC, DIMN, DIMN, DIMN, DIMN, DIMN, 0, 0, 0, 1, 1.f, nullptr, 0.f);
}

// round 13
// speedup vs baseline: 1.0959x; 1.0310x over previous
#include <cuda_runtime.h>
#include <math.h>
#include <stdint.h>

// ---------------- problem constants ----------------
#define DIMN   3072
#define HEADS  24
#define HD     128
#define S_HID  3072
#define S_ENC  512
#define SEQ    3584          // S_ENC + S_HID
#define CONDN  1024
#define RANKN  64
#define BLOCKL 2048          // S_HID - CONDN
#define NROWS_C (SEQ - S_ENC - CONDN)   // 2048 fully-masked query rows
#define KSPLIT 16            // split-K for LoRA down-proj
#define SCHUNK 28            // mean_k s-chunks (SEQ = 28*128)
static const float ATTN_SCALE = 0.08838834764831843f; // 1/sqrt(128)

// ---------------- device scratch (no allocs allowed) ----------------
__device__ float g_Pq[(size_t)S_HID * DIMN];
__device__ float g_Pk[(size_t)S_HID * DIMN];
__device__ float g_Pv[(size_t)S_HID * DIMN];
__device__ float g_Eq[(size_t)S_ENC * DIMN];
__device__ float g_Ek[(size_t)S_ENC * DIMN];
__device__ float g_Ev[(size_t)S_ENC * DIMN];
__device__ float g_Dt [(size_t)3 * CONDN * RANKN];
__device__ float g_DtP[(size_t)3 * KSPLIT * CONDN * RANKN];
__device__ float g_Q [(size_t)HEADS * SEQ * HD];
__device__ float g_K [(size_t)HEADS * SEQ * HD];
__device__ float g_V [(size_t)HEADS * SEQ * HD];      // natural layout [h][s][d]
__device__ float g_SA[(size_t)HEADS * S_ENC * SEQ];   // encoder-query scores
__device__ float g_SB[(size_t)HEADS * CONDN * CONDN]; // cond-block scores
__device__ float g_AO[(size_t)(S_ENC + CONDN) * DIMN];// attention out rows 0..1535
__device__ float g_mnP[(size_t)SCHUNK * DIMN];        // mean partials
__device__ float g_mean[DIMN];
__device__ float g_vec [DIMN];

// pointer tables for batched GEMM groups: [0..2]=qkv-proj, [3..5]=enc-proj,
// [6..8]=lora-down, [9..11]=lora-up
__device__ const float* g_tA[12];
__device__ const float* g_tB[12];
__device__ const float* g_tbias[12];
__device__ float*       g_tC[12];

// ---------------- helpers ----------------
__device__ __forceinline__ uint32_t f2tf(float f) {
    uint32_t u;
    asm("cvt.rna.tf32.f32 %0, %1;" : "=r"(u) : "f"(f));
    return u;
}

__device__ __forceinline__ void cpasync16(float* dst, const float* src, bool pred) {
    uint32_t d = (uint32_t)__cvta_generic_to_shared(dst);
    int sz = pred ? 16 : 0;   // src-size 0 => zero-fill, no memory access
    asm volatile("cp.async.cg.shared.global [%0], [%1], 16, %2;\n"
                 :: "r"(d), "l"(src), "r"(sz));
}

__device__ __forceinline__ void mma_tf32(float* c, const uint32_t* a, const uint32_t* b) {
    asm volatile(
        "mma.sync.aligned.m16n8k8.row.col.f32.tf32.tf32.f32 "
        "{%0,%1,%2,%3}, {%4,%5,%6,%7}, {%8,%9}, {%0,%1,%2,%3};\n"
        : "+f"(c[0]), "+f"(c[1]), "+f"(c[2]), "+f"(c[3])
        : "r"(a[0]), "r"(a[1]), "r"(a[2]), "r"(a[3]), "r"(b[0]), "r"(b[1]));
}

// ---------------- tf32 tensor-core GEMM ----------------
// TRB=true : C = alpha * A[M,K] @ B[N,K]^T  (B rows along K; weights layout)
// TRB=false: C = alpha * A[M,K] @ B[K,N]    (B rows along N; V layout)
// +bias, +beta*C.  TAB selects pointer-table batching (zi = z/zdiv picks table
// entry, remainder zr applies elem strides -> split-K within an entry).
#define BK 16
#define ASTR 20   // smem row stride for K-major tiles
#define BSTR_OF(TBN) (TBN + 4)   // smem row stride for [k][n] B tiles

template <int TBM, int TBN, int THREADS, int NSTAGE, int MT, int NT, int WMC,
          int OCC, bool TAB, bool TRB>
__global__ __launch_bounds__(THREADS, OCC)
void gemm_tf32(const float* __restrict__ A, const float* __restrict__ B,
               const float* __restrict__ bias, float* __restrict__ C,
               const float* const* __restrict__ Aarr,
               const float* const* __restrict__ Barr,
               const float* const* __restrict__ biasarr,
               float* const* __restrict__ Carr, int zdiv,
               int M, int N, int K, int lda, int ldb, int ldc,
               long long sA, long long sB, long long sC,
               float alpha, const float* __restrict__ alpha_ptr, float beta)
{
    constexpr int PF = NSTAGE - 1;
    constexpr int BSTR = BSTR_OF(TBN);
    constexpr int ASTG = TBM * ASTR;                       // A floats per stage
    constexpr int BSTG = TRB ? TBN * ASTR : BK * BSTR;     // B floats per stage
    extern __shared__ float smem[];
    float* As = smem;
    float* Bs = smem + NSTAGE * ASTG;

    const float* Ab;
    const float* Bb;
    float*       Cb;
    const float* biasb;
    if (TAB) {
        const int zi = blockIdx.z / zdiv;
        const int zr = blockIdx.z - zi * zdiv;
        Ab = Aarr[zi] + (long long)zr * sA;
        Bb = Barr[zi] + (long long)zr * sB;
        Cb = Carr[zi] + (long long)zr * sC;
        biasb = biasarr[zi];
    } else {
        Ab = A + (long long)blockIdx.z * sA;
        Bb = B + (long long)blockIdx.z * sB;
        Cb = C + (long long)blockIdx.z * sC;
        biasb = bias;
    }

    const int m0 = blockIdx.y * TBM;
    const int n0 = blockIdx.x * TBN;
    const int tid  = threadIdx.x;
    const int lane = tid & 31;
    const int warp = tid >> 5;
    const int wm = (warp % WMC) * (MT * 16);
    const int wn = (warp / WMC) * (NT * 8);
    const int g  = lane >> 2;               // groupID
    const int tg = lane & 3;                // thread-in-group

    float c[MT][NT][4];
#pragma unroll
    for (int i = 0; i < MT; i++)
#pragma unroll
        for (int j = 0; j < NT; j++)
#pragma unroll
            for (int r = 0; r < 4; r++) c[i][j][r] = 0.f;

    const int nk = K / BK;

    const int lrow = tid >> 2;              // 0..THREADS/4-1
    const int lkc  = (tid & 3) << 2;        // 0,4,8,12
    constexpr int RJUMP = THREADS / 4;

    auto load_tile = [&](int k0, int buf) {
        float* Ad = As + buf * ASTG;
        float* Bd = Bs + buf * BSTG;
#pragma unroll
        for (int j = 0; j < TBM / RJUMP; j++) {
            const int row = lrow + j * RJUMP;
            cpasync16(Ad + row * ASTR + lkc,
                      Ab + (long long)(m0 + row) * lda + k0 + lkc,
                      (m0 + row) < M);
        }
        if (TRB) {
#pragma unroll
            for (int j = 0; j < TBN / RJUMP; j++) {
                const int row = lrow + j * RJUMP;
                cpasync16(Bd + row * ASTR + lkc,
                          Bb + (long long)(n0 + row) * ldb + k0 + lkc,
                          (n0 + row) < N);
            }
        } else {
            // B[K][N]: load BK rows x TBN cols; chunks of 4 floats along n
            constexpr int CPT = (BK * TBN / 4) / THREADS;  // chunks per thread
#pragma unroll
            for (int j = 0; j < CPT; j++) {
                const int cidx = tid + j * THREADS;
                const int row  = cidx / (TBN / 4);
                const int col  = (cidx % (TBN / 4)) * 4;
                cpasync16(Bd + row * BSTR + col,
                          Bb + (long long)(k0 + row) * ldb + n0 + col,
                          (n0 + col) < N);
            }
        }
        asm volatile("cp.async.commit_group;\n");
    };

    for (int s = 0; s < PF; s++) {
        if (s < nk) load_tile(s * BK, s);
        else        asm volatile("cp.async.commit_group;\n");
    }

    for (int it = 0; it < nk; it++) {
        if (it + PF < nk) load_tile((it + PF) * BK, (it + PF) & (NSTAGE - 1));
        else              asm volatile("cp.async.commit_group;\n");
        asm volatile("cp.async.wait_group %0;\n" :: "n"(PF));
        __syncthreads();

        const int buf = it & (NSTAGE - 1);
        const float* Ac = As + buf * ASTG;
        const float* Bc = Bs + buf * BSTG;

#pragma unroll
        for (int ks = 0; ks < BK; ks += 8) {
            uint32_t bf[NT][2];
#pragma unroll
            for (int nt = 0; nt < NT; nt++) {
                if (TRB) {
                    const float* bp = Bc + (wn + nt * 8 + g) * ASTR + ks + tg;
                    bf[nt][0] = f2tf(bp[0]);
                    bf[nt][1] = f2tf(bp[4]);
                } else {
                    const float* bp = Bc + (ks + tg) * BSTR + wn + nt * 8 + g;
                    bf[nt][0] = f2tf(bp[0]);
                    bf[nt][1] = f2tf(bp[4 * BSTR]);
                }
            }
            uint32_t af[MT][4];
#pragma unroll
            for (int mt = 0; mt < MT; mt++) {
                const float* ap = Ac + (wm + mt * 16 + g) * ASTR + ks + tg;
                af[mt][0] = f2tf(ap[0]);
                af[mt][1] = f2tf(ap[8 * ASTR]);
                af[mt][2] = f2tf(ap[4]);
                af[mt][3] = f2tf(ap[8 * ASTR + 4]);
            }
#pragma unroll
            for (int mt = 0; mt < MT; mt++)
#pragma unroll
                for (int nt = 0; nt < NT; nt++)
                    mma_tf32(c[mt][nt], af[mt], bf[nt]);
        }
        __syncthreads();
    }

    float aE = alpha;
    if (alpha_ptr) aE *= *alpha_ptr;

#pragma unroll
    for (int mt = 0; mt < MT; mt++) {
#pragma unroll
        for (int r = 0; r < 2; r++) {
            const int gm = m0 + wm + mt * 16 + g + r * 8;
            if (gm >= M) continue;
            float* crow = Cb + (long long)gm * ldc;
#pragma unroll
            for (int nt = 0; nt < NT; nt++) {
                const int gn = n0 + wn + nt * 8 + tg * 2;
                if (gn >= N) continue;
                float x = c[mt][nt][r * 2 + 0] * aE;
                float y = c[mt][nt][r * 2 + 1] * aE;
                if (biasb) { x += biasb[gn]; y += biasb[gn + 1]; }
                if (beta != 0.f) {
                    float2 p = *(const float2*)(crow + gn);
                    x += beta * p.x; y += beta * p.y;
                }
                *(float2*)(crow + gn) = make_float2(x, y);
            }
        }
    }
}

#define BIG_SMEM     (4 * (128 * ASTR + 64 * ASTR) * 4)
#define SMALL_SMEM   (4 * (64 * ASTR + 64 * ASTR) * 4)
#define SMALLF_SMEM  (4 * (64 * ASTR + BK * BSTR_OF(64)) * 4)

// ---------------- setup kernel: fill the pointer tables ----------------
__global__ void setup_tabs(const float* hidden, const float* enc,
                           const float* Wq, const float* Wk, const float* Wv,
                           const float* Wqa, const float* Wka, const float* Wva,
                           const float* bq, const float* bk, const float* bv,
                           const float* bqa, const float* bka, const float* bva,
                           const float* qd, const float* kd, const float* vd,
                           const float* qu, const float* ku, const float* vu)
{
    g_tA[0] = hidden; g_tA[1] = hidden; g_tA[2] = hidden;
    g_tB[0] = Wq; g_tB[1] = Wk; g_tB[2] = Wv;
    g_tC[0] = g_Pq; g_tC[1] = g_Pk; g_tC[2] = g_Pv;
    g_tbias[0] = bq; g_tbias[1] = bk; g_tbias[2] = bv;
    g_tA[3] = enc; g_tA[4] = enc; g_tA[5] = enc;
    g_tB[3] = Wqa; g_tB[4] = Wka; g_tB[5] = Wva;
    g_tC[3] = g_Eq; g_tC[4] = g_Ek; g_tC[5] = g_Ev;
    g_tbias[3] = bqa; g_tbias[4] = bka; g_tbias[5] = bva;
    const float* hm = hidden + (long long)BLOCKL * DIMN;
    g_tA[6] = hm; g_tA[7] = hm; g_tA[8] = hm;
    g_tB[6] = qd; g_tB[7] = kd; g_tB[8] = vd;
    g_tC[6] = g_DtP + 0 * (size_t)KSPLIT * CONDN * RANKN;
    g_tC[7] = g_DtP + 1 * (size_t)KSPLIT * CONDN * RANKN;
    g_tC[8] = g_DtP + 2 * (size_t)KSPLIT * CONDN * RANKN;
    g_tbias[6] = nullptr; g_tbias[7] = nullptr; g_tbias[8] = nullptr;
    g_tA[9]  = g_Dt + 0 * (size_t)CONDN * RANKN;
    g_tA[10] = g_Dt + 1 * (size_t)CONDN * RANKN;
    g_tA[11] = g_Dt + 2 * (size_t)CONDN * RANKN;
    g_tB[9] = qu; g_tB[10] = ku; g_tB[11] = vu;
    g_tC[9]  = g_Pq + (long long)BLOCKL * DIMN;
    g_tC[10] = g_Pk + (long long)BLOCKL * DIMN;
    g_tC[11] = g_Pv + (long long)BLOCKL * DIMN;
    g_tbias[9] = nullptr; g_tbias[10] = nullptr; g_tbias[11] = nullptr;
}

// ---------------- elementwise kernels ----------------
__global__ void build_qkv(const float* __restrict__ Pq, const float* __restrict__ Pk,
                          const float* __restrict__ Pv, const float* __restrict__ Eq,
                          const float* __restrict__ Ek, const float* __restrict__ Ev,
                          const float* __restrict__ rc, const float* __restrict__ rs,
                          const float* __restrict__ nqw, const float* __restrict__ nkw,
                          const float* __restrict__ naqw, const float* __restrict__ nakw,
                          float* __restrict__ Q, float* __restrict__ K, float* __restrict__ V)
{
    const int s = blockIdx.x;
    const int h = blockIdx.y;
    const int d = threadIdx.x;

    const float *sq, *sk, *sv, *wq, *wk;
    if (s < S_ENC) {
        const long long off = (long long)s * DIMN + h * HD;
        sq = Eq + off; sk = Ek + off; sv = Ev + off;
        wq = naqw; wk = nakw;
    } else {
        const long long off = (long long)(s - S_ENC) * DIMN + h * HD;
        sq = Pq + off; sk = Pk + off; sv = Pv + off;
        wq = nqw; wk = nkw;
    }
    float q = sq[d], k = sk[d], v = sv[d];

    float ssq = q * q, ssk = k * k;
#pragma unroll
    for (int o = 16; o; o >>= 1) {
        ssq += __shfl_xor_sync(0xffffffffu, ssq, o);
        ssk += __shfl_xor_sync(0xffffffffu, ssk, o);
    }
    __shared__ float shq[4], shk[4];
    const int w = d >> 5;
    if ((d & 31) == 0) { shq[w] = ssq; shk[w] = ssk; }
    __syncthreads();
    const float tq = shq[0] + shq[1] + shq[2] + shq[3];
    const float tk = shk[0] + shk[1] + shk[2] + shk[3];

    const float qn = q * rsqrtf(tq * (1.0f / HD) + 1e-6f) * wq[d];
    const float kn = k * rsqrtf(tk * (1.0f / HD) + 1e-6f) * wk[d];

    const float qp = __shfl_xor_sync(0xffffffffu, qn, 1);
    const float kp = __shfl_xor_sync(0xffffffffu, kn, 1);
    const float qr = (d & 1) ? qp : -qp;
    const float kr = (d & 1) ? kp : -kp;

    const float cc = rc[(long long)s * HD + d];
    const float sn = rs[(long long)s * HD + d];

    const long long o = ((long long)h * SEQ + s) * HD + d;
    Q[o] = qn * cc + qr * sn;
    K[o] = kn * cc + kr * sn;
    V[o] = v;
}

// register-cached softmax: exactly 1 global read + 1 global write per element
template <int NC>
__global__ void softmax_k(float* __restrict__ S)
{
    constexpr int PT = NC / 256;
    float* r = S + (long long)blockIdx.x * NC;
    const int tid = threadIdx.x;
    __shared__ float sh[8];

    float v[PT];
#pragma unroll
    for (int i = 0; i < PT; i++) v[i] = r[tid + i * 256];

    float m = v[0];
#pragma unroll
    for (int i = 1; i < PT; i++) m = fmaxf(m, v[i]);
#pragma unroll
    for (int o = 16; o; o >>= 1) m = fmaxf(m, __shfl_xor_sync(0xffffffffu, m, o));
    if ((tid & 31) == 0) sh[tid >> 5] = m;
    __syncthreads();
    float bm = sh[0];
#pragma unroll
    for (int i = 1; i < 8; i++) bm = fmaxf(bm, sh[i]);
    __syncthreads();

    float sum = 0.f;
#pragma unroll
    for (int i = 0; i < PT; i++) {
        v[i] = expf(v[i] - bm);
        sum += v[i];
    }
#pragma unroll
    for (int o = 16; o; o >>= 1) sum += __shfl_xor_sync(0xffffffffu, sum, o);
    if ((tid & 31) == 0) sh[tid >> 5] = sum;
    __syncthreads();
    float bs = 0.f;
#pragma unroll
    for (int i = 0; i < 8; i++) bs += sh[i];
    const float inv = 1.0f / bs;
#pragma unroll
    for (int i = 0; i < PT; i++) r[tid + i * 256] = v[i] * inv;
}

// mean of V over s (rows >= 1536 are uniform softmax): chunked coalesced partials
__global__ void mean_part(const float* __restrict__ V, float* __restrict__ P)
{
    const int h  = blockIdx.x;
    const int ch = blockIdx.y;
    const int d  = threadIdx.x;
    const float* base = V + ((long long)h * SEQ + ch * (SEQ / SCHUNK)) * HD + d;
    float s = 0.f;
#pragma unroll 4
    for (int i = 0; i < SEQ / SCHUNK; i++) s += base[(long long)i * HD];
    P[(size_t)ch * DIMN + h * HD + d] = s;
}

__global__ void mean_fin(const float* __restrict__ P, float* __restrict__ mean)
{
    const int j = blockIdx.x * 256 + threadIdx.x;
    float s = 0.f;
#pragma unroll
    for (int c = 0; c < SCHUNK; c++) s += P[(size_t)c * DIMN + j];
    mean[j] = s * (1.0f / SEQ);
}

__global__ void gemv_out(const float* __restrict__ mean, const float* __restrict__ Wo,
                         const float* __restrict__ bo, float* __restrict__ vec)
{
    const int j = blockIdx.x * 8 + (threadIdx.x >> 5);
    const int lane = threadIdx.x & 31;
    const float* w = Wo + (long long)j * DIMN;
    float s = 0.f;
    for (int d = lane; d < DIMN; d += 32) s += mean[d] * w[d];
#pragma unroll
    for (int o = 16; o; o >>= 1) s += __shfl_xor_sync(0xffffffffu, s, o);
    if (lane == 0) vec[j] = s + bo[j];
}

__global__ void fill_rows(const float* __restrict__ vec, float* __restrict__ out)
{
    const long long i = (long long)blockIdx.x * 256 + threadIdx.x;
    const float4 v = ((const float4*)vec)[i % (DIMN / 4)];
    ((float4*)out)[i] = v;
}

__global__ void reduce_splitk3(const float* __restrict__ P, float* __restrict__ D)
{
    const int i = blockIdx.y;
    const int j = blockIdx.x * 256 + threadIdx.x;
    const float* base = P + (size_t)i * KSPLIT * CONDN * RANKN + j;
    float s = 0.f;
#pragma unroll
    for (int z = 0; z < KSPLIT; z++) s += base[(size_t)z * CONDN * RANKN];
    D[(size_t)i * CONDN * RANKN + j] = s;
}

// ---------------- host-side launch helpers ----------------
#define NULLTAB nullptr, nullptr, nullptr, nullptr, 1

static void gemm_big(const float* A, const float* B, const float* bias, float* C,
                     int M, int N, int K, int lda, int ldb, int ldc,
                     long long sA, long long sB, long long sC, int batch,
                     float alpha, const float* aptr, float beta)
{
    dim3 gdim((N + 63) / 64, (M + 127) / 128, batch);
    gemm_tf32<128, 64, 256, 4, 2, 4, 4, 3, false, true><<<gdim, 256, BIG_SMEM>>>(
        A, B, bias, C, NULLTAB, M, N, K, lda, ldb, ldc, sA, sB, sC, alpha, aptr, beta);
}

static void gemm_small_nt(const float* A, const float* B, float* C,
                          int M, int N, int K, int lda, int ldb, int ldc,
                          long long sA, long long sB, long long sC, int batch)
{
    dim3 gdim((N + 63) / 64, (M + 63) / 64, batch);
    gemm_tf32<64, 64, 128, 4, 2, 4, 2, 4, false, false><<<gdim, 128, SMALLF_SMEM>>>(
        A, B, nullptr, C, NULLTAB, M, N, K, lda, ldb, ldc, sA, sB, sC,
        1.f, nullptr, 0.f);
}

static void gemm_small(const float* A, const float* B, const float* bias, float* C,
                       int M, int N, int K, int lda, int ldb, int ldc,
                       long long sA, long long sB, long long sC, int batch,
                       float alpha, const float* aptr, float beta)
{
    dim3 gdim((N + 63) / 64, (M + 63) / 64, batch);
    gemm_tf32<64, 64, 128, 4, 2, 4, 2, 4, false, true><<<gdim, 128, SMALL_SMEM>>>(
        A, B, bias, C, NULLTAB, M, N, K, lda, ldb, ldc, sA, sB, sC, alpha, aptr, beta);
}

static void gemm_big_tab(const float* const* tA, const float* const* tB,
                         const float* const* tbias, float* const* tC,
                         int zcnt, int zdiv,
                         int M, int N, int K, int lda, int ldb, int ldc,
                         long long sA, long long sB, long long sC,
                         float alpha, const float* aptr, float beta)
{
    dim3 gdim((N + 63) / 64, (M + 127) / 128, zcnt);
    gemm_tf32<128, 64, 256, 4, 2, 4, 4, 3, true, true><<<gdim, 256, BIG_SMEM>>>(
        nullptr, nullptr, nullptr, nullptr, tA, tB, tbias, tC, zdiv,
        M, N, K, lda, ldb, ldc, sA, sB, sC, alpha, aptr, beta);
}

static void gemm_small_tab(const float* const* tA, const float* const* tB,
                           const float* const* tbias, float* const* tC,
                           int zcnt, int zdiv,
                           int M, int N, int K, int lda, int ldb, int ldc,
                           long long sA, long long sB, long long sC,
                           float alpha, const float* aptr, float beta)
{
    dim3 gdim((N + 63) / 64, (M + 63) / 64, zcnt);
    gemm_tf32<64, 64, 128, 4, 2, 4, 2, 4, true, true><<<gdim, 128, SMALL_SMEM>>>(
        nullptr, nullptr, nullptr, nullptr, tA, tB, tbias, tC, zdiv,
        M, N, K, lda, ldb, ldc, sA, sB, sC, alpha, aptr, beta);
}

extern "C" void kernel_launch(void* const* d_in, const int* in_sizes, int n_in,
                              void* d_out, int out_size)
{
    const float* hidden = (const float*)d_in[0];
    const float* enc    = (const float*)d_in[1];
    const float* rc     = (const float*)d_in[2];
    const float* rs     = (const float*)d_in[3];
    const float* Wq  = (const float*)d_in[4];
    const float* Wk  = (const float*)d_in[5];
    const float* Wv  = (const float*)d_in[6];
    const float* Wqa = (const float*)d_in[7];
    const float* Wka = (const float*)d_in[8];
    const float* Wva = (const float*)d_in[9];
    const float* Wo  = (const float*)d_in[10];
    const float* Woa = (const float*)d_in[11];
    const float* bq  = (const float*)d_in[12];
    const float* bk  = (const float*)d_in[13];
    const float* bv  = (const float*)d_in[14];
    const float* bqa = (const float*)d_in[15];
    const float* bka = (const float*)d_in[16];
    const float* bva = (const float*)d_in[17];
    const float* bo  = (const float*)d_in[18];
    const float* boa = (const float*)d_in[19];
    const float* nqw  = (const float*)d_in[20];
    const float* nkw  = (const float*)d_in[21];
    const float* naqw = (const float*)d_in[22];
    const float* nakw = (const float*)d_in[23];
    const float* qd = (const float*)d_in[24];
    const float* kd = (const float*)d_in[25];
    const float* vd = (const float*)d_in[26];
    const float* qu = (const float*)d_in[27];
    const float* ku = (const float*)d_in[28];
    const float* vu = (const float*)d_in[29];
    const float* lw = (const float*)d_in[30];

    float *Pq, *Pk, *Pv, *Eq, *Ek, *Ev, *Q, *K, *V, *SA, *SB, *AO, *mnP, *mean, *vec;
    cudaGetSymbolAddress((void**)&Pq, g_Pq);
    cudaGetSymbolAddress((void**)&Pk, g_Pk);
    cudaGetSymbolAddress((void**)&Pv, g_Pv);
    cudaGetSymbolAddress((void**)&Eq, g_Eq);
    cudaGetSymbolAddress((void**)&Ek, g_Ek);
    cudaGetSymbolAddress((void**)&Ev, g_Ev);
    cudaGetSymbolAddress((void**)&Q,  g_Q);
    cudaGetSymbolAddress((void**)&K,  g_K);
    cudaGetSymbolAddress((void**)&V,  g_V);
    cudaGetSymbolAddress((void**)&SA, g_SA);
    cudaGetSymbolAddress((void**)&SB, g_SB);
    cudaGetSymbolAddress((void**)&AO, g_AO);
    cudaGetSymbolAddress((void**)&mnP, g_mnP);
    cudaGetSymbolAddress((void**)&mean, g_mean);
    cudaGetSymbolAddress((void**)&vec,  g_vec);

    const float* const* tA;
    const float* const* tB;
    const float* const* tbias;
    float* const* tC;
    {
        void *pA, *pB, *pb, *pC;
        cudaGetSymbolAddress(&pA, g_tA);
        cudaGetSymbolAddress(&pB, g_tB);
        cudaGetSymbolAddress(&pb, g_tbias);
        cudaGetSymbolAddress(&pC, g_tC);
        tA = (const float* const*)pA;
        tB = (const float* const*)pB;
        tbias = (const float* const*)pb;
        tC = (float* const*)pC;
    }

    float* out = (float*)d_out;

    // opt-in to >48KB dynamic smem (required — launches fail without it)
    cudaFuncSetAttribute(gemm_tf32<128, 64, 256, 4, 2, 4, 4, 3, false, true>,
                         cudaFuncAttributeMaxDynamicSharedMemorySize, BIG_SMEM);
    cudaFuncSetAttribute(gemm_tf32<128, 64, 256, 4, 2, 4, 4, 3, true, true>,
                         cudaFuncAttributeMaxDynamicSharedMemorySize, BIG_SMEM);
    cudaFuncSetAttribute(gemm_tf32<64, 64, 128, 4, 2, 4, 2, 4, false, true>,
                         cudaFuncAttributeMaxDynamicSharedMemorySize, SMALL_SMEM);
    cudaFuncSetAttribute(gemm_tf32<64, 64, 128, 4, 2, 4, 2, 4, true, true>,
                         cudaFuncAttributeMaxDynamicSharedMemorySize, SMALL_SMEM);
    cudaFuncSetAttribute(gemm_tf32<64, 64, 128, 4, 2, 4, 2, 4, false, false>,
                         cudaFuncAttributeMaxDynamicSharedMemorySize, SMALLF_SMEM);

    // 0) fill pointer tables
    setup_tabs<<<1, 1>>>(hidden, enc, Wq, Wk, Wv, Wqa, Wka, Wva,
                         bq, bk, bv, bqa, bka, bva, qd, kd, vd, qu, ku, vu);

    // 1) image q/k/v projections — ONE batched launch
    gemm_big_tab(tA + 0, tB + 0, tbias + 0, tC + 0, 3, 1,
                 S_HID, DIMN, DIMN, DIMN, DIMN, DIMN, 0, 0, 0, 1.f, nullptr, 0.f);

    // 2) encoder projections — ONE batched launch
    gemm_small_tab(tA + 3, tB + 3, tbias + 3, tC + 3, 3, 1,
                   S_ENC, DIMN, DIMN, DIMN, DIMN, DIMN, 0, 0, 0, 1.f, nullptr, 0.f);

    // 3) LoRA down: 3 branches x split-K 16 in one launch (z = 48)
    gemm_small_tab(tA + 6, tB + 6, tbias + 6, tC + 6, 3 * KSPLIT, KSPLIT,
                   CONDN, RANKN, DIMN / KSPLIT, DIMN, DIMN, RANKN,
                   DIMN / KSPLIT, DIMN / KSPLIT, (long long)CONDN * RANKN,
                   1.f, nullptr, 0.f);
    {
        float* DtP;
        float* Dt;
        cudaGetSymbolAddress((void**)&DtP, g_DtP);
        cudaGetSymbolAddress((void**)&Dt,  g_Dt);
        dim3 rg((CONDN * RANKN) / 256, 3);
        reduce_splitk3<<<rg, 256>>>(DtP, Dt);
    }
    // LoRA up: 3 branches in one launch; sc = lora_w[0]
    gemm_small_tab(tA + 9, tB + 9, tbias + 9, tC + 9, 3, 1,
                   CONDN, DIMN, RANKN, RANKN, RANKN, DIMN, 0, 0, 0, 1.f, lw, 1.f);

    // 4) heads + RMSNorm + RoPE + concat; V in natural [h][s][d] layout
    build_qkv<<<dim3(SEQ, HEADS), HD>>>(Pq, Pk, Pv, Eq, Ek, Ev, rc, rs,
                                        nqw, nkw, naqw, nakw, Q, K, V);

    // 5) block A: encoder queries vs full keys
    gemm_big(Q, K, nullptr, SA, S_ENC, SEQ, HD, HD, HD, SEQ,
             (long long)SEQ * HD, (long long)SEQ * HD, (long long)S_ENC * SEQ, HEADS,
             ATTN_SCALE, nullptr, 0.f);
    softmax_k<SEQ><<<HEADS * S_ENC, 256>>>(SA);
    gemm_small_nt(SA, V, AO, S_ENC, HD, SEQ, SEQ, HD, DIMN,
                  (long long)S_ENC * SEQ, (long long)SEQ * HD, HD, HEADS);

    // 6) block B: cond queries vs cond keys
    gemm_big(Q + (long long)S_ENC * HD, K + (long long)S_ENC * HD, nullptr, SB,
             CONDN, CONDN, HD, HD, HD, CONDN,
             (long long)SEQ * HD, (long long)SEQ * HD, (long long)CONDN * CONDN, HEADS,
             ATTN_SCALE, nullptr, 0.f);
    softmax_k<CONDN><<<HEADS * CONDN, 256>>>(SB);
    gemm_small_nt(SB, V + (long long)S_ENC * HD, AO + (long long)S_ENC * DIMN,
                  CONDN, HD, CONDN, CONDN, HD, DIMN,
                  (long long)CONDN * CONDN, (long long)SEQ * HD, HD, HEADS);

    // 7) fully-masked rows -> uniform softmax -> mean of V; one out-proj row
    mean_part<<<dim3(HEADS, SCHUNK), HD>>>(V, mnP);
    mean_fin<<<DIMN / 256, 256>>>(mnP, mean);
    gemv_out<<<DIMN / 8, 256>>>(mean, Wo, bo, vec);

    // 8) output projections
    gemm_big(AO + (long long)S_ENC * DIMN, Wo, bo, out,
             CONDN, DIMN, DIMN, DIMN, DIMN, DIMN, 0, 0, 0, 1, 1.f, nullptr, 0.f);
    fill_rows<<<(NROWS_C * (DIMN / 4)) / 256, 256>>>(vec, out + (long long)CONDN * DIMN);
    gemm_small(AO, Woa, boa, out + (long long)S_HID * DIMN,
               S_ENC, DIMN, DIMN, DIMN, DIMN, DIMN, 0, 0, 0, 1, 1.f, nullptr, 0.f);
}

// round 14
// speedup vs baseline: 1.6132x; 1.4720x over previous
#include <cuda_runtime.h>
#include <cuda_fp16.h>
#include <math.h>
#include <stdint.h>

// ---------------- problem constants ----------------
#define DIMN   3072
#define HEADS  24
#define HD     128
#define S_HID  3072
#define S_ENC  512
#define SEQ    3584          // S_ENC + S_HID
#define CONDN  1024
#define RANKN  64
#define BLOCKL 2048          // S_HID - CONDN
#define NROWS_C (SEQ - S_ENC - CONDN)   // 2048 fully-masked query rows
#define KSPLIT 16            // split-K for LoRA down-proj
#define SCHUNK 28            // mean s-chunks (SEQ = 28*128)
static const float ATTN_SCALE = 0.08838834764831843f; // 1/sqrt(128)

// ---------------- device scratch (no allocs allowed) ----------------
__device__ float g_Pq[(size_t)S_HID * DIMN];
__device__ float g_Pk[(size_t)S_HID * DIMN];
__device__ float g_Pv[(size_t)S_HID * DIMN];
__device__ float g_Eq[(size_t)S_ENC * DIMN];
__device__ float g_Ek[(size_t)S_ENC * DIMN];
__device__ float g_Ev[(size_t)S_ENC * DIMN];
__device__ float g_DtP[(size_t)3 * KSPLIT * CONDN * RANKN];
__device__ float g_V [(size_t)HEADS * SEQ * HD];      // natural layout [h][s][d]
__device__ float g_SA[(size_t)HEADS * S_ENC * SEQ];   // encoder-query scores
__device__ float g_SB[(size_t)HEADS * CONDN * CONDN]; // cond-block scores
__device__ float g_mnP[(size_t)SCHUNK * DIMN];
__device__ float g_mean[DIMN];
__device__ float g_vec [DIMN];
// half operand buffers
__device__ __half g_hH[(size_t)S_HID * DIMN];
__device__ __half g_hE[(size_t)S_ENC * DIMN];
__device__ __half g_hW[8][(size_t)DIMN * DIMN];   // Wq Wk Wv Wqa Wka Wva Wo Woa
__device__ __half g_hdn[3][(size_t)RANKN * DIMN];
__device__ __half g_hup[3][(size_t)DIMN * RANKN];
__device__ __half g_Qh[(size_t)HEADS * SEQ * HD];
__device__ __half g_Kh[(size_t)HEADS * SEQ * HD];
__device__ __half g_Dth[(size_t)3 * CONDN * RANKN];
__device__ __half g_AOh[(size_t)(S_ENC + CONDN) * DIMN];

// pointer tables for batched f16 GEMM groups:
// [0..2]=qkv-proj, [3..5]=enc-proj, [6..8]=lora-down, [9..11]=lora-up
__device__ const __half* g_hA[12];
__device__ const __half* g_hB[12];
__device__ const float*  g_tbias[12];
__device__ float*        g_tC[12];

// ---------------- helpers ----------------
__device__ __forceinline__ uint32_t f2tf(float f) {
    uint32_t u;
    asm("cvt.rna.tf32.f32 %0, %1;" : "=r"(u) : "f"(f));
    return u;
}

__device__ __forceinline__ void cpa16(void* dst, const void* src, bool pred) {
    uint32_t d = (uint32_t)__cvta_generic_to_shared(dst);
    int sz = pred ? 16 : 0;   // src-size 0 => zero-fill
    asm volatile("cp.async.cg.shared.global [%0], [%1], 16, %2;\n"
                 :: "r"(d), "l"(src), "r"(sz));
}

__device__ __forceinline__ void mma_tf32(float* c, const uint32_t* a, const uint32_t* b) {
    asm volatile(
        "mma.sync.aligned.m16n8k8.row.col.f32.tf32.tf32.f32 "
        "{%0,%1,%2,%3}, {%4,%5,%6,%7}, {%8,%9}, {%0,%1,%2,%3};\n"
        : "+f"(c[0]), "+f"(c[1]), "+f"(c[2]), "+f"(c[3])
        : "r"(a[0]), "r"(a[1]), "r"(a[2]), "r"(a[3]), "r"(b[0]), "r"(b[1]));
}

__device__ __forceinline__ void mma_f16(float* c, const uint32_t* a, const uint32_t* b) {
    asm volatile(
        "mma.sync.aligned.m16n8k16.row.col.f32.f16.f16.f32 "
        "{%0,%1,%2,%3}, {%4,%5,%6,%7}, {%8,%9}, {%0,%1,%2,%3};\n"
        : "+f"(c[0]), "+f"(c[1]), "+f"(c[2]), "+f"(c[3])
        : "r"(a[0]), "r"(a[1]), "r"(a[2]), "r"(a[3]), "r"(b[0]), "r"(b[1]));
}

// ---------------- fp16 tensor-core GEMM ----------------
// C(f32) = alpha * A[M,K](half) @ B[N,K]^T(half) + bias + beta*C.
// BK = 32 halves per stage; smem rows stride 20 half2 (conflict-free).
// TAB: operands from pointer tables (zi = z/zdiv entry, zr*strides = split-K).
#define ASTRH 20   // smem row stride in half2 units

template <int TBM, int TBN, int THREADS, int NSTAGE, int MT, int NT, int WMC,
          int OCC, bool TAB>
__global__ __launch_bounds__(THREADS, OCC)
void gemm_f16(const __half* __restrict__ A, const __half* __restrict__ B,
              const float* __restrict__ bias, float* __restrict__ C,
              const __half* const* __restrict__ Aarr,
              const __half* const* __restrict__ Barr,
              const float* const* __restrict__ biasarr,
              float* const* __restrict__ Carr, int zdiv,
              int M, int N, int K, int lda, int ldb, int ldc,
              long long sA, long long sB, long long sC,
              float alpha, const float* __restrict__ alpha_ptr, float beta)
{
    constexpr int PF = NSTAGE - 1;
    constexpr int ASTG = TBM * ASTRH;   // half2 per A stage
    constexpr int BSTG = TBN * ASTRH;
    extern __shared__ uint32_t smh[];
    uint32_t* As = smh;
    uint32_t* Bs = smh + NSTAGE * ASTG;

    const __half* Ab;
    const __half* Bb;
    float*        Cb;
    const float*  biasb;
    if (TAB) {
        const int zi = blockIdx.z / zdiv;
        const int zr = blockIdx.z - zi * zdiv;
        Ab = Aarr[zi] + (long long)zr * sA;
        Bb = Barr[zi] + (long long)zr * sB;
        Cb = Carr[zi] + (long long)zr * sC;
        biasb = biasarr[zi];
    } else {
        Ab = A + (long long)blockIdx.z * sA;
        Bb = B + (long long)blockIdx.z * sB;
        Cb = C + (long long)blockIdx.z * sC;
        biasb = bias;
    }

    const int m0 = blockIdx.y * TBM;
    const int n0 = blockIdx.x * TBN;
    const int tid  = threadIdx.x;
    const int lane = tid & 31;
    const int warp = tid >> 5;
    const int wm = (warp % WMC) * (MT * 16);
    const int wn = (warp / WMC) * (NT * 8);
    const int g  = lane >> 2;
    const int tg = lane & 3;

    float c[MT][NT][4];
#pragma unroll
    for (int i = 0; i < MT; i++)
#pragma unroll
        for (int j = 0; j < NT; j++)
#pragma unroll
            for (int r = 0; r < 4; r++) c[i][j][r] = 0.f;

    const int nk = K / 32;

    auto load_tile = [&](int k0 /*halves*/, int buf) {
        uint32_t* Ad = As + buf * ASTG;
        uint32_t* Bd = Bs + buf * BSTG;
#pragma unroll
        for (int j = 0; j < TBM * 4 / THREADS; j++) {
            const int cidx = tid + j * THREADS;
            const int row  = cidx >> 2;
            const int ch2  = (cidx & 3) << 2;     // half2 offset in row
            cpa16(Ad + row * ASTRH + ch2,
                  Ab + (long long)(m0 + row) * lda + k0 + ch2 * 2,
                  (m0 + row) < M);
        }
#pragma unroll
        for (int j = 0; j < TBN * 4 / THREADS; j++) {
            const int cidx = tid + j * THREADS;
            const int row  = cidx >> 2;
            const int ch2  = (cidx & 3) << 2;
            cpa16(Bd + row * ASTRH + ch2,
                  Bb + (long long)(n0 + row) * ldb + k0 + ch2 * 2,
                  (n0 + row) < N);
        }
        asm volatile("cp.async.commit_group;\n");
    };

    for (int s = 0; s < PF; s++) {
        if (s < nk) load_tile(s * 32, s);
        else        asm volatile("cp.async.commit_group;\n");
    }

    for (int it = 0; it < nk; it++) {
        if (it + PF < nk) load_tile((it + PF) * 32, (it + PF) & (NSTAGE - 1));
        else              asm volatile("cp.async.commit_group;\n");
        asm volatile("cp.async.wait_group %0;\n" :: "n"(PF));
        __syncthreads();

        const int buf = it & (NSTAGE - 1);
        const uint32_t* Ac = As + buf * ASTG;
        const uint32_t* Bc = Bs + buf * BSTG;

#pragma unroll
        for (int s16 = 0; s16 < 2; s16++) {       // two k16 steps per BK=32
            const int cb = s16 * 8;               // half2 column base
            uint32_t bf[NT][2];
#pragma unroll
            for (int nt = 0; nt < NT; nt++) {
                const uint32_t* bp = Bc + (wn + nt * 8 + g) * ASTRH + cb + tg;
                bf[nt][0] = bp[0];
                bf[nt][1] = bp[4];
            }
            uint32_t af[MT][4];
#pragma unroll
            for (int mt = 0; mt < MT; mt++) {
                const uint32_t* ap = Ac + (wm + mt * 16 + g) * ASTRH + cb + tg;
                af[mt][0] = ap[0];
                af[mt][1] = ap[8 * ASTRH];
                af[mt][2] = ap[4];
                af[mt][3] = ap[8 * ASTRH + 4];
            }
#pragma unroll
            for (int mt = 0; mt < MT; mt++)
#pragma unroll
                for (int nt = 0; nt < NT; nt++)
                    mma_f16(c[mt][nt], af[mt], bf[nt]);
        }
        __syncthreads();
    }

    float aE = alpha;
    if (alpha_ptr) aE *= *alpha_ptr;

#pragma unroll
    for (int mt = 0; mt < MT; mt++) {
#pragma unroll
        for (int r = 0; r < 2; r++) {
            const int gm = m0 + wm + mt * 16 + g + r * 8;
            if (gm >= M) continue;
            float* crow = Cb + (long long)gm * ldc;
#pragma unroll
            for (int nt = 0; nt < NT; nt++) {
                const int gn = n0 + wn + nt * 8 + tg * 2;
                if (gn >= N) continue;
                float x = c[mt][nt][r * 2 + 0] * aE;
                float y = c[mt][nt][r * 2 + 1] * aE;
                if (biasb) { x += biasb[gn]; y += biasb[gn + 1]; }
                if (beta != 0.f) {
                    float2 p = *(const float2*)(crow + gn);
                    x += beta * p.x; y += beta * p.y;
                }
                *(float2*)(crow + gn) = make_float2(x, y);
            }
        }
    }
}

#define BIGH_SMEM   (4 * (128 + 64) * ASTRH * 4)
#define SMALLH_SMEM (4 * ( 64 + 64) * ASTRH * 4)

// ---------------- tf32 AV GEMM: AO(half) = P(f32)[M,K] @ V(f32)[K,N] ----------------
// 64x64 tile, 128 thr, 4-stage, BK=16; B in natural [K][N] layout; half output.
#define AVBK 16
#define AASTR 20
#define BVSTR 68

__global__ __launch_bounds__(128, 4)
void gemm_av(const float* __restrict__ A, const float* __restrict__ B,
             __half* __restrict__ C,
             int M, int N, int K, int lda, int ldb, int ldc,
             long long sA, long long sB, long long sC)
{
    constexpr int NSTAGE = 4, PF = 3;
    constexpr int ASTG = 64 * AASTR;
    constexpr int BSTG = AVBK * BVSTR;
    extern __shared__ float smem[];
    float* As = smem;
    float* Bs = smem + NSTAGE * ASTG;

    const float* Ab = A + (long long)blockIdx.z * sA;
    const float* Bb = B + (long long)blockIdx.z * sB;
    __half*      Cb = C + (long long)blockIdx.z * sC;

    const int m0 = blockIdx.y * 64;
    const int n0 = blockIdx.x * 64;
    const int tid  = threadIdx.x;
    const int lane = tid & 31;
    const int warp = tid >> 5;
    const int wm = (warp & 1) * 32;
    const int wn = (warp >> 1) * 32;
    const int g  = lane >> 2;
    const int tg = lane & 3;

    float c[2][4][4];
#pragma unroll
    for (int i = 0; i < 2; i++)
#pragma unroll
        for (int j = 0; j < 4; j++)
#pragma unroll
            for (int r = 0; r < 4; r++) c[i][j][r] = 0.f;

    const int nk = K / AVBK;

    auto load_tile = [&](int k0, int buf) {
        float* Ad = As + buf * ASTG;
        float* Bd = Bs + buf * BSTG;
#pragma unroll
        for (int j = 0; j < 2; j++) {
            const int cidx = tid + j * 128;
            const int row  = cidx >> 2;
            const int kc   = (cidx & 3) << 2;
            cpa16(Ad + row * AASTR + kc,
                  Ab + (long long)(m0 + row) * lda + k0 + kc,
                  (m0 + row) < M);
        }
#pragma unroll
        for (int j = 0; j < 2; j++) {
            const int cidx = tid + j * 128;
            const int row  = cidx >> 4;            // k row (16 chunks per row)
            const int col  = (cidx & 15) << 2;     // n offset
            cpa16(Bd + row * BVSTR + col,
                  Bb + (long long)(k0 + row) * ldb + n0 + col,
                  (n0 + col) < N);
        }
        asm volatile("cp.async.commit_group;\n");
    };

    for (int s = 0; s < PF; s++) {
        if (s < nk) load_tile(s * AVBK, s);
        else        asm volatile("cp.async.commit_group;\n");
    }

    for (int it = 0; it < nk; it++) {
        if (it + PF < nk) load_tile((it + PF) * AVBK, (it + PF) & 3);
        else              asm volatile("cp.async.commit_group;\n");
        asm volatile("cp.async.wait_group %0;\n" :: "n"(PF));
        __syncthreads();

        const int buf = it & 3;
        const float* Ac = As + buf * ASTG;
        const float* Bc = Bs + buf * BSTG;

#pragma unroll
        for (int ks = 0; ks < AVBK; ks += 8) {
            uint32_t bf[4][2];
#pragma unroll
            for (int nt = 0; nt < 4; nt++) {
                const float* bp = Bc + (ks + tg) * BVSTR + wn + nt * 8 + g;
                bf[nt][0] = f2tf(bp[0]);
                bf[nt][1] = f2tf(bp[4 * BVSTR]);
            }
            uint32_t af[2][4];
#pragma unroll
            for (int mt = 0; mt < 2; mt++) {
                const float* ap = Ac + (wm + mt * 16 + g) * AASTR + ks + tg;
                af[mt][0] = f2tf(ap[0]);
                af[mt][1] = f2tf(ap[8 * AASTR]);
                af[mt][2] = f2tf(ap[4]);
                af[mt][3] = f2tf(ap[8 * AASTR + 4]);
            }
#pragma unroll
            for (int mt = 0; mt < 2; mt++)
#pragma unroll
                for (int nt = 0; nt < 4; nt++)
                    mma_tf32(c[mt][nt], af[mt], bf[nt]);
        }
        __syncthreads();
    }

#pragma unroll
    for (int mt = 0; mt < 2; mt++) {
#pragma unroll
        for (int r = 0; r < 2; r++) {
            const int gm = m0 + wm + mt * 16 + g + r * 8;
            if (gm >= M) continue;
            __half* crow = Cb + (long long)gm * ldc;
#pragma unroll
            for (int nt = 0; nt < 4; nt++) {
                const int gn = n0 + wn + nt * 8 + tg * 2;
                if (gn >= N) continue;
                *(__half2*)(crow + gn) =
                    __floats2half2_rn(c[mt][nt][r * 2 + 0], c[mt][nt][r * 2 + 1]);
            }
        }
    }
}

#define AV_SMEM (4 * (64 * AASTR + AVBK * BVSTR) * 4)

// ---------------- setup kernel: fill pointer tables ----------------
__global__ void setup_tabs(const float* bq, const float* bk, const float* bv,
                           const float* bqa, const float* bka, const float* bva)
{
    g_hA[0] = g_hH; g_hA[1] = g_hH; g_hA[2] = g_hH;
    g_hB[0] = g_hW[0]; g_hB[1] = g_hW[1]; g_hB[2] = g_hW[2];
    g_tC[0] = g_Pq; g_tC[1] = g_Pk; g_tC[2] = g_Pv;
    g_tbias[0] = bq; g_tbias[1] = bk; g_tbias[2] = bv;

    g_hA[3] = g_hE; g_hA[4] = g_hE; g_hA[5] = g_hE;
    g_hB[3] = g_hW[3]; g_hB[4] = g_hW[4]; g_hB[5] = g_hW[5];
    g_tC[3] = g_Eq; g_tC[4] = g_Ek; g_tC[5] = g_Ev;
    g_tbias[3] = bqa; g_tbias[4] = bka; g_tbias[5] = bva;

    const __half* hm = g_hH + (long long)BLOCKL * DIMN;
    g_hA[6] = hm; g_hA[7] = hm; g_hA[8] = hm;
    g_hB[6] = g_hdn[0]; g_hB[7] = g_hdn[1]; g_hB[8] = g_hdn[2];
    g_tC[6] = g_DtP + 0 * (size_t)KSPLIT * CONDN * RANKN;
    g_tC[7] = g_DtP + 1 * (size_t)KSPLIT * CONDN * RANKN;
    g_tC[8] = g_DtP + 2 * (size_t)KSPLIT * CONDN * RANKN;
    g_tbias[6] = nullptr; g_tbias[7] = nullptr; g_tbias[8] = nullptr;

    g_hA[9]  = g_Dth + 0 * (size_t)CONDN * RANKN;
    g_hA[10] = g_Dth + 1 * (size_t)CONDN * RANKN;
    g_hA[11] = g_Dth + 2 * (size_t)CONDN * RANKN;
    g_hB[9] = g_hup[0]; g_hB[10] = g_hup[1]; g_hB[11] = g_hup[2];
    g_tC[9]  = g_Pq + (long long)BLOCKL * DIMN;
    g_tC[10] = g_Pk + (long long)BLOCKL * DIMN;
    g_tC[11] = g_Pv + (long long)BLOCKL * DIMN;
    g_tbias[9] = nullptr; g_tbias[10] = nullptr; g_tbias[11] = nullptr;
}

// ---------------- elementwise kernels ----------------
__global__ void h_copy(const float* __restrict__ s, __half* __restrict__ d, int n4)
{
    int i = blockIdx.x * 256 + threadIdx.x;
    if (i < n4) {
        float4 v = ((const float4*)s)[i];
        ((__half2*)d)[2 * i + 0] = __floats2half2_rn(v.x, v.y);
        ((__half2*)d)[2 * i + 1] = __floats2half2_rn(v.z, v.w);
    }
}

__global__ void build_qkv(const float* __restrict__ Pq, const float* __restrict__ Pk,
                          const float* __restrict__ Pv, const float* __restrict__ Eq,
                          const float* __restrict__ Ek, const float* __restrict__ Ev,
                          const float* __restrict__ rc, const float* __restrict__ rs,
                          const float* __restrict__ nqw, const float* __restrict__ nkw,
                          const float* __restrict__ naqw, const float* __restrict__ nakw,
                          __half* __restrict__ Qh, __half* __restrict__ Kh,
                          float* __restrict__ V)
{
    const int s = blockIdx.x;
    const int h = blockIdx.y;
    const int d = threadIdx.x;

    const float *sq, *sk, *sv, *wq, *wk;
    if (s < S_ENC) {
        const long long off = (long long)s * DIMN + h * HD;
        sq = Eq + off; sk = Ek + off; sv = Ev + off;
        wq = naqw; wk = nakw;
    } else {
        const long long off = (long long)(s - S_ENC) * DIMN + h * HD;
        sq = Pq + off; sk = Pk + off; sv = Pv + off;
        wq = nqw; wk = nkw;
    }
    float q = sq[d], k = sk[d], v = sv[d];

    float ssq = q * q, ssk = k * k;
#pragma unroll
    for (int o = 16; o; o >>= 1) {
        ssq += __shfl_xor_sync(0xffffffffu, ssq, o);
        ssk += __shfl_xor_sync(0xffffffffu, ssk, o);
    }
    __shared__ float shq[4], shk[4];
    const int w = d >> 5;
    if ((d & 31) == 0) { shq[w] = ssq; shk[w] = ssk; }
    __syncthreads();
    const float tq = shq[0] + shq[1] + shq[2] + shq[3];
    const float tk = shk[0] + shk[1] + shk[2] + shk[3];

    const float qn = q * rsqrtf(tq * (1.0f / HD) + 1e-6f) * wq[d];
    const float kn = k * rsqrtf(tk * (1.0f / HD) + 1e-6f) * wk[d];

    const float qp = __shfl_xor_sync(0xffffffffu, qn, 1);
    const float kp = __shfl_xor_sync(0xffffffffu, kn, 1);
    const float qr = (d & 1) ? qp : -qp;
    const float kr = (d & 1) ? kp : -kp;

    const float cc = rc[(long long)s * HD + d];
    const float sn = rs[(long long)s * HD + d];

    const long long o = ((long long)h * SEQ + s) * HD + d;
    Qh[o] = __float2half_rn(qn * cc + qr * sn);
    Kh[o] = __float2half_rn(kn * cc + kr * sn);
    V[o] = v;
}

// register-cached softmax: 1 global read + 1 global write per element
template <int NC>
__global__ void softmax_k(float* __restrict__ S)
{
    constexpr int PT = NC / 256;
    float* r = S + (long long)blockIdx.x * NC;
    const int tid = threadIdx.x;
    __shared__ float sh[8];

    float v[PT];
#pragma unroll
    for (int i = 0; i < PT; i++) v[i] = r[tid + i * 256];

    float m = v[0];
#pragma unroll
    for (int i = 1; i < PT; i++) m = fmaxf(m, v[i]);
#pragma unroll
    for (int o = 16; o; o >>= 1) m = fmaxf(m, __shfl_xor_sync(0xffffffffu, m, o));
    if ((tid & 31) == 0) sh[tid >> 5] = m;
    __syncthreads();
    float bm = sh[0];
#pragma unroll
    for (int i = 1; i < 8; i++) bm = fmaxf(bm, sh[i]);
    __syncthreads();

    float sum = 0.f;
#pragma unroll
    for (int i = 0; i < PT; i++) {
        v[i] = expf(v[i] - bm);
        sum += v[i];
    }
#pragma unroll
    for (int o = 16; o; o >>= 1) sum += __shfl_xor_sync(0xffffffffu, sum, o);
    if ((tid & 31) == 0) sh[tid >> 5] = sum;
    __syncthreads();
    float bs = 0.f;
#pragma unroll
    for (int i = 0; i < 8; i++) bs += sh[i];
    const float inv = 1.0f / bs;
#pragma unroll
    for (int i = 0; i < PT; i++) r[tid + i * 256] = v[i] * inv;
}

__global__ void mean_part(const float* __restrict__ V, float* __restrict__ P)
{
    const int h  = blockIdx.x;
    const int ch = blockIdx.y;
    const int d  = threadIdx.x;
    const float* base = V + ((long long)h * SEQ + ch * (SEQ / SCHUNK)) * HD + d;
    float s = 0.f;
#pragma unroll 4
    for (int i = 0; i < SEQ / SCHUNK; i++) s += base[(long long)i * HD];
    P[(size_t)ch * DIMN + h * HD + d] = s;
}

__global__ void mean_fin(const float* __restrict__ P, float* __restrict__ mean)
{
    const int j = blockIdx.x * 256 + threadIdx.x;
    float s = 0.f;
#pragma unroll
    for (int c = 0; c < SCHUNK; c++) s += P[(size_t)c * DIMN + j];
    mean[j] = s * (1.0f / SEQ);
}

__global__ void gemv_out(const float* __restrict__ mean, const float* __restrict__ Wo,
                         const float* __restrict__ bo, float* __restrict__ vec)
{
    const int j = blockIdx.x * 8 + (threadIdx.x >> 5);
    const int lane = threadIdx.x & 31;
    const float* w = Wo + (long long)j * DIMN;
    float s = 0.f;
    for (int d = lane; d < DIMN; d += 32) s += mean[d] * w[d];
#pragma unroll
    for (int o = 16; o; o >>= 1) s += __shfl_xor_sync(0xffffffffu, s, o);
    if (lane == 0) vec[j] = s + bo[j];
}

__global__ void fill_rows(const float* __restrict__ vec, float* __restrict__ out)
{
    const long long i = (long long)blockIdx.x * 256 + threadIdx.x;
    const float4 v = ((const float4*)vec)[i % (DIMN / 4)];
    ((float4*)out)[i] = v;
}

__global__ void reduce_splitk3(const float* __restrict__ P, __half* __restrict__ D)
{
    const int i = blockIdx.y;
    const int j = blockIdx.x * 256 + threadIdx.x;
    const float* base = P + (size_t)i * KSPLIT * CONDN * RANKN + j;
    float s = 0.f;
#pragma unroll
    for (int z = 0; z < KSPLIT; z++) s += base[(size_t)z * CONDN * RANKN];
    D[(size_t)i * CONDN * RANKN + j] = __float2half_rn(s);
}

// ---------------- host-side launch helpers ----------------
#define NULLTAB nullptr, nullptr, nullptr, nullptr, 1

static void f16_big(const __half* A, const __half* B, const float* bias, float* C,
                    int M, int N, int K, int lda, int ldb, int ldc,
                    long long sA, long long sB, long long sC, int batch,
                    float alpha, const float* aptr, float beta)
{
    dim3 g((N + 63) / 64, (M + 127) / 128, batch);
    gemm_f16<128, 64, 256, 4, 2, 4, 4, 3, false><<<g, 256, BIGH_SMEM>>>(
        A, B, bias, C, NULLTAB, M, N, K, lda, ldb, ldc, sA, sB, sC, alpha, aptr, beta);
}

static void f16_small(const __half* A, const __half* B, const float* bias, float* C,
                      int M, int N, int K, int lda, int ldb, int ldc,
                      long long sA, long long sB, long long sC, int batch,
                      float alpha, const float* aptr, float beta)
{
    dim3 g((N + 63) / 64, (M + 63) / 64, batch);
    gemm_f16<64, 64, 128, 4, 2, 4, 2, 4, false><<<g, 128, SMALLH_SMEM>>>(
        A, B, bias, C, NULLTAB, M, N, K, lda, ldb, ldc, sA, sB, sC, alpha, aptr, beta);
}

static void f16_big_tab(const __half* const* tA, const __half* const* tB,
                        const float* const* tbias, float* const* tC,
                        int zcnt, int zdiv,
                        int M, int N, int K, int lda, int ldb, int ldc,
                        long long sA, long long sB, long long sC,
                        float alpha, const float* aptr, float beta)
{
    dim3 g((N + 63) / 64, (M + 127) / 128, zcnt);
    gemm_f16<128, 64, 256, 4, 2, 4, 4, 3, true><<<g, 256, BIGH_SMEM>>>(
        nullptr, nullptr, nullptr, nullptr, tA, tB, tbias, tC, zdiv,
        M, N, K, lda, ldb, ldc, sA, sB, sC, alpha, aptr, beta);
}

static void f16_small_tab(const __half* const* tA, const __half* const* tB,
                          const float* const* tbias, float* const* tC,
                          int zcnt, int zdiv,
                          int M, int N, int K, int lda, int ldb, int ldc,
                          long long sA, long long sB, long long sC,
                          float alpha, const float* aptr, float beta)
{
    dim3 g((N + 63) / 64, (M + 63) / 64, zcnt);
    gemm_f16<64, 64, 128, 4, 2, 4, 2, 4, true><<<g, 128, SMALLH_SMEM>>>(
        nullptr, nullptr, nullptr, nullptr, tA, tB, tbias, tC, zdiv,
        M, N, K, lda, ldb, ldc, sA, sB, sC, alpha, aptr, beta);
}

static void hcopy(const float* s, __half* d, long long n)
{
    int n4 = (int)(n / 4);
    h_copy<<<(n4 + 255) / 256, 256>>>(s, d, n4);
}

extern "C" void kernel_launch(void* const* d_in, const int* in_sizes, int n_in,
                              void* d_out, int out_size)
{
    const float* hidden = (const float*)d_in[0];
    const float* enc    = (const float*)d_in[1];
    const float* rc     = (const float*)d_in[2];
    const float* rs     = (const float*)d_in[3];
    const float* Wq  = (const float*)d_in[4];
    const float* Wk  = (const float*)d_in[5];
    const float* Wv  = (const float*)d_in[6];
    const float* Wqa = (const float*)d_in[7];
    const float* Wka = (const float*)d_in[8];
    const float* Wva = (const float*)d_in[9];
    const float* Wo  = (const float*)d_in[10];
    const float* Woa = (const float*)d_in[11];
    const float* bq  = (const float*)d_in[12];
    const float* bk  = (const float*)d_in[13];
    const float* bv  = (const float*)d_in[14];
    const float* bqa = (const float*)d_in[15];
    const float* bka = (const float*)d_in[16];
    const float* bva = (const float*)d_in[17];
    const float* bo  = (const float*)d_in[18];
    const float* boa = (const float*)d_in[19];
    const float* nqw  = (const float*)d_in[20];
    const float* nkw  = (const float*)d_in[21];
    const float* naqw = (const float*)d_in[22];
    const float* nakw = (const float*)d_in[23];
    const float* qd = (const float*)d_in[24];
    const float* kd = (const float*)d_in[25];
    const float* vd = (const float*)d_in[26];
    const float* qu = (const float*)d_in[27];
    const float* ku = (const float*)d_in[28];
    const float* vu = (const float*)d_in[29];
    const float* lw = (const float*)d_in[30];

    float *Pq, *Pk, *Pv, *Eq, *Ek, *Ev, *DtP, *V, *SA, *SB, *mnP, *mean, *vec;
    __half *hH, *hE, *hW, *hdn, *hup, *Qh, *Kh, *Dth, *AOh;
    cudaGetSymbolAddress((void**)&Pq, g_Pq);
    cudaGetSymbolAddress((void**)&Pk, g_Pk);
    cudaGetSymbolAddress((void**)&Pv, g_Pv);
    cudaGetSymbolAddress((void**)&Eq, g_Eq);
    cudaGetSymbolAddress((void**)&Ek, g_Ek);
    cudaGetSymbolAddress((void**)&Ev, g_Ev);
    cudaGetSymbolAddress((void**)&DtP, g_DtP);
    cudaGetSymbolAddress((void**)&V,  g_V);
    cudaGetSymbolAddress((void**)&SA, g_SA);
    cudaGetSymbolAddress((void**)&SB, g_SB);
    cudaGetSymbolAddress((void**)&mnP, g_mnP);
    cudaGetSymbolAddress((void**)&mean, g_mean);
    cudaGetSymbolAddress((void**)&vec,  g_vec);
    cudaGetSymbolAddress((void**)&hH,  g_hH);
    cudaGetSymbolAddress((void**)&hE,  g_hE);
    cudaGetSymbolAddress((void**)&hW,  g_hW);
    cudaGetSymbolAddress((void**)&hdn, g_hdn);
    cudaGetSymbolAddress((void**)&hup, g_hup);
    cudaGetSymbolAddress((void**)&Qh,  g_Qh);
    cudaGetSymbolAddress((void**)&Kh,  g_Kh);
    cudaGetSymbolAddress((void**)&Dth, g_Dth);
    cudaGetSymbolAddress((void**)&AOh, g_AOh);

    const __half* const* tA;
    const __half* const* tB;
    const float* const* tbias;
    float* const* tC;
    {
        void *pA, *pB, *pb, *pC;
        cudaGetSymbolAddress(&pA, g_hA);
        cudaGetSymbolAddress(&pB, g_hB);
        cudaGetSymbolAddress(&pb, g_tbias);
        cudaGetSymbolAddress(&pC, g_tC);
        tA = (const __half* const*)pA;
        tB = (const __half* const*)pB;
        tbias = (const float* const*)pb;
        tC = (float* const*)pC;
    }

    float* out = (float*)d_out;

    // REQUIRED smem opt-ins (launches fail without them)
    cudaFuncSetAttribute(gemm_f16<128, 64, 256, 4, 2, 4, 4, 3, false>,
                         cudaFuncAttributeMaxDynamicSharedMemorySize, BIGH_SMEM);
    cudaFuncSetAttribute(gemm_f16<128, 64, 256, 4, 2, 4, 4, 3, true>,
                         cudaFuncAttributeMaxDynamicSharedMemorySize, BIGH_SMEM);
    cudaFuncSetAttribute(gemm_f16<64, 64, 128, 4, 2, 4, 2, 4, false>,
                         cudaFuncAttributeMaxDynamicSharedMemorySize, SMALLH_SMEM);
    cudaFuncSetAttribute(gemm_f16<64, 64, 128, 4, 2, 4, 2, 4, true>,
                         cudaFuncAttributeMaxDynamicSharedMemorySize, SMALLH_SMEM);
    cudaFuncSetAttribute(gemm_av,
                         cudaFuncAttributeMaxDynamicSharedMemorySize, AV_SMEM);

    // 0) convert operands to half + fill tables
    hcopy(hidden, hH, (long long)S_HID * DIMN);
    hcopy(enc,    hE, (long long)S_ENC * DIMN);
    const float* Ws[8] = {Wq, Wk, Wv, Wqa, Wka, Wva, Wo, Woa};
    for (int i = 0; i < 8; i++)
        hcopy(Ws[i], hW + (long long)i * DIMN * DIMN, (long long)DIMN * DIMN);
    hcopy(qd, hdn + 0 * (long long)RANKN * DIMN, (long long)RANKN * DIMN);
    hcopy(kd, hdn + 1 * (long long)RANKN * DIMN, (long long)RANKN * DIMN);
    hcopy(vd, hdn + 2 * (long long)RANKN * DIMN, (long long)RANKN * DIMN);
    hcopy(qu, hup + 0 * (long long)DIMN * RANKN, (long long)DIMN * RANKN);
    hcopy(ku, hup + 1 * (long long)DIMN * RANKN, (long long)DIMN * RANKN);
    hcopy(vu, hup + 2 * (long long)DIMN * RANKN, (long long)DIMN * RANKN);
    setup_tabs<<<1, 1>>>(bq, bk, bv, bqa, bka, bva);

    // 1) image q/k/v projections — one batched f16 launch
    f16_big_tab(tA + 0, tB + 0, tbias + 0, tC + 0, 3, 1,
                S_HID, DIMN, DIMN, DIMN, DIMN, DIMN, 0, 0, 0, 1.f, nullptr, 0.f);

    // 2) encoder projections — one batched f16 launch
    f16_small_tab(tA + 3, tB + 3, tbias + 3, tC + 3, 3, 1,
                  S_ENC, DIMN, DIMN, DIMN, DIMN, DIMN, 0, 0, 0, 1.f, nullptr, 0.f);

    // 3) LoRA down (3 branches x split-K 16, one launch) -> reduce -> up (one launch)
    f16_small_tab(tA + 6, tB + 6, tbias + 6, tC + 6, 3 * KSPLIT, KSPLIT,
                  CONDN, RANKN, DIMN / KSPLIT, DIMN, DIMN, RANKN,
                  DIMN / KSPLIT, DIMN / KSPLIT, (long long)CONDN * RANKN,
                  1.f, nullptr, 0.f);
    {
        dim3 rg((CONDN * RANKN) / 256, 3);
        reduce_splitk3<<<rg, 256>>>(DtP, Dth);
    }
    f16_small_tab(tA + 9, tB + 9, tbias + 9, tC + 9, 3, 1,
                  CONDN, DIMN, RANKN, RANKN, RANKN, DIMN, 0, 0, 0, 1.f, lw, 1.f);

    // 4) heads + RMSNorm + RoPE; Q/K half, V f32 natural layout
    build_qkv<<<dim3(SEQ, HEADS), HD>>>(Pq, Pk, Pv, Eq, Ek, Ev, rc, rs,
                                        nqw, nkw, naqw, nakw, Qh, Kh, V);

    // 5) block A: encoder queries vs full keys (f16 QK), softmax, AV (tf32->half)
    f16_big(Qh, Kh, nullptr, SA, S_ENC, SEQ, HD, HD, HD, SEQ,
            (long long)SEQ * HD, (long long)SEQ * HD, (long long)S_ENC * SEQ, HEADS,
            ATTN_SCALE, nullptr, 0.f);
    softmax_k<SEQ><<<HEADS * S_ENC, 256>>>(SA);
    {
        dim3 g(HD / 64, S_ENC / 64, HEADS);
        gemm_av<<<g, 128, AV_SMEM>>>(SA, V, AOh, S_ENC, HD, SEQ, SEQ, HD, DIMN,
                                     (long long)S_ENC * SEQ, (long long)SEQ * HD, HD);
    }

    // 6) block B: cond queries vs cond keys
    f16_big(Qh + (long long)S_ENC * HD, Kh + (long long)S_ENC * HD, nullptr, SB,
            CONDN, CONDN, HD, HD, HD, CONDN,
            (long long)SEQ * HD, (long long)SEQ * HD, (long long)CONDN * CONDN, HEADS,
            ATTN_SCALE, nullptr, 0.f);
    softmax_k<CONDN><<<HEADS * CONDN, 256>>>(SB);
    {
        dim3 g(HD / 64, CONDN / 64, HEADS);
        gemm_av<<<g, 128, AV_SMEM>>>(SB, V + (long long)S_ENC * HD,
                                     AOh + (long long)S_ENC * DIMN,
                                     CONDN, HD, CONDN, CONDN, HD, DIMN,
                                     (long long)CONDN * CONDN, (long long)SEQ * HD, HD);
    }

    // 7) fully-masked rows -> uniform softmax -> mean of V; one out-proj row
    mean_part<<<dim3(HEADS, SCHUNK), HD>>>(V, mnP);
    mean_fin<<<DIMN / 256, 256>>>(mnP, mean);
    gemv_out<<<DIMN / 8, 256>>>(mean, Wo, bo, vec);

    // 8) output projections (f16)
    f16_big(AOh + (long long)S_ENC * DIMN, hW + 6 * (long long)DIMN * DIMN, bo, out,
            CONDN, DIMN, DIMN, DIMN, DIMN, DIMN, 0, 0, 0, 1, 1.f, nullptr, 0.f);
    fill_rows<<<(NROWS_C * (DIMN / 4)) / 256, 256>>>(vec, out + (long long)CONDN * DIMN);
    f16_small(AOh, hW + 7 * (long long)DIMN * DIMN, boa, out + (long long)S_HID * DIMN,
              S_ENC, DIMN, DIMN, DIMN, DIMN, DIMN, 0, 0, 0, 1, 1.f, nullptr, 0.f);
}

// round 15
// speedup vs baseline: 1.7806x; 1.1038x over previous
#include <cuda_runtime.h>
#include <cuda_fp16.h>
#include <math.h>
#include <stdint.h>

// ---------------- problem constants ----------------
#define DIMN   3072
#define HEADS  24
#define HD     128
#define S_HID  3072
#define S_ENC  512
#define SEQ    3584          // S_ENC + S_HID
#define CONDN  1024
#define RANKN  64
#define BLOCKL 2048          // S_HID - CONDN
#define NROWS_C (SEQ - S_ENC - CONDN)   // 2048 fully-masked query rows
#define KSPLIT 16            // split-K for LoRA down-proj
#define SCHUNK 28            // mean s-chunks (SEQ = 28*128)
static const float ATTN_SCALE = 0.08838834764831843f; // 1/sqrt(128)

// ---------------- device scratch (no allocs allowed) ----------------
__device__ float g_Pq[(size_t)S_HID * DIMN];   // only rows [0,1024) used
__device__ float g_Pk[(size_t)S_HID * DIMN];
__device__ float g_Pv[(size_t)S_HID * DIMN];
__device__ float g_Eq[(size_t)S_ENC * DIMN];
__device__ float g_Ek[(size_t)S_ENC * DIMN];
__device__ float g_Ev[(size_t)S_ENC * DIMN];
__device__ float g_DtP[(size_t)2 * KSPLIT * CONDN * RANKN];   // k, v branches
__device__ float g_V [(size_t)HEADS * SEQ * HD];      // natural layout [h][s][d]
__device__ float g_SA[(size_t)HEADS * S_ENC * SEQ];   // encoder-query scores
__device__ float g_SB[(size_t)HEADS * CONDN * CONDN]; // cond-block scores
__device__ float g_mnP[(size_t)SCHUNK * DIMN];
__device__ float g_mean[DIMN];
__device__ float g_vec [DIMN];
// half operand buffers
__device__ __half g_hH[(size_t)S_HID * DIMN];
__device__ __half g_hE[(size_t)S_ENC * DIMN];
__device__ __half g_hW[8][(size_t)DIMN * DIMN];   // Wq Wk Wv Wqa Wka Wva Wo Woa
__device__ __half g_hdn[2][(size_t)RANKN * DIMN]; // kd, vd
__device__ __half g_hup[2][(size_t)DIMN * RANKN]; // ku, vu
__device__ __half g_Qh[(size_t)HEADS * SEQ * HD];
__device__ __half g_Kh[(size_t)HEADS * SEQ * HD];
__device__ __half g_Dth[(size_t)2 * CONDN * RANKN];
__device__ __half g_AOh[(size_t)(S_ENC + CONDN) * DIMN];

// pointer tables for batched f16 GEMM groups:
// [0..1]=img k/v proj, [2..4]=enc proj, [5..6]=lora-down k/v, [7..8]=lora-up k/v
__device__ const __half* g_hA[9];
__device__ const __half* g_hB[9];
__device__ const float*  g_tbias[9];
__device__ float*        g_tC[9];
// fused conversion tables (14 entries)
__device__ const float* g_cS[14];
__device__ __half*      g_cD[14];

// conversion chunk counts (float4 units) — compile-time
#define C_HID (S_HID * DIMN / 4)
#define C_ENC (S_ENC * DIMN / 4)
#define C_W   (DIMN * DIMN / 4)
#define C_LR  (RANKN * DIMN / 4)
#define C_TOTAL (C_HID + C_ENC + 8 * C_W + 4 * C_LR)

// ---------------- helpers ----------------
__device__ __forceinline__ uint32_t f2tf(float f) {
    uint32_t u;
    asm("cvt.rna.tf32.f32 %0, %1;" : "=r"(u) : "f"(f));
    return u;
}

__device__ __forceinline__ void cpa16(void* dst, const void* src, bool pred) {
    uint32_t d = (uint32_t)__cvta_generic_to_shared(dst);
    int sz = pred ? 16 : 0;   // src-size 0 => zero-fill
    asm volatile("cp.async.cg.shared.global [%0], [%1], 16, %2;\n"
                 :: "r"(d), "l"(src), "r"(sz));
}

__device__ __forceinline__ void mma_tf32(float* c, const uint32_t* a, const uint32_t* b) {
    asm volatile(
        "mma.sync.aligned.m16n8k8.row.col.f32.tf32.tf32.f32 "
        "{%0,%1,%2,%3}, {%4,%5,%6,%7}, {%8,%9}, {%0,%1,%2,%3};\n"
        : "+f"(c[0]), "+f"(c[1]), "+f"(c[2]), "+f"(c[3])
        : "r"(a[0]), "r"(a[1]), "r"(a[2]), "r"(a[3]), "r"(b[0]), "r"(b[1]));
}

__device__ __forceinline__ void mma_f16(float* c, const uint32_t* a, const uint32_t* b) {
    asm volatile(
        "mma.sync.aligned.m16n8k16.row.col.f32.f16.f16.f32 "
        "{%0,%1,%2,%3}, {%4,%5,%6,%7}, {%8,%9}, {%0,%1,%2,%3};\n"
        : "+f"(c[0]), "+f"(c[1]), "+f"(c[2]), "+f"(c[3])
        : "r"(a[0]), "r"(a[1]), "r"(a[2]), "r"(a[3]), "r"(b[0]), "r"(b[1]));
}

// ---------------- fp16 tensor-core GEMM ----------------
// C(f32) = alpha * A[M,K](half) @ B[N,K]^T(half) + bias + beta*C.
// BK = 32 halves per stage; smem rows stride 20 half2 (conflict-free).
// TAB: operands from pointer tables (zi = z/zdiv entry, zr*strides = split-K).
#define ASTRH 20   // smem row stride in half2 units

template <int TBM, int TBN, int THREADS, int NSTAGE, int MT, int NT, int WMC,
          int OCC, bool TAB>
__global__ __launch_bounds__(THREADS, OCC)
void gemm_f16(const __half* __restrict__ A, const __half* __restrict__ B,
              const float* __restrict__ bias, float* __restrict__ C,
              const __half* const* __restrict__ Aarr,
              const __half* const* __restrict__ Barr,
              const float* const* __restrict__ biasarr,
              float* const* __restrict__ Carr, int zdiv,
              int M, int N, int K, int lda, int ldb, int ldc,
              long long sA, long long sB, long long sC,
              float alpha, const float* __restrict__ alpha_ptr, float beta)
{
    constexpr int PF = NSTAGE - 1;
    constexpr int ASTG = TBM * ASTRH;   // half2 per A stage
    constexpr int BSTG = TBN * ASTRH;
    extern __shared__ uint32_t smh[];
    uint32_t* As = smh;
    uint32_t* Bs = smh + NSTAGE * ASTG;

    const __half* Ab;
    const __half* Bb;
    float*        Cb;
    const float*  biasb;
    if (TAB) {
        const int zi = blockIdx.z / zdiv;
        const int zr = blockIdx.z - zi * zdiv;
        Ab = Aarr[zi] + (long long)zr * sA;
        Bb = Barr[zi] + (long long)zr * sB;
        Cb = Carr[zi] + (long long)zr * sC;
        biasb = biasarr[zi];
    } else {
        Ab = A + (long long)blockIdx.z * sA;
        Bb = B + (long long)blockIdx.z * sB;
        Cb = C + (long long)blockIdx.z * sC;
        biasb = bias;
    }

    const int m0 = blockIdx.y * TBM;
    const int n0 = blockIdx.x * TBN;
    const int tid  = threadIdx.x;
    const int lane = tid & 31;
    const int warp = tid >> 5;
    const int wm = (warp % WMC) * (MT * 16);
    const int wn = (warp / WMC) * (NT * 8);
    const int g  = lane >> 2;
    const int tg = lane & 3;

    float c[MT][NT][4];
#pragma unroll
    for (int i = 0; i < MT; i++)
#pragma unroll
        for (int j = 0; j < NT; j++)
#pragma unroll
            for (int r = 0; r < 4; r++) c[i][j][r] = 0.f;

    const int nk = K / 32;

    auto load_tile = [&](int k0 /*halves*/, int buf) {
        uint32_t* Ad = As + buf * ASTG;
        uint32_t* Bd = Bs + buf * BSTG;
#pragma unroll
        for (int j = 0; j < TBM * 4 / THREADS; j++) {
            const int cidx = tid + j * THREADS;
            const int row  = cidx >> 2;
            const int ch2  = (cidx & 3) << 2;     // half2 offset in row
            cpa16(Ad + row * ASTRH + ch2,
                  Ab + (long long)(m0 + row) * lda + k0 + ch2 * 2,
                  (m0 + row) < M);
        }
#pragma unroll
        for (int j = 0; j < TBN * 4 / THREADS; j++) {
            const int cidx = tid + j * THREADS;
            const int row  = cidx >> 2;
            const int ch2  = (cidx & 3) << 2;
            cpa16(Bd + row * ASTRH + ch2,
                  Bb + (long long)(n0 + row) * ldb + k0 + ch2 * 2,
                  (n0 + row) < N);
        }
        asm volatile("cp.async.commit_group;\n");
    };

    for (int s = 0; s < PF; s++) {
        if (s < nk) load_tile(s * 32, s);
        else        asm volatile("cp.async.commit_group;\n");
    }

    for (int it = 0; it < nk; it++) {
        if (it + PF < nk) load_tile((it + PF) * 32, (it + PF) & (NSTAGE - 1));
        else              asm volatile("cp.async.commit_group;\n");
        asm volatile("cp.async.wait_group %0;\n" :: "n"(PF));
        __syncthreads();

        const int buf = it & (NSTAGE - 1);
        const uint32_t* Ac = As + buf * ASTG;
        const uint32_t* Bc = Bs + buf * BSTG;

#pragma unroll
        for (int s16 = 0; s16 < 2; s16++) {       // two k16 steps per BK=32
            const int cb = s16 * 8;               // half2 column base
            uint32_t bf[NT][2];
#pragma unroll
            for (int nt = 0; nt < NT; nt++) {
                const uint32_t* bp = Bc + (wn + nt * 8 + g) * ASTRH + cb + tg;
                bf[nt][0] = bp[0];
                bf[nt][1] = bp[4];
            }
            uint32_t af[MT][4];
#pragma unroll
            for (int mt = 0; mt < MT; mt++) {
                const uint32_t* ap = Ac + (wm + mt * 16 + g) * ASTRH + cb + tg;
                af[mt][0] = ap[0];
                af[mt][1] = ap[8 * ASTRH];
                af[mt][2] = ap[4];
                af[mt][3] = ap[8 * ASTRH + 4];
            }
#pragma unroll
            for (int mt = 0; mt < MT; mt++)
#pragma unroll
                for (int nt = 0; nt < NT; nt++)
                    mma_f16(c[mt][nt], af[mt], bf[nt]);
        }
        __syncthreads();
    }

    float aE = alpha;
    if (alpha_ptr) aE *= *alpha_ptr;

#pragma unroll
    for (int mt = 0; mt < MT; mt++) {
#pragma unroll
        for (int r = 0; r < 2; r++) {
            const int gm = m0 + wm + mt * 16 + g + r * 8;
            if (gm >= M) continue;
            float* crow = Cb + (long long)gm * ldc;
#pragma unroll
            for (int nt = 0; nt < NT; nt++) {
                const int gn = n0 + wn + nt * 8 + tg * 2;
                if (gn >= N) continue;
                float x = c[mt][nt][r * 2 + 0] * aE;
                float y = c[mt][nt][r * 2 + 1] * aE;
                if (biasb) { x += biasb[gn]; y += biasb[gn + 1]; }
                if (beta != 0.f) {
                    float2 p = *(const float2*)(crow + gn);
                    x += beta * p.x; y += beta * p.y;
                }
                *(float2*)(crow + gn) = make_float2(x, y);
            }
        }
    }
}

#define BIGH_SMEM   (4 * (128 + 64) * ASTRH * 4)
#define SMALLH_SMEM (4 * ( 64 + 64) * ASTRH * 4)

// ---------------- tf32 AV GEMM: AO(half) = P(f32)[M,K] @ V(f32)[K,N] ----------------
#define AVBK 16
#define AASTR 20
#define BVSTR 68

__global__ __launch_bounds__(128, 4)
void gemm_av(const float* __restrict__ A, const float* __restrict__ B,
             __half* __restrict__ C,
             int M, int N, int K, int lda, int ldb, int ldc,
             long long sA, long long sB, long long sC)
{
    constexpr int NSTAGE = 4, PF = 3;
    constexpr int ASTG = 64 * AASTR;
    constexpr int BSTG = AVBK * BVSTR;
    extern __shared__ float smem[];
    float* As = smem;
    float* Bs = smem + NSTAGE * ASTG;

    const float* Ab = A + (long long)blockIdx.z * sA;
    const float* Bb = B + (long long)blockIdx.z * sB;
    __half*      Cb = C + (long long)blockIdx.z * sC;

    const int m0 = blockIdx.y * 64;
    const int n0 = blockIdx.x * 64;
    const int tid  = threadIdx.x;
    const int lane = tid & 31;
    const int warp = tid >> 5;
    const int wm = (warp & 1) * 32;
    const int wn = (warp >> 1) * 32;
    const int g  = lane >> 2;
    const int tg = lane & 3;

    float c[2][4][4];
#pragma unroll
    for (int i = 0; i < 2; i++)
#pragma unroll
        for (int j = 0; j < 4; j++)
#pragma unroll
            for (int r = 0; r < 4; r++) c[i][j][r] = 0.f;

    const int nk = K / AVBK;

    auto load_tile = [&](int k0, int buf) {
        float* Ad = As + buf * ASTG;
        float* Bd = Bs + buf * BSTG;
#pragma unroll
        for (int j = 0; j < 2; j++) {
            const int cidx = tid + j * 128;
            const int row  = cidx >> 2;
            const int kc   = (cidx & 3) << 2;
            cpa16(Ad + row * AASTR + kc,
                  Ab + (long long)(m0 + row) * lda + k0 + kc,
                  (m0 + row) < M);
        }
#pragma unroll
        for (int j = 0; j < 2; j++) {
            const int cidx = tid + j * 128;
            const int row  = cidx >> 4;
            const int col  = (cidx & 15) << 2;
            cpa16(Bd + row * BVSTR + col,
                  Bb + (long long)(k0 + row) * ldb + n0 + col,
                  (n0 + col) < N);
        }
        asm volatile("cp.async.commit_group;\n");
    };

    for (int s = 0; s < PF; s++) {
        if (s < nk) load_tile(s * AVBK, s);
        else        asm volatile("cp.async.commit_group;\n");
    }

    for (int it = 0; it < nk; it++) {
        if (it + PF < nk) load_tile((it + PF) * AVBK, (it + PF) & 3);
        else              asm volatile("cp.async.commit_group;\n");
        asm volatile("cp.async.wait_group %0;\n" :: "n"(PF));
        __syncthreads();

        const int buf = it & 3;
        const float* Ac = As + buf * ASTG;
        const float* Bc = Bs + buf * BSTG;

#pragma unroll
        for (int ks = 0; ks < AVBK; ks += 8) {
            uint32_t bf[4][2];
#pragma unroll
            for (int nt = 0; nt < 4; nt++) {
                const float* bp = Bc + (ks + tg) * BVSTR + wn + nt * 8 + g;
                bf[nt][0] = f2tf(bp[0]);
                bf[nt][1] = f2tf(bp[4 * BVSTR]);
            }
            uint32_t af[2][4];
#pragma unroll
            for (int mt = 0; mt < 2; mt++) {
                const float* ap = Ac + (wm + mt * 16 + g) * AASTR + ks + tg;
                af[mt][0] = f2tf(ap[0]);
                af[mt][1] = f2tf(ap[8 * AASTR]);
                af[mt][2] = f2tf(ap[4]);
                af[mt][3] = f2tf(ap[8 * AASTR + 4]);
            }
#pragma unroll
            for (int mt = 0; mt < 2; mt++)
#pragma unroll
                for (int nt = 0; nt < 4; nt++)
                    mma_tf32(c[mt][nt], af[mt], bf[nt]);
        }
        __syncthreads();
    }

#pragma unroll
    for (int mt = 0; mt < 2; mt++) {
#pragma unroll
        for (int r = 0; r < 2; r++) {
            const int gm = m0 + wm + mt * 16 + g + r * 8;
            if (gm >= M) continue;
            __half* crow = Cb + (long long)gm * ldc;
#pragma unroll
            for (int nt = 0; nt < 4; nt++) {
                const int gn = n0 + wn + nt * 8 + tg * 2;
                if (gn >= N) continue;
                *(__half2*)(crow + gn) =
                    __floats2half2_rn(c[mt][nt][r * 2 + 0], c[mt][nt][r * 2 + 1]);
            }
        }
    }
}

#define AV_SMEM (4 * (64 * AASTR + AVBK * BVSTR) * 4)

// ---------------- setup kernel: fill pointer tables ----------------
__global__ void setup_tabs(const float* hidden, const float* enc,
                           const float* Wq, const float* Wk, const float* Wv,
                           const float* Wqa, const float* Wka, const float* Wva,
                           const float* Wo, const float* Woa,
                           const float* bq, const float* bk, const float* bv,
                           const float* bqa, const float* bka, const float* bva,
                           const float* kd, const float* vd,
                           const float* ku, const float* vu)
{
    // conversion tables
    g_cS[0] = hidden; g_cD[0] = g_hH;
    g_cS[1] = enc;    g_cD[1] = g_hE;
    const float* Ws[8] = {Wq, Wk, Wv, Wqa, Wka, Wva, Wo, Woa};
    for (int i = 0; i < 8; i++) { g_cS[2 + i] = Ws[i]; g_cD[2 + i] = g_hW[i]; }
    g_cS[10] = kd; g_cD[10] = g_hdn[0];
    g_cS[11] = vd; g_cD[11] = g_hdn[1];
    g_cS[12] = ku; g_cD[12] = g_hup[0];
    g_cS[13] = vu; g_cD[13] = g_hup[1];

    // GEMM tables
    // [0..1] image k/v projections (q handled separately, M=1024)
    g_hA[0] = g_hH; g_hA[1] = g_hH;
    g_hB[0] = g_hW[1]; g_hB[1] = g_hW[2];
    g_tC[0] = g_Pk; g_tC[1] = g_Pv;
    g_tbias[0] = bk; g_tbias[1] = bv;
    // [2..4] encoder projections
    g_hA[2] = g_hE; g_hA[3] = g_hE; g_hA[4] = g_hE;
    g_hB[2] = g_hW[3]; g_hB[3] = g_hW[4]; g_hB[4] = g_hW[5];
    g_tC[2] = g_Eq; g_tC[3] = g_Ek; g_tC[4] = g_Ev;
    g_tbias[2] = bqa; g_tbias[3] = bka; g_tbias[4] = bva;
    // [5..6] LoRA down k/v (split-K via zr)
    const __half* hm = g_hH + (long long)BLOCKL * DIMN;
    g_hA[5] = hm; g_hA[6] = hm;
    g_hB[5] = g_hdn[0]; g_hB[6] = g_hdn[1];
    g_tC[5] = g_DtP + 0 * (size_t)KSPLIT * CONDN * RANKN;
    g_tC[6] = g_DtP + 1 * (size_t)KSPLIT * CONDN * RANKN;
    g_tbias[5] = nullptr; g_tbias[6] = nullptr;
    // [7..8] LoRA up k/v
    g_hA[7] = g_Dth + 0 * (size_t)CONDN * RANKN;
    g_hA[8] = g_Dth + 1 * (size_t)CONDN * RANKN;
    g_hB[7] = g_hup[0]; g_hB[8] = g_hup[1];
    g_tC[7] = g_Pk + (long long)BLOCKL * DIMN;
    g_tC[8] = g_Pv + (long long)BLOCKL * DIMN;
    g_tbias[7] = nullptr; g_tbias[8] = nullptr;
}

// ---------------- fused f32->f16 conversion (all operands, one launch) ----------------
__global__ void conv_all()
{
    int idx = blockIdx.x * 256 + threadIdx.x;
    const int sz[14] = {C_HID, C_ENC, C_W, C_W, C_W, C_W, C_W, C_W, C_W, C_W,
                        C_LR, C_LR, C_LR, C_LR};
#pragma unroll
    for (int e = 0; e < 14; e++) {
        if (idx < sz[e]) {
            float4 v = ((const float4*)g_cS[e])[idx];
            __half2* d = (__half2*)g_cD[e];
            d[2 * idx + 0] = __floats2half2_rn(v.x, v.y);
            d[2 * idx + 1] = __floats2half2_rn(v.z, v.w);
            return;
        }
        idx -= sz[e];
    }
}

// ---------------- elementwise kernels ----------------
__global__ void build_qkv(const float* __restrict__ Pq, const float* __restrict__ Pk,
                          const float* __restrict__ Pv, const float* __restrict__ Eq,
                          const float* __restrict__ Ek, const float* __restrict__ Ev,
                          const float* __restrict__ rc, const float* __restrict__ rs,
                          const float* __restrict__ nqw, const float* __restrict__ nkw,
                          const float* __restrict__ naqw, const float* __restrict__ nakw,
                          __half* __restrict__ Qh, __half* __restrict__ Kh,
                          float* __restrict__ V)
{
    const int s = blockIdx.x;
    const int h = blockIdx.y;
    const int d = threadIdx.x;
    const bool needQ = (s < S_ENC + CONDN);   // rows >= 1536 are fully masked

    const float *sq, *sk, *sv, *wq, *wk;
    if (s < S_ENC) {
        const long long off = (long long)s * DIMN + h * HD;
        sq = Eq + off; sk = Ek + off; sv = Ev + off;
        wq = naqw; wk = nakw;
    } else {
        const long long off = (long long)(s - S_ENC) * DIMN + h * HD;
        sq = Pq + off; sk = Pk + off; sv = Pv + off;
        wq = nqw; wk = nkw;
    }
    float q = needQ ? sq[d] : 0.f;
    float k = sk[d], v = sv[d];

    float ssq = q * q, ssk = k * k;
#pragma unroll
    for (int o = 16; o; o >>= 1) {
        ssq += __shfl_xor_sync(0xffffffffu, ssq, o);
        ssk += __shfl_xor_sync(0xffffffffu, ssk, o);
    }
    __shared__ float shq[4], shk[4];
    const int w = d >> 5;
    if ((d & 31) == 0) { shq[w] = ssq; shk[w] = ssk; }
    __syncthreads();
    const float tq = shq[0] + shq[1] + shq[2] + shq[3];
    const float tk = shk[0] + shk[1] + shk[2] + shk[3];

    const float qn = q * rsqrtf(tq * (1.0f / HD) + 1e-6f) * wq[d];
    const float kn = k * rsqrtf(tk * (1.0f / HD) + 1e-6f) * wk[d];

    const float qp = __shfl_xor_sync(0xffffffffu, qn, 1);
    const float kp = __shfl_xor_sync(0xffffffffu, kn, 1);
    const float qr = (d & 1) ? qp : -qp;
    const float kr = (d & 1) ? kp : -kp;

    const float cc = rc[(long long)s * HD + d];
    const float sn = rs[(long long)s * HD + d];

    const long long o = ((long long)h * SEQ + s) * HD + d;
    if (needQ) Qh[o] = __float2half_rn(qn * cc + qr * sn);
    Kh[o] = __float2half_rn(kn * cc + kr * sn);
    V[o] = v;
}

// register-cached softmax: 1 global read + 1 global write per element
template <int NC>
__global__ void softmax_k(float* __restrict__ S)
{
    constexpr int PT = NC / 256;
    float* r = S + (long long)blockIdx.x * NC;
    const int tid = threadIdx.x;
    __shared__ float sh[8];

    float v[PT];
#pragma unroll
    for (int i = 0; i < PT; i++) v[i] = r[tid + i * 256];

    float m = v[0];
#pragma unroll
    for (int i = 1; i < PT; i++) m = fmaxf(m, v[i]);
#pragma unroll
    for (int o = 16; o; o >>= 1) m = fmaxf(m, __shfl_xor_sync(0xffffffffu, m, o));
    if ((tid & 31) == 0) sh[tid >> 5] = m;
    __syncthreads();
    float bm = sh[0];
#pragma unroll
    for (int i = 1; i < 8; i++) bm = fmaxf(bm, sh[i]);
    __syncthreads();

    float sum = 0.f;
#pragma unroll
    for (int i = 0; i < PT; i++) {
        v[i] = expf(v[i] - bm);
        sum += v[i];
    }
#pragma unroll
    for (int o = 16; o; o >>= 1) sum += __shfl_xor_sync(0xffffffffu, sum, o);
    if ((tid & 31) == 0) sh[tid >> 5] = sum;
    __syncthreads();
    float bs = 0.f;
#pragma unroll
    for (int i = 0; i < 8; i++) bs += sh[i];
    const float inv = 1.0f / bs;
#pragma unroll
    for (int i = 0; i < PT; i++) r[tid + i * 256] = v[i] * inv;
}

__global__ void mean_part(const float* __restrict__ V, float* __restrict__ P)
{
    const int h  = blockIdx.x;
    const int ch = blockIdx.y;
    const int d  = threadIdx.x;
    const float* base = V + ((long long)h * SEQ + ch * (SEQ / SCHUNK)) * HD + d;
    float s = 0.f;
#pragma unroll 4
    for (int i = 0; i < SEQ / SCHUNK; i++) s += base[(long long)i * HD];
    P[(size_t)ch * DIMN + h * HD + d] = s;
}

__global__ void mean_fin(const float* __restrict__ P, float* __restrict__ mean)
{
    const int j = blockIdx.x * 256 + threadIdx.x;
    float s = 0.f;
#pragma unroll
    for (int c = 0; c < SCHUNK; c++) s += P[(size_t)c * DIMN + j];
    mean[j] = s * (1.0f / SEQ);
}

__global__ void gemv_out(const float* __restrict__ mean, const float* __restrict__ Wo,
                         const float* __restrict__ bo, float* __restrict__ vec)
{
    const int j = blockIdx.x * 8 + (threadIdx.x >> 5);
    const int lane = threadIdx.x & 31;
    const float* w = Wo + (long long)j * DIMN;
    float s = 0.f;
    for (int d = lane; d < DIMN; d += 32) s += mean[d] * w[d];
#pragma unroll
    for (int o = 16; o; o >>= 1) s += __shfl_xor_sync(0xffffffffu, s, o);
    if (lane == 0) vec[j] = s + bo[j];
}

__global__ void fill_rows(const float* __restrict__ vec, float* __restrict__ out)
{
    const long long i = (long long)blockIdx.x * 256 + threadIdx.x;
    const float4 v = ((const float4*)vec)[i % (DIMN / 4)];
    ((float4*)out)[i] = v;
}

__global__ void reduce_splitk2(const float* __restrict__ P, __half* __restrict__ D)
{
    const int i = blockIdx.y;   // branch (k=0, v=1)
    const int j = blockIdx.x * 256 + threadIdx.x;
    const float* base = P + (size_t)i * KSPLIT * CONDN * RANKN + j;
    float s = 0.f;
#pragma unroll
    for (int z = 0; z < KSPLIT; z++) s += base[(size_t)z * CONDN * RANKN];
    D[(size_t)i * CONDN * RANKN + j] = __float2half_rn(s);
}

// ---------------- host-side launch helpers ----------------
#define NULLTAB nullptr, nullptr, nullptr, nullptr, 1

static void f16_big(const __half* A, const __half* B, const float* bias, float* C,
                    int M, int N, int K, int lda, int ldb, int ldc,
                    long long sA, long long sB, long long sC, int batch,
                    float alpha, const float* aptr, float beta)
{
    dim3 g((N + 63) / 64, (M + 127) / 128, batch);
    gemm_f16<128, 64, 256, 4, 2, 4, 4, 3, false><<<g, 256, BIGH_SMEM>>>(
        A, B, bias, C, NULLTAB, M, N, K, lda, ldb, ldc, sA, sB, sC, alpha, aptr, beta);
}

static void f16_small(const __half* A, const __half* B, const float* bias, float* C,
                      int M, int N, int K, int lda, int ldb, int ldc,
                      long long sA, long long sB, long long sC, int batch,
                      float alpha, const float* aptr, float beta)
{
    dim3 g((N + 63) / 64, (M + 63) / 64, batch);
    gemm_f16<64, 64, 128, 4, 2, 4, 2, 4, false><<<g, 128, SMALLH_SMEM>>>(
        A, B, bias, C, NULLTAB, M, N, K, lda, ldb, ldc, sA, sB, sC, alpha, aptr, beta);
}

static void f16_big_tab(const __half* const* tA, const __half* const* tB,
                        const float* const* tbias, float* const* tC,
                        int zcnt, int zdiv,
                        int M, int N, int K, int lda, int ldb, int ldc,
                        long long sA, long long sB, long long sC,
                        float alpha, const float* aptr, float beta)
{
    dim3 g((N + 63) / 64, (M + 127) / 128, zcnt);
    gemm_f16<128, 64, 256, 4, 2, 4, 4, 3, true><<<g, 256, BIGH_SMEM>>>(
        nullptr, nullptr, nullptr, nullptr, tA, tB, tbias, tC, zdiv,
        M, N, K, lda, ldb, ldc, sA, sB, sC, alpha, aptr, beta);
}

static void f16_small_tab(const __half* const* tA, const __half* const* tB,
                          const float* const* tbias, float* const* tC,
                          int zcnt, int zdiv,
                          int M, int N, int K, int lda, int ldb, int ldc,
                          long long sA, long long sB, long long sC,
                          float alpha, const float* aptr, float beta)
{
    dim3 g((N + 63) / 64, (M + 63) / 64, zcnt);
    gemm_f16<64, 64, 128, 4, 2, 4, 2, 4, true><<<g, 128, SMALLH_SMEM>>>(
        nullptr, nullptr, nullptr, nullptr, tA, tB, tbias, tC, zdiv,
        M, N, K, lda, ldb, ldc, sA, sB, sC, alpha, aptr, beta);
}

extern "C" void kernel_launch(void* const* d_in, const int* in_sizes, int n_in,
                              void* d_out, int out_size)
{
    const float* hidden = (const float*)d_in[0];
    const float* enc    = (const float*)d_in[1];
    const float* rc     = (const float*)d_in[2];
    const float* rs     = (const float*)d_in[3];
    const float* Wq  = (const float*)d_in[4];
    const float* Wk  = (const float*)d_in[5];
    const float* Wv  = (const float*)d_in[6];
    const float* Wqa = (const float*)d_in[7];
    const float* Wka = (const float*)d_in[8];
    const float* Wva = (const float*)d_in[9];
    const float* Wo  = (const float*)d_in[10];
    const float* Woa = (const float*)d_in[11];
    const float* bq  = (const float*)d_in[12];
    const float* bk  = (const float*)d_in[13];
    const float* bv  = (const float*)d_in[14];
    const float* bqa = (const float*)d_in[15];
    const float* bka = (const float*)d_in[16];
    const float* bva = (const float*)d_in[17];
    const float* bo  = (const float*)d_in[18];
    const float* boa = (const float*)d_in[19];
    const float* nqw  = (const float*)d_in[20];
    const float* nkw  = (const float*)d_in[21];
    const float* naqw = (const float*)d_in[22];
    const float* nakw = (const float*)d_in[23];
    const float* qd = (const float*)d_in[24];
    const float* kd = (const float*)d_in[25];
    const float* vd = (const float*)d_in[26];
    const float* qu = (const float*)d_in[27];
    const float* ku = (const float*)d_in[28];
    const float* vu = (const float*)d_in[29];
    const float* lw = (const float*)d_in[30];
    (void)qd; (void)qu;   // q-LoRA provably dead (only touches fully-masked rows)

    float *Pq, *Pk, *Pv, *Eq, *Ek, *Ev, *DtP, *V, *SA, *SB, *mnP, *mean, *vec;
    __half *hH, *hW, *Qh, *Kh, *Dth, *AOh;
    cudaGetSymbolAddress((void**)&Pq, g_Pq);
    cudaGetSymbolAddress((void**)&Pk, g_Pk);
    cudaGetSymbolAddress((void**)&Pv, g_Pv);
    cudaGetSymbolAddress((void**)&Eq, g_Eq);
    cudaGetSymbolAddress((void**)&Ek, g_Ek);
    cudaGetSymbolAddress((void**)&Ev, g_Ev);
    cudaGetSymbolAddress((void**)&DtP, g_DtP);
    cudaGetSymbolAddress((void**)&V,  g_V);
    cudaGetSymbolAddress((void**)&SA, g_SA);
    cudaGetSymbolAddress((void**)&SB, g_SB);
    cudaGetSymbolAddress((void**)&mnP, g_mnP);
    cudaGetSymbolAddress((void**)&mean, g_mean);
    cudaGetSymbolAddress((void**)&vec,  g_vec);
    cudaGetSymbolAddress((void**)&hH,  g_hH);
    cudaGetSymbolAddress((void**)&hW,  g_hW);
    cudaGetSymbolAddress((void**)&Qh,  g_Qh);
    cudaGetSymbolAddress((void**)&Kh,  g_Kh);
    cudaGetSymbolAddress((void**)&Dth, g_Dth);
    cudaGetSymbolAddress((void**)&AOh, g_AOh);

    const __half* const* tA;
    const __half* const* tB;
    const float* const* tbias;
    float* const* tC;
    {
        void *pA, *pB, *pb, *pC;
        cudaGetSymbolAddress(&pA, g_hA);
        cudaGetSymbolAddress(&pB, g_hB);
        cudaGetSymbolAddress(&pb, g_tbias);
        cudaGetSymbolAddress(&pC, g_tC);
        tA = (const __half* const*)pA;
        tB = (const __half* const*)pB;
        tbias = (const float* const*)pb;
        tC = (float* const*)pC;
    }

    float* out = (float*)d_out;

    // REQUIRED smem opt-ins (launches fail without them)
    cudaFuncSetAttribute(gemm_f16<128, 64, 256, 4, 2, 4, 4, 3, false>,
                         cudaFuncAttributeMaxDynamicSharedMemorySize, BIGH_SMEM);
    cudaFuncSetAttribute(gemm_f16<128, 64, 256, 4, 2, 4, 4, 3, true>,
                         cudaFuncAttributeMaxDynamicSharedMemorySize, BIGH_SMEM);
    cudaFuncSetAttribute(gemm_f16<64, 64, 128, 4, 2, 4, 2, 4, false>,
                         cudaFuncAttributeMaxDynamicSharedMemorySize, SMALLH_SMEM);
    cudaFuncSetAttribute(gemm_f16<64, 64, 128, 4, 2, 4, 2, 4, true>,
                         cudaFuncAttributeMaxDynamicSharedMemorySize, SMALLH_SMEM);
    cudaFuncSetAttribute(gemm_av,
                         cudaFuncAttributeMaxDynamicSharedMemorySize, AV_SMEM);

    // 0) fill tables, then convert ALL f16 operands in one fused launch
    setup_tabs<<<1, 1>>>(hidden, enc, Wq, Wk, Wv, Wqa, Wka, Wva, Wo, Woa,
                         bq, bk, bv, bqa, bka, bva, kd, vd, ku, vu);
    conv_all<<<C_TOTAL / 256, 256>>>();

    // 1) image k/v projections (batched, z=2); q projection only needs image
    //    rows [0,1024) (query rows >= 1536 are fully masked -> output is mean(V))
    f16_big_tab(tA + 0, tB + 0, tbias + 0, tC + 0, 2, 1,
                S_HID, DIMN, DIMN, DIMN, DIMN, DIMN, 0, 0, 0, 1.f, nullptr, 0.f);
    f16_big(hH, hW + 0 * (long long)DIMN * DIMN, bq, Pq,
            CONDN, DIMN, DIMN, DIMN, DIMN, DIMN, 0, 0, 0, 1, 1.f, nullptr, 0.f);

    // 2) encoder projections (batched, z=3)
    f16_small_tab(tA + 2, tB + 2, tbias + 2, tC + 2, 3, 1,
                  S_ENC, DIMN, DIMN, DIMN, DIMN, DIMN, 0, 0, 0, 1.f, nullptr, 0.f);

    // 3) LoRA k/v only (q-LoRA touches only masked rows -> dead)
    f16_small_tab(tA + 5, tB + 5, tbias + 5, tC + 5, 2 * KSPLIT, KSPLIT,
                  CONDN, RANKN, DIMN / KSPLIT, DIMN, DIMN, RANKN,
                  DIMN / KSPLIT, DIMN / KSPLIT, (long long)CONDN * RANKN,
                  1.f, nullptr, 0.f);
    {
        dim3 rg((CONDN * RANKN) / 256, 2);
        reduce_splitk2<<<rg, 256>>>(DtP, Dth);
    }
    f16_small_tab(tA + 7, tB + 7, tbias + 7, tC + 7, 2, 1,
                  CONDN, DIMN, RANKN, RANKN, RANKN, DIMN, 0, 0, 0, 1.f, lw, 1.f);

    // 4) heads + RMSNorm + RoPE; Q only for rows < 1536
    build_qkv<<<dim3(SEQ, HEADS), HD>>>(Pq, Pk, Pv, Eq, Ek, Ev, rc, rs,
                                        nqw, nkw, naqw, nakw, Qh, Kh, V);

    // 5) block A: encoder queries vs full keys
    f16_big(Qh, Kh, nullptr, SA, S_ENC, SEQ, HD, HD, HD, SEQ,
            (long long)SEQ * HD, (long long)SEQ * HD, (long long)S_ENC * SEQ, HEADS,
            ATTN_SCALE, nullptr, 0.f);
    softmax_k<SEQ><<<HEADS * S_ENC, 256>>>(SA);
    {
        dim3 g(HD / 64, S_ENC / 64, HEADS);
        gemm_av<<<g, 128, AV_SMEM>>>(SA, V, AOh, S_ENC, HD, SEQ, SEQ, HD, DIMN,
                                     (long long)S_ENC * SEQ, (long long)SEQ * HD, HD);
    }

    // 6) block B: cond queries vs cond keys
    f16_big(Qh + (long long)S_ENC * HD, Kh + (long long)S_ENC * HD, nullptr, SB,
            CONDN, CONDN, HD, HD, HD, CONDN,
            (long long)SEQ * HD, (long long)SEQ * HD, (long long)CONDN * CONDN, HEADS,
            ATTN_SCALE, nullptr, 0.f);
    softmax_k<CONDN><<<HEADS * CONDN, 256>>>(SB);
    {
        dim3 g(HD / 64, CONDN / 64, HEADS);
        gemm_av<<<g, 128, AV_SMEM>>>(SB, V + (long long)S_ENC * HD,
                                     AOh + (long long)S_ENC * DIMN,
                                     CONDN, HD, CONDN, CONDN, HD, DIMN,
                                     (long long)CONDN * CONDN, (long long)SEQ * HD, HD);
    }

    // 7) fully-masked rows -> uniform softmax -> mean of V; one out-proj row
    mean_part<<<dim3(HEADS, SCHUNK), HD>>>(V, mnP);
    mean_fin<<<DIMN / 256, 256>>>(mnP, mean);
    gemv_out<<<DIMN / 8, 256>>>(mean, Wo, bo, vec);

    // 8) output projections (f16)
    f16_big(AOh + (long long)S_ENC * DIMN, hW + 6 * (long long)DIMN * DIMN, bo, out,
            CONDN, DIMN, DIMN, DIMN, DIMN, DIMN, 0, 0, 0, 1, 1.f, nullptr, 0.f);
    fill_rows<<<(NROWS_C * (DIMN / 4)) / 256, 256>>>(vec, out + (long long)CONDN * DIMN);
    f16_small(AOh, hW + 7 * (long long)DIMN * DIMN, boa, out + (long long)S_HID * DIMN,
              S_ENC, DIMN, DIMN, DIMN, DIMN, DIMN, 0, 0, 0, 1, 1.f, nullptr, 0.f);
}

// round 16
// speedup vs baseline: 1.8931x; 1.0631x over previous
#include <cuda_runtime.h>
#include <cuda_fp16.h>
#include <math.h>
#include <stdint.h>

// ---------------- problem constants ----------------
#define DIMN   3072
#define HEADS  24
#define HD     128
#define S_HID  3072
#define S_ENC  512
#define SEQ    3584          // S_ENC + S_HID
#define CONDN  1024
#define RANKN  64
#define BLOCKL 2048          // S_HID - CONDN
#define NROWS_C (SEQ - S_ENC - CONDN)   // 2048 fully-masked query rows
#define KSPLIT 16            // split-K for LoRA down-proj
#define SCHUNK 28            // mean s-chunks (SEQ = 28*128)
static const float ATTN_SCALE = 0.08838834764831843f; // 1/sqrt(128)

// ---------------- device scratch (no allocs allowed) ----------------
__device__ float g_Pq[(size_t)S_HID * DIMN];   // only rows [0,1024) used
__device__ float g_Pk[(size_t)S_HID * DIMN];
__device__ float g_Pv[(size_t)S_HID * DIMN];
__device__ float g_Eq[(size_t)S_ENC * DIMN];
__device__ float g_Ek[(size_t)S_ENC * DIMN];
__device__ float g_Ev[(size_t)S_ENC * DIMN];
__device__ float g_DtP[(size_t)2 * KSPLIT * CONDN * RANKN];   // k, v branches
__device__ float g_V [(size_t)HEADS * SEQ * HD];      // natural layout [h][s][d]
__device__ float g_SA[(size_t)HEADS * S_ENC * SEQ];   // encoder-query scores
__device__ float g_SB[(size_t)HEADS * CONDN * CONDN]; // cond-block scores
__device__ float g_mnP[(size_t)SCHUNK * DIMN];
__device__ float g_mean[DIMN];
__device__ float g_vec [DIMN];
// half operand buffers
__device__ __half g_hH[(size_t)S_HID * DIMN];
__device__ __half g_hE[(size_t)S_ENC * DIMN];
__device__ __half g_hW[8][(size_t)DIMN * DIMN];   // Wq Wk Wv Wqa Wka Wva Wo Woa
__device__ __half g_hdn[2][(size_t)RANKN * DIMN]; // kd, vd
__device__ __half g_hup[2][(size_t)DIMN * RANKN]; // ku, vu
__device__ __half g_Qh[(size_t)HEADS * SEQ * HD];
__device__ __half g_Kh[(size_t)HEADS * SEQ * HD];
__device__ __half g_Dth[(size_t)2 * CONDN * RANKN];
__device__ __half g_AOh[(size_t)(S_ENC + CONDN) * DIMN];

// pointer tables for batched f16 GEMM groups:
// [0..1]=img k/v proj, [2..4]=enc proj, [5..6]=lora-down k/v, [7..8]=lora-up k/v
__device__ const __half* g_hA[9];
__device__ const __half* g_hB[9];
__device__ const float*  g_tbias[9];
__device__ float*        g_tC[9];
// fused conversion tables (14 entries)
__device__ const float* g_cS[14];
__device__ __half*      g_cD[14];

// conversion chunk counts (float4 units) — compile-time
#define C_HID (S_HID * DIMN / 4)
#define C_ENC (S_ENC * DIMN / 4)
#define C_W   (DIMN * DIMN / 4)
#define C_LR  (RANKN * DIMN / 4)
#define C_TOTAL (C_HID + C_ENC + 8 * C_W + 4 * C_LR)

// ---------------- helpers ----------------
__device__ __forceinline__ uint32_t f2tf(float f) {
    uint32_t u;
    asm("cvt.rna.tf32.f32 %0, %1;" : "=r"(u) : "f"(f));
    return u;
}

__device__ __forceinline__ void cpa16(void* dst, const void* src, bool pred) {
    uint32_t d = (uint32_t)__cvta_generic_to_shared(dst);
    int sz = pred ? 16 : 0;   // src-size 0 => zero-fill
    asm volatile("cp.async.cg.shared.global [%0], [%1], 16, %2;\n"
                 :: "r"(d), "l"(src), "r"(sz));
}

__device__ __forceinline__ void mma_tf32(float* c, const uint32_t* a, const uint32_t* b) {
    asm volatile(
        "mma.sync.aligned.m16n8k8.row.col.f32.tf32.tf32.f32 "
        "{%0,%1,%2,%3}, {%4,%5,%6,%7}, {%8,%9}, {%0,%1,%2,%3};\n"
        : "+f"(c[0]), "+f"(c[1]), "+f"(c[2]), "+f"(c[3])
        : "r"(a[0]), "r"(a[1]), "r"(a[2]), "r"(a[3]), "r"(b[0]), "r"(b[1]));
}

__device__ __forceinline__ void mma_f16(float* c, const uint32_t* a, const uint32_t* b) {
    asm volatile(
        "mma.sync.aligned.m16n8k16.row.col.f32.f16.f16.f32 "
        "{%0,%1,%2,%3}, {%4,%5,%6,%7}, {%8,%9}, {%0,%1,%2,%3};\n"
        : "+f"(c[0]), "+f"(c[1]), "+f"(c[2]), "+f"(c[3])
        : "r"(a[0]), "r"(a[1]), "r"(a[2]), "r"(a[3]), "r"(b[0]), "r"(b[1]));
}

// ---------------- fp16 tensor-core GEMM (LDSM fragment loads) ----------------
// C(f32) = alpha * A[M,K](half) @ B[N,K]^T(half) + bias + beta*C.
// BK = 32 halves per stage; smem row stride 80 B (20 half2) -> ldmatrix rows
// hit all 32 banks exactly once (conflict-free).
// TAB: operands from pointer tables (zi = z/zdiv entry, zr*strides = split-K).
#define ASTRH 20   // smem row stride in half2 units (80 bytes)

template <int TBM, int TBN, int THREADS, int NSTAGE, int MT, int NT, int WMC,
          int OCC, bool TAB>
__global__ __launch_bounds__(THREADS, OCC)
void gemm_f16(const __half* __restrict__ A, const __half* __restrict__ B,
              const float* __restrict__ bias, float* __restrict__ C,
              const __half* const* __restrict__ Aarr,
              const __half* const* __restrict__ Barr,
              const float* const* __restrict__ biasarr,
              float* const* __restrict__ Carr, int zdiv,
              int M, int N, int K, int lda, int ldb, int ldc,
              long long sA, long long sB, long long sC,
              float alpha, const float* __restrict__ alpha_ptr, float beta)
{
    constexpr int PF = NSTAGE - 1;
    constexpr int ASTG = TBM * ASTRH;   // half2 per A stage
    constexpr int BSTG = TBN * ASTRH;
    extern __shared__ uint32_t smh[];
    uint32_t* As = smh;
    uint32_t* Bs = smh + NSTAGE * ASTG;

    const __half* Ab;
    const __half* Bb;
    float*        Cb;
    const float*  biasb;
    if (TAB) {
        const int zi = blockIdx.z / zdiv;
        const int zr = blockIdx.z - zi * zdiv;
        Ab = Aarr[zi] + (long long)zr * sA;
        Bb = Barr[zi] + (long long)zr * sB;
        Cb = Carr[zi] + (long long)zr * sC;
        biasb = biasarr[zi];
    } else {
        Ab = A + (long long)blockIdx.z * sA;
        Bb = B + (long long)blockIdx.z * sB;
        Cb = C + (long long)blockIdx.z * sC;
        biasb = bias;
    }

    const int m0 = blockIdx.y * TBM;
    const int n0 = blockIdx.x * TBN;
    const int tid  = threadIdx.x;
    const int lane = tid & 31;
    const int warp = tid >> 5;
    const int wm = (warp % WMC) * (MT * 16);
    const int wn = (warp / WMC) * (NT * 8);
    const int g  = lane >> 2;
    const int tg = lane & 3;

    // ldmatrix per-lane byte offsets: quad q = lane>>3 selects 8x8 matrix
    //   q&1   -> +8 rows, q>>1 -> +8 k (16 bytes)
    const int lrow8 = (lane & 7) + ((lane >> 3) & 1) * 8;
    const int lk16  = (lane >> 4) * 16;
    const uint32_t smb = (uint32_t)__cvta_generic_to_shared(smh);
    uint32_t aoff[MT];
#pragma unroll
    for (int mt = 0; mt < MT; mt++)
        aoff[mt] = (uint32_t)((wm + mt * 16 + lrow8) * (ASTRH * 4) + lk16);
    uint32_t boff[NT / 2];
#pragma unroll
    for (int np = 0; np < NT / 2; np++)
        boff[np] = (uint32_t)((wn + np * 16 + lrow8) * (ASTRH * 4) + lk16);

    float c[MT][NT][4];
#pragma unroll
    for (int i = 0; i < MT; i++)
#pragma unroll
        for (int j = 0; j < NT; j++)
#pragma unroll
            for (int r = 0; r < 4; r++) c[i][j][r] = 0.f;

    const int nk = K / 32;

    auto load_tile = [&](int k0 /*halves*/, int buf) {
        uint32_t* Ad = As + buf * ASTG;
        uint32_t* Bd = Bs + buf * BSTG;
#pragma unroll
        for (int j = 0; j < TBM * 4 / THREADS; j++) {
            const int cidx = tid + j * THREADS;
            const int row  = cidx >> 2;
            const int ch2  = (cidx & 3) << 2;     // half2 offset in row
            cpa16(Ad + row * ASTRH + ch2,
                  Ab + (long long)(m0 + row) * lda + k0 + ch2 * 2,
                  (m0 + row) < M);
        }
#pragma unroll
        for (int j = 0; j < TBN * 4 / THREADS; j++) {
            const int cidx = tid + j * THREADS;
            const int row  = cidx >> 2;
            const int ch2  = (cidx & 3) << 2;
            cpa16(Bd + row * ASTRH + ch2,
                  Bb + (long long)(n0 + row) * ldb + k0 + ch2 * 2,
                  (n0 + row) < N);
        }
        asm volatile("cp.async.commit_group;\n");
    };

    for (int s = 0; s < PF; s++) {
        if (s < nk) load_tile(s * 32, s);
        else        asm volatile("cp.async.commit_group;\n");
    }

    for (int it = 0; it < nk; it++) {
        if (it + PF < nk) load_tile((it + PF) * 32, (it + PF) & (NSTAGE - 1));
        else              asm volatile("cp.async.commit_group;\n");
        asm volatile("cp.async.wait_group %0;\n" :: "n"(PF));
        __syncthreads();

        const int buf = it & (NSTAGE - 1);
        const uint32_t Abs = smb + (uint32_t)(buf * ASTG) * 4u;
        const uint32_t Bbs = smb + (uint32_t)(NSTAGE * ASTG + buf * BSTG) * 4u;

#pragma unroll
        for (int s16 = 0; s16 < 2; s16++) {       // two k16 steps per BK=32
            const uint32_t kb = s16 * 32;         // bytes (16 halves)
            uint32_t bf[NT][2];
#pragma unroll
            for (int np = 0; np < NT / 2; np++) {
                asm volatile(
                    "ldmatrix.sync.aligned.m8n8.x4.shared.b16 {%0,%1,%2,%3}, [%4];"
                    : "=r"(bf[2 * np][0]), "=r"(bf[2 * np + 1][0]),
                      "=r"(bf[2 * np][1]), "=r"(bf[2 * np + 1][1])
                    : "r"(Bbs + boff[np] + kb));
            }
            uint32_t af[MT][4];
#pragma unroll
            for (int mt = 0; mt < MT; mt++) {
                asm volatile(
                    "ldmatrix.sync.aligned.m8n8.x4.shared.b16 {%0,%1,%2,%3}, [%4];"
                    : "=r"(af[mt][0]), "=r"(af[mt][1]),
                      "=r"(af[mt][2]), "=r"(af[mt][3])
                    : "r"(Abs + aoff[mt] + kb));
            }
#pragma unroll
            for (int mt = 0; mt < MT; mt++)
#pragma unroll
                for (int nt = 0; nt < NT; nt++)
                    mma_f16(c[mt][nt], af[mt], bf[nt]);
        }
        __syncthreads();
    }

    float aE = alpha;
    if (alpha_ptr) aE *= *alpha_ptr;

#pragma unroll
    for (int mt = 0; mt < MT; mt++) {
#pragma unroll
        for (int r = 0; r < 2; r++) {
            const int gm = m0 + wm + mt * 16 + g + r * 8;
            if (gm >= M) continue;
            float* crow = Cb + (long long)gm * ldc;
#pragma unroll
            for (int nt = 0; nt < NT; nt++) {
                const int gn = n0 + wn + nt * 8 + tg * 2;
                if (gn >= N) continue;
                float x = c[mt][nt][r * 2 + 0] * aE;
                float y = c[mt][nt][r * 2 + 1] * aE;
                if (biasb) { x += biasb[gn]; y += biasb[gn + 1]; }
                if (beta != 0.f) {
                    float2 p = *(const float2*)(crow + gn);
                    x += beta * p.x; y += beta * p.y;
                }
                *(float2*)(crow + gn) = make_float2(x, y);
            }
        }
    }
}

#define BIGH_SMEM   (4 * (128 + 64) * ASTRH * 4)
#define SMALLH_SMEM (4 * ( 64 + 64) * ASTRH * 4)

// ---------------- tf32 AV GEMM: AO(half) = P(f32)[M,K] @ V(f32)[K,N] ----------------
#define AVBK 16
#define AASTR 20
#define BVSTR 68

__global__ __launch_bounds__(128, 4)
void gemm_av(const float* __restrict__ A, const float* __restrict__ B,
             __half* __restrict__ C,
             int M, int N, int K, int lda, int ldb, int ldc,
             long long sA, long long sB, long long sC)
{
    constexpr int NSTAGE = 4, PF = 3;
    constexpr int ASTG = 64 * AASTR;
    constexpr int BSTG = AVBK * BVSTR;
    extern __shared__ float smem[];
    float* As = smem;
    float* Bs = smem + NSTAGE * ASTG;

    const float* Ab = A + (long long)blockIdx.z * sA;
    const float* Bb = B + (long long)blockIdx.z * sB;
    __half*      Cb = C + (long long)blockIdx.z * sC;

    const int m0 = blockIdx.y * 64;
    const int n0 = blockIdx.x * 64;
    const int tid  = threadIdx.x;
    const int lane = tid & 31;
    const int warp = tid >> 5;
    const int wm = (warp & 1) * 32;
    const int wn = (warp >> 1) * 32;
    const int g  = lane >> 2;
    const int tg = lane & 3;

    float c[2][4][4];
#pragma unroll
    for (int i = 0; i < 2; i++)
#pragma unroll
        for (int j = 0; j < 4; j++)
#pragma unroll
            for (int r = 0; r < 4; r++) c[i][j][r] = 0.f;

    const int nk = K / AVBK;

    auto load_tile = [&](int k0, int buf) {
        float* Ad = As + buf * ASTG;
        float* Bd = Bs + buf * BSTG;
#pragma unroll
        for (int j = 0; j < 2; j++) {
            const int cidx = tid + j * 128;
            const int row  = cidx >> 2;
            const int kc   = (cidx & 3) << 2;
            cpa16(Ad + row * AASTR + kc,
                  Ab + (long long)(m0 + row) * lda + k0 + kc,
                  (m0 + row) < M);
        }
#pragma unroll
        for (int j = 0; j < 2; j++) {
            const int cidx = tid + j * 128;
            const int row  = cidx >> 4;
            const int col  = (cidx & 15) << 2;
            cpa16(Bd + row * BVSTR + col,
                  Bb + (long long)(k0 + row) * ldb + n0 + col,
                  (n0 + col) < N);
        }
        asm volatile("cp.async.commit_group;\n");
    };

    for (int s = 0; s < PF; s++) {
        if (s < nk) load_tile(s * AVBK, s);
        else        asm volatile("cp.async.commit_group;\n");
    }

    for (int it = 0; it < nk; it++) {
        if (it + PF < nk) load_tile((it + PF) * AVBK, (it + PF) & 3);
        else              asm volatile("cp.async.commit_group;\n");
        asm volatile("cp.async.wait_group %0;\n" :: "n"(PF));
        __syncthreads();

        const int buf = it & 3;
        const float* Ac = As + buf * ASTG;
        const float* Bc = Bs + buf * BSTG;

#pragma unroll
        for (int ks = 0; ks < AVBK; ks += 8) {
            uint32_t bf[4][2];
#pragma unroll
            for (int nt = 0; nt < 4; nt++) {
                const float* bp = Bc + (ks + tg) * BVSTR + wn + nt * 8 + g;
                bf[nt][0] = f2tf(bp[0]);
                bf[nt][1] = f2tf(bp[4 * BVSTR]);
            }
            uint32_t af[2][4];
#pragma unroll
            for (int mt = 0; mt < 2; mt++) {
                const float* ap = Ac + (wm + mt * 16 + g) * AASTR + ks + tg;
                af[mt][0] = f2tf(ap[0]);
                af[mt][1] = f2tf(ap[8 * AASTR]);
                af[mt][2] = f2tf(ap[4]);
                af[mt][3] = f2tf(ap[8 * AASTR + 4]);
            }
#pragma unroll
            for (int mt = 0; mt < 2; mt++)
#pragma unroll
                for (int nt = 0; nt < 4; nt++)
                    mma_tf32(c[mt][nt], af[mt], bf[nt]);
        }
        __syncthreads();
    }

#pragma unroll
    for (int mt = 0; mt < 2; mt++) {
#pragma unroll
        for (int r = 0; r < 2; r++) {
            const int gm = m0 + wm + mt * 16 + g + r * 8;
            if (gm >= M) continue;
            __half* crow = Cb + (long long)gm * ldc;
#pragma unroll
            for (int nt = 0; nt < 4; nt++) {
                const int gn = n0 + wn + nt * 8 + tg * 2;
                if (gn >= N) continue;
                *(__half2*)(crow + gn) =
                    __floats2half2_rn(c[mt][nt][r * 2 + 0], c[mt][nt][r * 2 + 1]);
            }
        }
    }
}

#define AV_SMEM (4 * (64 * AASTR + AVBK * BVSTR) * 4)

// ---------------- setup kernel: fill pointer tables ----------------
__global__ void setup_tabs(const float* hidden, const float* enc,
                           const float* Wq, const float* Wk, const float* Wv,
                           const float* Wqa, const float* Wka, const float* Wva,
                           const float* Wo, const float* Woa,
                           const float* bq, const float* bk, const float* bv,
                           const float* bqa, const float* bka, const float* bva,
                           const float* kd, const float* vd,
                           const float* ku, const float* vu)
{
    // conversion tables
    g_cS[0] = hidden; g_cD[0] = g_hH;
    g_cS[1] = enc;    g_cD[1] = g_hE;
    const float* Ws[8] = {Wq, Wk, Wv, Wqa, Wka, Wva, Wo, Woa};
    for (int i = 0; i < 8; i++) { g_cS[2 + i] = Ws[i]; g_cD[2 + i] = g_hW[i]; }
    g_cS[10] = kd; g_cD[10] = g_hdn[0];
    g_cS[11] = vd; g_cD[11] = g_hdn[1];
    g_cS[12] = ku; g_cD[12] = g_hup[0];
    g_cS[13] = vu; g_cD[13] = g_hup[1];

    // GEMM tables
    // [0..1] image k/v projections (q handled separately, M=1024)
    g_hA[0] = g_hH; g_hA[1] = g_hH;
    g_hB[0] = g_hW[1]; g_hB[1] = g_hW[2];
    g_tC[0] = g_Pk; g_tC[1] = g_Pv;
    g_tbias[0] = bk; g_tbias[1] = bv;
    // [2..4] encoder projections
    g_hA[2] = g_hE; g_hA[3] = g_hE; g_hA[4] = g_hE;
    g_hB[2] = g_hW[3]; g_hB[3] = g_hW[4]; g_hB[4] = g_hW[5];
    g_tC[2] = g_Eq; g_tC[3] = g_Ek; g_tC[4] = g_Ev;
    g_tbias[2] = bqa; g_tbias[3] = bka; g_tbias[4] = bva;
    // [5..6] LoRA down k/v (split-K via zr)
    const __half* hm = g_hH + (long long)BLOCKL * DIMN;
    g_hA[5] = hm; g_hA[6] = hm;
    g_hB[5] = g_hdn[0]; g_hB[6] = g_hdn[1];
    g_tC[5] = g_DtP + 0 * (size_t)KSPLIT * CONDN * RANKN;
    g_tC[6] = g_DtP + 1 * (size_t)KSPLIT * CONDN * RANKN;
    g_tbias[5] = nullptr; g_tbias[6] = nullptr;
    // [7..8] LoRA up k/v
    g_hA[7] = g_Dth + 0 * (size_t)CONDN * RANKN;
    g_hA[8] = g_Dth + 1 * (size_t)CONDN * RANKN;
    g_hB[7] = g_hup[0]; g_hB[8] = g_hup[1];
    g_tC[7] = g_Pk + (long long)BLOCKL * DIMN;
    g_tC[8] = g_Pv + (long long)BLOCKL * DIMN;
    g_tbias[7] = nullptr; g_tbias[8] = nullptr;
}

// ---------------- fused f32->f16 conversion (all operands, one launch) ----------------
__global__ void conv_all()
{
    int idx = blockIdx.x * 256 + threadIdx.x;
    const int sz[14] = {C_HID, C_ENC, C_W, C_W, C_W, C_W, C_W, C_W, C_W, C_W,
                        C_LR, C_LR, C_LR, C_LR};
#pragma unroll
    for (int e = 0; e < 14; e++) {
        if (idx < sz[e]) {
            float4 v = ((const float4*)g_cS[e])[idx];
            __half2* d = (__half2*)g_cD[e];
            d[2 * idx + 0] = __floats2half2_rn(v.x, v.y);
            d[2 * idx + 1] = __floats2half2_rn(v.z, v.w);
            return;
        }
        idx -= sz[e];
    }
}

// ---------------- elementwise kernels ----------------
__global__ void build_qkv(const float* __restrict__ Pq, const float* __restrict__ Pk,
                          const float* __restrict__ Pv, const float* __restrict__ Eq,
                          const float* __restrict__ Ek, const float* __restrict__ Ev,
                          const float* __restrict__ rc, const float* __restrict__ rs,
                          const float* __restrict__ nqw, const float* __restrict__ nkw,
                          const float* __restrict__ naqw, const float* __restrict__ nakw,
                          __half* __restrict__ Qh, __half* __restrict__ Kh,
                          float* __restrict__ V)
{
    const int s = blockIdx.x;
    const int h = blockIdx.y;
    const int d = threadIdx.x;
    const bool needQ = (s < S_ENC + CONDN);   // rows >= 1536 are fully masked

    const float *sq, *sk, *sv, *wq, *wk;
    if (s < S_ENC) {
        const long long off = (long long)s * DIMN + h * HD;
        sq = Eq + off; sk = Ek + off; sv = Ev + off;
        wq = naqw; wk = nakw;
    } else {
        const long long off = (long long)(s - S_ENC) * DIMN + h * HD;
        sq = Pq + off; sk = Pk + off; sv = Pv + off;
        wq = nqw; wk = nkw;
    }
    float q = needQ ? sq[d] : 0.f;
    float k = sk[d], v = sv[d];

    float ssq = q * q, ssk = k * k;
#pragma unroll
    for (int o = 16; o; o >>= 1) {
        ssq += __shfl_xor_sync(0xffffffffu, ssq, o);
        ssk += __shfl_xor_sync(0xffffffffu, ssk, o);
    }
    __shared__ float shq[4], shk[4];
    const int w = d >> 5;
    if ((d & 31) == 0) { shq[w] = ssq; shk[w] = ssk; }
    __syncthreads();
    const float tq = shq[0] + shq[1] + shq[2] + shq[3];
    const float tk = shk[0] + shk[1] + shk[2] + shk[3];

    const float qn = q * rsqrtf(tq * (1.0f / HD) + 1e-6f) * wq[d];
    const float kn = k * rsqrtf(tk * (1.0f / HD) + 1e-6f) * wk[d];

    const float qp = __shfl_xor_sync(0xffffffffu, qn, 1);
    const float kp = __shfl_xor_sync(0xffffffffu, kn, 1);
    const float qr = (d & 1) ? qp : -qp;
    const float kr = (d & 1) ? kp : -kp;

    const float cc = rc[(long long)s * HD + d];
    const float sn = rs[(long long)s * HD + d];

    const long long o = ((long long)h * SEQ + s) * HD + d;
    if (needQ) Qh[o] = __float2half_rn(qn * cc + qr * sn);
    Kh[o] = __float2half_rn(kn * cc + kr * sn);
    V[o] = v;
}

// register-cached softmax: 1 global read + 1 global write per element
template <int NC>
__global__ void softmax_k(float* __restrict__ S)
{
    constexpr int PT = NC / 256;
    float* r = S + (long long)blockIdx.x * NC;
    const int tid = threadIdx.x;
    __shared__ float sh[8];

    float v[PT];
#pragma unroll
    for (int i = 0; i < PT; i++) v[i] = r[tid + i * 256];

    float m = v[0];
#pragma unroll
    for (int i = 1; i < PT; i++) m = fmaxf(m, v[i]);
#pragma unroll
    for (int o = 16; o; o >>= 1) m = fmaxf(m, __shfl_xor_sync(0xffffffffu, m, o));
    if ((tid & 31) == 0) sh[tid >> 5] = m;
    __syncthreads();
    float bm = sh[0];
#pragma unroll
    for (int i = 1; i < 8; i++) bm = fmaxf(bm, sh[i]);
    __syncthreads();

    float sum = 0.f;
#pragma unroll
    for (int i = 0; i < PT; i++) {
        v[i] = expf(v[i] - bm);
        sum += v[i];
    }
#pragma unroll
    for (int o = 16; o; o >>= 1) sum += __shfl_xor_sync(0xffffffffu, sum, o);
    if ((tid & 31) == 0) sh[tid >> 5] = sum;
    __syncthreads();
    float bs = 0.f;
#pragma unroll
    for (int i = 0; i < 8; i++) bs += sh[i];
    const float inv = 1.0f / bs;
#pragma unroll
    for (int i = 0; i < PT; i++) r[tid + i * 256] = v[i] * inv;
}

__global__ void mean_part(const float* __restrict__ V, float* __restrict__ P)
{
    const int h  = blockIdx.x;
    const int ch = blockIdx.y;
    const int d  = threadIdx.x;
    const float* base = V + ((long long)h * SEQ + ch * (SEQ / SCHUNK)) * HD + d;
    float s = 0.f;
#pragma unroll 4
    for (int i = 0; i < SEQ / SCHUNK; i++) s += base[(long long)i * HD];
    P[(size_t)ch * DIMN + h * HD + d] = s;
}

__global__ void mean_fin(const float* __restrict__ P, float* __restrict__ mean)
{
    const int j = blockIdx.x * 256 + threadIdx.x;
    float s = 0.f;
#pragma unroll
    for (int c = 0; c < SCHUNK; c++) s += P[(size_t)c * DIMN + j];
    mean[j] = s * (1.0f / SEQ);
}

__global__ void gemv_out(const float* __restrict__ mean, const float* __restrict__ Wo,
                         const float* __restrict__ bo, float* __restrict__ vec)
{
    const int j = blockIdx.x * 8 + (threadIdx.x >> 5);
    const int lane = threadIdx.x & 31;
    const float* w = Wo + (long long)j * DIMN;
    float s = 0.f;
    for (int d = lane; d < DIMN; d += 32) s += mean[d] * w[d];
#pragma unroll
    for (int o = 16; o; o >>= 1) s += __shfl_xor_sync(0xffffffffu, s, o);
    if (lane == 0) vec[j] = s + bo[j];
}

__global__ void fill_rows(const float* __restrict__ vec, float* __restrict__ out)
{
    const long long i = (long long)blockIdx.x * 256 + threadIdx.x;
    const float4 v = ((const float4*)vec)[i % (DIMN / 4)];
    ((float4*)out)[i] = v;
}

__global__ void reduce_splitk2(const float* __restrict__ P, __half* __restrict__ D)
{
    const int i = blockIdx.y;   // branch (k=0, v=1)
    const int j = blockIdx.x * 256 + threadIdx.x;
    const float* base = P + (size_t)i * KSPLIT * CONDN * RANKN + j;
    float s = 0.f;
#pragma unroll
    for (int z = 0; z < KSPLIT; z++) s += base[(size_t)z * CONDN * RANKN];
    D[(size_t)i * CONDN * RANKN + j] = __float2half_rn(s);
}

// ---------------- host-side launch helpers ----------------
#define NULLTAB nullptr, nullptr, nullptr, nullptr, 1

static void f16_big(const __half* A, const __half* B, const float* bias, float* C,
                    int M, int N, int K, int lda, int ldb, int ldc,
                    long long sA, long long sB, long long sC, int batch,
                    float alpha, const float* aptr, float beta)
{
    dim3 g((N + 63) / 64, (M + 127) / 128, batch);
    gemm_f16<128, 64, 256, 4, 2, 4, 4, 3, false><<<g, 256, BIGH_SMEM>>>(
        A, B, bias, C, NULLTAB, M, N, K, lda, ldb, ldc, sA, sB, sC, alpha, aptr, beta);
}

static void f16_small(const __half* A, const __half* B, const float* bias, float* C,
                      int M, int N, int K, int lda, int ldb, int ldc,
                      long long sA, long long sB, long long sC, int batch,
                      float alpha, const float* aptr, float beta)
{
    dim3 g((N + 63) / 64, (M + 63) / 64, batch);
    gemm_f16<64, 64, 128, 4, 2, 4, 2, 4, false><<<g, 128, SMALLH_SMEM>>>(
        A, B, bias, C, NULLTAB, M, N, K, lda, ldb, ldc, sA, sB, sC, alpha, aptr, beta);
}

static void f16_big_tab(const __half* const* tA, const __half* const* tB,
                        const float* const* tbias, float* const* tC,
                        int zcnt, int zdiv,
                        int M, int N, int K, int lda, int ldb, int ldc,
                        long long sA, long long sB, long long sC,
                        float alpha, const float* aptr, float beta)
{
    dim3 g((N + 63) / 64, (M + 127) / 128, zcnt);
    gemm_f16<128, 64, 256, 4, 2, 4, 4, 3, true><<<g, 256, BIGH_SMEM>>>(
        nullptr, nullptr, nullptr, nullptr, tA, tB, tbias, tC, zdiv,
        M, N, K, lda, ldb, ldc, sA, sB, sC, alpha, aptr, beta);
}

static void f16_small_tab(const __half* const* tA, const __half* const* tB,
                          const float* const* tbias, float* const* tC,
                          int zcnt, int zdiv,
                          int M, int N, int K, int lda, int ldb, int ldc,
                          long long sA, long long sB, long long sC,
                          float alpha, const float* aptr, float beta)
{
    dim3 g((N + 63) / 64, (M + 63) / 64, zcnt);
    gemm_f16<64, 64, 128, 4, 2, 4, 2, 4, true><<<g, 128, SMALLH_SMEM>>>(
        nullptr, nullptr, nullptr, nullptr, tA, tB, tbias, tC, zdiv,
        M, N, K, lda, ldb, ldc, sA, sB, sC, alpha, aptr, beta);
}

extern "C" void kernel_launch(void* const* d_in, const int* in_sizes, int n_in,
                              void* d_out, int out_size)
{
    const float* hidden = (const float*)d_in[0];
    const float* enc    = (const float*)d_in[1];
    const float* rc     = (const float*)d_in[2];
    const float* rs     = (const float*)d_in[3];
    const float* Wq  = (const float*)d_in[4];
    const float* Wk  = (const float*)d_in[5];
    const float* Wv  = (const float*)d_in[6];
    const float* Wqa = (const float*)d_in[7];
    const float* Wka = (const float*)d_in[8];
    const float* Wva = (const float*)d_in[9];
    const float* Wo  = (const float*)d_in[10];
    const float* Woa = (const float*)d_in[11];
    const float* bq  = (const float*)d_in[12];
    const float* bk  = (const float*)d_in[13];
    const float* bv  = (const float*)d_in[14];
    const float* bqa = (const float*)d_in[15];
    const float* bka = (const float*)d_in[16];
    const float* bva = (const float*)d_in[17];
    const float* bo  = (const float*)d_in[18];
    const float* boa = (const float*)d_in[19];
    const float* nqw  = (const float*)d_in[20];
    const float* nkw  = (const float*)d_in[21];
    const float* naqw = (const float*)d_in[22];
    const float* nakw = (const float*)d_in[23];
    const float* qd = (const float*)d_in[24];
    const float* kd = (const float*)d_in[25];
    const float* vd = (const float*)d_in[26];
    const float* qu = (const float*)d_in[27];
    const float* ku = (const float*)d_in[28];
    const float* vu = (const float*)d_in[29];
    const float* lw = (const float*)d_in[30];
    (void)qd; (void)qu;   // q-LoRA provably dead (only touches fully-masked rows)

    float *Pq, *Pk, *Pv, *Eq, *Ek, *Ev, *DtP, *V, *SA, *SB, *mnP, *mean, *vec;
    __half *hH, *hW, *Qh, *Kh, *Dth, *AOh;
    cudaGetSymbolAddress((void**)&Pq, g_Pq);
    cudaGetSymbolAddress((void**)&Pk, g_Pk);
    cudaGetSymbolAddress((void**)&Pv, g_Pv);
    cudaGetSymbolAddress((void**)&Eq, g_Eq);
    cudaGetSymbolAddress((void**)&Ek, g_Ek);
    cudaGetSymbolAddress((void**)&Ev, g_Ev);
    cudaGetSymbolAddress((void**)&DtP, g_DtP);
    cudaGetSymbolAddress((void**)&V,  g_V);
    cudaGetSymbolAddress((void**)&SA, g_SA);
    cudaGetSymbolAddress((void**)&SB, g_SB);
    cudaGetSymbolAddress((void**)&mnP, g_mnP);
    cudaGetSymbolAddress((void**)&mean, g_mean);
    cudaGetSymbolAddress((void**)&vec,  g_vec);
    cudaGetSymbolAddress((void**)&hH,  g_hH);
    cudaGetSymbolAddress((void**)&hW,  g_hW);
    cudaGetSymbolAddress((void**)&Qh,  g_Qh);
    cudaGetSymbolAddress((void**)&Kh,  g_Kh);
    cudaGetSymbolAddress((void**)&Dth, g_Dth);
    cudaGetSymbolAddress((void**)&AOh, g_AOh);

    const __half* const* tA;
    const __half* const* tB;
    const float* const* tbias;
    float* const* tC;
    {
        void *pA, *pB, *pb, *pC;
        cudaGetSymbolAddress(&pA, g_hA);
        cudaGetSymbolAddress(&pB, g_hB);
        cudaGetSymbolAddress(&pb, g_tbias);
        cudaGetSymbolAddress(&pC, g_tC);
        tA = (const __half* const*)pA;
        tB = (const __half* const*)pB;
        tbias = (const float* const*)pb;
        tC = (float* const*)pC;
    }

    float* out = (float*)d_out;

    // REQUIRED smem opt-ins (launches fail without them)
    cudaFuncSetAttribute(gemm_f16<128, 64, 256, 4, 2, 4, 4, 3, false>,
                         cudaFuncAttributeMaxDynamicSharedMemorySize, BIGH_SMEM);
    cudaFuncSetAttribute(gemm_f16<128, 64, 256, 4, 2, 4, 4, 3, true>,
                         cudaFuncAttributeMaxDynamicSharedMemorySize, BIGH_SMEM);
    cudaFuncSetAttribute(gemm_f16<64, 64, 128, 4, 2, 4, 2, 4, false>,
                         cudaFuncAttributeMaxDynamicSharedMemorySize, SMALLH_SMEM);
    cudaFuncSetAttribute(gemm_f16<64, 64, 128, 4, 2, 4, 2, 4, true>,
                         cudaFuncAttributeMaxDynamicSharedMemorySize, SMALLH_SMEM);
    cudaFuncSetAttribute(gemm_av,
                         cudaFuncAttributeMaxDynamicSharedMemorySize, AV_SMEM);

    // 0) fill tables, then convert ALL f16 operands in one fused launch
    setup_tabs<<<1, 1>>>(hidden, enc, Wq, Wk, Wv, Wqa, Wka, Wva, Wo, Woa,
                         bq, bk, bv, bqa, bka, bva, kd, vd, ku, vu);
    conv_all<<<C_TOTAL / 256, 256>>>();

    // 1) image k/v projections (batched, z=2); q projection only image rows [0,1024)
    f16_big_tab(tA + 0, tB + 0, tbias + 0, tC + 0, 2, 1,
                S_HID, DIMN, DIMN, DIMN, DIMN, DIMN, 0, 0, 0, 1.f, nullptr, 0.f);
    f16_big(hH, hW + 0 * (long long)DIMN * DIMN, bq, Pq,
            CONDN, DIMN, DIMN, DIMN, DIMN, DIMN, 0, 0, 0, 1, 1.f, nullptr, 0.f);

    // 2) encoder projections (batched, z=3)
    f16_small_tab(tA + 2, tB + 2, tbias + 2, tC + 2, 3, 1,
                  S_ENC, DIMN, DIMN, DIMN, DIMN, DIMN, 0, 0, 0, 1.f, nullptr, 0.f);

    // 3) LoRA k/v only (q-LoRA dead)
    f16_small_tab(tA + 5, tB + 5, tbias + 5, tC + 5, 2 * KSPLIT, KSPLIT,
                  CONDN, RANKN, DIMN / KSPLIT, DIMN, DIMN, RANKN,
                  DIMN / KSPLIT, DIMN / KSPLIT, (long long)CONDN * RANKN,
                  1.f, nullptr, 0.f);
    {
        dim3 rg((CONDN * RANKN) / 256, 2);
        reduce_splitk2<<<rg, 256>>>(DtP, Dth);
    }
    f16_small_tab(tA + 7, tB + 7, tbias + 7, tC + 7, 2, 1,
                  CONDN, DIMN, RANKN, RANKN, RANKN, DIMN, 0, 0, 0, 1.f, lw, 1.f);

    // 4) heads + RMSNorm + RoPE; Q only for rows < 1536
    build_qkv<<<dim3(SEQ, HEADS), HD>>>(Pq, Pk, Pv, Eq, Ek, Ev, rc, rs,
                                        nqw, nkw, naqw, nakw, Qh, Kh, V);

    // 5) block A: encoder queries vs full keys
    f16_big(Qh, Kh, nullptr, SA, S_ENC, SEQ, HD, HD, HD, SEQ,
            (long long)SEQ * HD, (long long)SEQ * HD, (long long)S_ENC * SEQ, HEADS,
            ATTN_SCALE, nullptr, 0.f);
    softmax_k<SEQ><<<HEADS * S_ENC, 256>>>(SA);
    {
        dim3 g(HD / 64, S_ENC / 64, HEADS);
        gemm_av<<<g, 128, AV_SMEM>>>(SA, V, AOh, S_ENC, HD, SEQ, SEQ, HD, DIMN,
                                     (long long)S_ENC * SEQ, (long long)SEQ * HD, HD);
    }

    // 6) block B: cond queries vs cond keys
    f16_big(Qh + (long long)S_ENC * HD, Kh + (long long)S_ENC * HD, nullptr, SB,
            CONDN, CONDN, HD, HD, HD, CONDN,
            (long long)SEQ * HD, (long long)SEQ * HD, (long long)CONDN * CONDN, HEADS,
            ATTN_SCALE, nullptr, 0.f);
    softmax_k<CONDN><<<HEADS * CONDN, 256>>>(SB);
    {
        dim3 g(HD / 64, CONDN / 64, HEADS);
        gemm_av<<<g, 128, AV_SMEM>>>(SB, V + (long long)S_ENC * HD,
                                     AOh + (long long)S_ENC * DIMN,
                                     CONDN, HD, CONDN, CONDN, HD, DIMN,
                                     (long long)CONDN * CONDN, (long long)SEQ * HD, HD);
    }

    // 7) fully-masked rows -> uniform softmax -> mean of V; one out-proj row
    mean_part<<<dim3(HEADS, SCHUNK), HD>>>(V, mnP);
    mean_fin<<<DIMN / 256, 256>>>(mnP, mean);
    gemv_out<<<DIMN / 8, 256>>>(mean, Wo, bo, vec);

    // 8) output projections (f16)
    f16_big(AOh + (long long)S_ENC * DIMN, hW + 6 * (long long)DIMN * DIMN, bo, out,
            CONDN, DIMN, DIMN, DIMN, DIMN, DIMN, 0, 0, 0, 1, 1.f, nullptr, 0.f);
    fill_rows<<<(NROWS_C * (DIMN / 4)) / 256, 256>>>(vec, out + (long long)CONDN * DIMN);
    f16_small(AOh, hW + 7 * (long long)DIMN * DIMN, boa, out + (long long)S_HID * DIMN,
              S_ENC, DIMN, DIMN, DIMN, DIMN, DIMN, 0, 0, 0, 1, 1.f, nullptr, 0.f);
}

// round 17
// speedup vs baseline: 1.9372x; 1.0233x over previous
#include <cuda_runtime.h>
#include <cuda_fp16.h>
#include <math.h>
#include <stdint.h>

// ---------------- problem constants ----------------
#define DIMN   3072
#define HEADS  24
#define HD     128
#define S_HID  3072
#define S_ENC  512
#define SEQ    3584          // S_ENC + S_HID
#define CONDN  1024
#define RANKN  64
#define BLOCKL 2048          // S_HID - CONDN
#define NROWS_C (SEQ - S_ENC - CONDN)   // 2048 fully-masked query rows
#define KSPLIT 16            // split-K for LoRA down-proj
#define SCHUNK 28            // mean s-chunks (SEQ = 28*128)
static const float ATTN_SCALE = 0.08838834764831843f; // 1/sqrt(128)

// ---------------- device scratch (no allocs allowed) ----------------
__device__ float g_Pq[(size_t)S_HID * DIMN];   // only rows [0,1024) used
__device__ float g_Pk[(size_t)S_HID * DIMN];
__device__ float g_Pv[(size_t)S_HID * DIMN];
__device__ float g_Eq[(size_t)S_ENC * DIMN];
__device__ float g_Ek[(size_t)S_ENC * DIMN];
__device__ float g_Ev[(size_t)S_ENC * DIMN];
__device__ float g_DtP[(size_t)2 * KSPLIT * CONDN * RANKN];   // k, v branches
__device__ float g_V [(size_t)HEADS * SEQ * HD];      // natural layout [h][s][d]
__device__ float g_SA[(size_t)HEADS * S_ENC * SEQ];   // encoder-query scores
__device__ float g_SB[(size_t)HEADS * CONDN * CONDN]; // cond-block scores
__device__ float g_mnP[(size_t)SCHUNK * DIMN];
__device__ float g_mean[DIMN];
__device__ float g_vec [DIMN];
// half operand buffers
__device__ __half g_hH[(size_t)S_HID * DIMN];
__device__ __half g_hE[(size_t)S_ENC * DIMN];
__device__ __half g_hW[8][(size_t)DIMN * DIMN];   // Wq Wk Wv Wqa Wka Wva Wo Woa
__device__ __half g_hdn[2][(size_t)RANKN * DIMN]; // kd, vd
__device__ __half g_hup[2][(size_t)DIMN * RANKN]; // ku, vu
__device__ __half g_Qh[(size_t)HEADS * SEQ * HD];
__device__ __half g_Kh[(size_t)HEADS * SEQ * HD];
__device__ __half g_Dth[(size_t)2 * CONDN * RANKN];
__device__ __half g_AOh[(size_t)(S_ENC + CONDN) * DIMN];

// pointer tables for batched f16 GEMM groups:
// [0..1]=img k/v proj, [2..4]=enc proj, [5..6]=lora-down k/v, [7..8]=lora-up k/v
__device__ const __half* g_hA[9];
__device__ const __half* g_hB[9];
__device__ const float*  g_tbias[9];
__device__ float*        g_tC[9];
// fused conversion tables (14 entries)
__device__ const float* g_cS[14];
__device__ __half*      g_cD[14];

// conversion chunk counts (float4 units) — compile-time
#define C_HID (S_HID * DIMN / 4)
#define C_ENC (S_ENC * DIMN / 4)
#define C_W   (DIMN * DIMN / 4)
#define C_LR  (RANKN * DIMN / 4)
#define C_TOTAL (C_HID + C_ENC + 8 * C_W + 4 * C_LR)

// ---------------- helpers ----------------
__device__ __forceinline__ uint32_t f2tf(float f) {
    uint32_t u;
    asm("cvt.rna.tf32.f32 %0, %1;" : "=r"(u) : "f"(f));
    return u;
}

__device__ __forceinline__ void cpa16(void* dst, const void* src, bool pred) {
    uint32_t d = (uint32_t)__cvta_generic_to_shared(dst);
    int sz = pred ? 16 : 0;   // src-size 0 => zero-fill
    asm volatile("cp.async.cg.shared.global [%0], [%1], 16, %2;\n"
                 :: "r"(d), "l"(src), "r"(sz));
}

__device__ __forceinline__ void mma_tf32(float* c, const uint32_t* a, const uint32_t* b) {
    asm volatile(
        "mma.sync.aligned.m16n8k8.row.col.f32.tf32.tf32.f32 "
        "{%0,%1,%2,%3}, {%4,%5,%6,%7}, {%8,%9}, {%0,%1,%2,%3};\n"
        : "+f"(c[0]), "+f"(c[1]), "+f"(c[2]), "+f"(c[3])
        : "r"(a[0]), "r"(a[1]), "r"(a[2]), "r"(a[3]), "r"(b[0]), "r"(b[1]));
}

__device__ __forceinline__ void mma_f16(float* c, const uint32_t* a, const uint32_t* b) {
    asm volatile(
        "mma.sync.aligned.m16n8k16.row.col.f32.f16.f16.f32 "
        "{%0,%1,%2,%3}, {%4,%5,%6,%7}, {%8,%9}, {%0,%1,%2,%3};\n"
        : "+f"(c[0]), "+f"(c[1]), "+f"(c[2]), "+f"(c[3])
        : "r"(a[0]), "r"(a[1]), "r"(a[2]), "r"(a[3]), "r"(b[0]), "r"(b[1]));
}

// ---------------- fp16 tensor-core GEMM (LDSM fragment loads) ----------------
// C(f32) = alpha * A[M,K](half) @ B[N,K]^T(half) + bias + beta*C.
// BK = 32 halves per stage; smem row stride 80 B (20 half2) -> ldmatrix rows
// hit all 32 banks exactly once (conflict-free).
// TAB: operands from pointer tables (zi = z/zdiv entry, zr*strides = split-K).
#define ASTRH 20   // smem row stride in half2 units (80 bytes)

template <int TBM, int TBN, int THREADS, int NSTAGE, int MT, int NT, int WMC,
          int OCC, bool TAB>
__global__ __launch_bounds__(THREADS, OCC)
void gemm_f16(const __half* __restrict__ A, const __half* __restrict__ B,
              const float* __restrict__ bias, float* __restrict__ C,
              const __half* const* __restrict__ Aarr,
              const __half* const* __restrict__ Barr,
              const float* const* __restrict__ biasarr,
              float* const* __restrict__ Carr, int zdiv,
              int M, int N, int K, int lda, int ldb, int ldc,
              long long sA, long long sB, long long sC,
              float alpha, const float* __restrict__ alpha_ptr, float beta)
{
    constexpr int PF = NSTAGE - 1;
    constexpr int ASTG = TBM * ASTRH;   // half2 per A stage
    constexpr int BSTG = TBN * ASTRH;
    extern __shared__ uint32_t smh[];
    uint32_t* As = smh;
    uint32_t* Bs = smh + NSTAGE * ASTG;

    const __half* Ab;
    const __half* Bb;
    float*        Cb;
    const float*  biasb;
    if (TAB) {
        const int zi = blockIdx.z / zdiv;
        const int zr = blockIdx.z - zi * zdiv;
        Ab = Aarr[zi] + (long long)zr * sA;
        Bb = Barr[zi] + (long long)zr * sB;
        Cb = Carr[zi] + (long long)zr * sC;
        biasb = biasarr[zi];
    } else {
        Ab = A + (long long)blockIdx.z * sA;
        Bb = B + (long long)blockIdx.z * sB;
        Cb = C + (long long)blockIdx.z * sC;
        biasb = bias;
    }

    const int m0 = blockIdx.y * TBM;
    const int n0 = blockIdx.x * TBN;
    const int tid  = threadIdx.x;
    const int lane = tid & 31;
    const int warp = tid >> 5;
    const int wm = (warp % WMC) * (MT * 16);
    const int wn = (warp / WMC) * (NT * 8);
    const int g  = lane >> 2;
    const int tg = lane & 3;

    // ldmatrix per-lane byte offsets: quad q = lane>>3 selects 8x8 matrix
    const int lrow8 = (lane & 7) + ((lane >> 3) & 1) * 8;
    const int lk16  = (lane >> 4) * 16;
    const uint32_t smb = (uint32_t)__cvta_generic_to_shared(smh);
    uint32_t aoff[MT];
#pragma unroll
    for (int mt = 0; mt < MT; mt++)
        aoff[mt] = (uint32_t)((wm + mt * 16 + lrow8) * (ASTRH * 4) + lk16);
    uint32_t boff[NT / 2];
#pragma unroll
    for (int np = 0; np < NT / 2; np++)
        boff[np] = (uint32_t)((wn + np * 16 + lrow8) * (ASTRH * 4) + lk16);

    float c[MT][NT][4];
#pragma unroll
    for (int i = 0; i < MT; i++)
#pragma unroll
        for (int j = 0; j < NT; j++)
#pragma unroll
            for (int r = 0; r < 4; r++) c[i][j][r] = 0.f;

    const int nk = K / 32;

    auto load_tile = [&](int k0 /*halves*/, int buf) {
        uint32_t* Ad = As + buf * ASTG;
        uint32_t* Bd = Bs + buf * BSTG;
#pragma unroll
        for (int j = 0; j < TBM * 4 / THREADS; j++) {
            const int cidx = tid + j * THREADS;
            const int row  = cidx >> 2;
            const int ch2  = (cidx & 3) << 2;     // half2 offset in row
            cpa16(Ad + row * ASTRH + ch2,
                  Ab + (long long)(m0 + row) * lda + k0 + ch2 * 2,
                  (m0 + row) < M);
        }
#pragma unroll
        for (int j = 0; j < TBN * 4 / THREADS; j++) {
            const int cidx = tid + j * THREADS;
            const int row  = cidx >> 2;
            const int ch2  = (cidx & 3) << 2;
            cpa16(Bd + row * ASTRH + ch2,
                  Bb + (long long)(n0 + row) * ldb + k0 + ch2 * 2,
                  (n0 + row) < N);
        }
        asm volatile("cp.async.commit_group;\n");
    };

    for (int s = 0; s < PF; s++) {
        if (s < nk) load_tile(s * 32, s);
        else        asm volatile("cp.async.commit_group;\n");
    }

    for (int it = 0; it < nk; it++) {
        if (it + PF < nk) load_tile((it + PF) * 32, (it + PF) & (NSTAGE - 1));
        else              asm volatile("cp.async.commit_group;\n");
        asm volatile("cp.async.wait_group %0;\n" :: "n"(PF));
        __syncthreads();

        const int buf = it & (NSTAGE - 1);
        const uint32_t Abs = smb + (uint32_t)(buf * ASTG) * 4u;
        const uint32_t Bbs = smb + (uint32_t)(NSTAGE * ASTG + buf * BSTG) * 4u;

#pragma unroll
        for (int s16 = 0; s16 < 2; s16++) {       // two k16 steps per BK=32
            const uint32_t kb = s16 * 32;         // bytes (16 halves)
            uint32_t bf[NT][2];
#pragma unroll
            for (int np = 0; np < NT / 2; np++) {
                asm volatile(
                    "ldmatrix.sync.aligned.m8n8.x4.shared.b16 {%0,%1,%2,%3}, [%4];"
                    : "=r"(bf[2 * np][0]), "=r"(bf[2 * np + 1][0]),
                      "=r"(bf[2 * np][1]), "=r"(bf[2 * np + 1][1])
                    : "r"(Bbs + boff[np] + kb));
            }
            uint32_t af[MT][4];
#pragma unroll
            for (int mt = 0; mt < MT; mt++) {
                asm volatile(
                    "ldmatrix.sync.aligned.m8n8.x4.shared.b16 {%0,%1,%2,%3}, [%4];"
                    : "=r"(af[mt][0]), "=r"(af[mt][1]),
                      "=r"(af[mt][2]), "=r"(af[mt][3])
                    : "r"(Abs + aoff[mt] + kb));
            }
#pragma unroll
            for (int mt = 0; mt < MT; mt++)
#pragma unroll
                for (int nt = 0; nt < NT; nt++)
                    mma_f16(c[mt][nt], af[mt], bf[nt]);
        }
        __syncthreads();
    }

    float aE = alpha;
    if (alpha_ptr) aE *= *alpha_ptr;

#pragma unroll
    for (int mt = 0; mt < MT; mt++) {
#pragma unroll
        for (int r = 0; r < 2; r++) {
            const int gm = m0 + wm + mt * 16 + g + r * 8;
            if (gm >= M) continue;
            float* crow = Cb + (long long)gm * ldc;
#pragma unroll
            for (int nt = 0; nt < NT; nt++) {
                const int gn = n0 + wn + nt * 8 + tg * 2;
                if (gn >= N) continue;
                float x = c[mt][nt][r * 2 + 0] * aE;
                float y = c[mt][nt][r * 2 + 1] * aE;
                if (biasb) { x += biasb[gn]; y += biasb[gn + 1]; }
                if (beta != 0.f) {
                    float2 p = *(const float2*)(crow + gn);
                    x += beta * p.x; y += beta * p.y;
                }
                *(float2*)(crow + gn) = make_float2(x, y);
            }
        }
    }
}

#define BIGH_SMEM   (4 * (128 + 64) * ASTRH * 4)
#define BIG2H_SMEM  (4 * (128 + 128) * ASTRH * 4)
#define SMALLH_SMEM (4 * ( 64 + 64) * ASTRH * 4)

// ---------------- tf32 AV GEMM: AO(half) = P(f32)[M,K] @ V(f32)[K,N] ----------------
#define AVBK 16
#define AASTR 20
#define BVSTR 68

__global__ __launch_bounds__(128, 4)
void gemm_av(const float* __restrict__ A, const float* __restrict__ B,
             __half* __restrict__ C,
             int M, int N, int K, int lda, int ldb, int ldc,
             long long sA, long long sB, long long sC)
{
    constexpr int NSTAGE = 4, PF = 3;
    constexpr int ASTG = 64 * AASTR;
    constexpr int BSTG = AVBK * BVSTR;
    extern __shared__ float smem[];
    float* As = smem;
    float* Bs = smem + NSTAGE * ASTG;

    const float* Ab = A + (long long)blockIdx.z * sA;
    const float* Bb = B + (long long)blockIdx.z * sB;
    __half*      Cb = C + (long long)blockIdx.z * sC;

    const int m0 = blockIdx.y * 64;
    const int n0 = blockIdx.x * 64;
    const int tid  = threadIdx.x;
    const int lane = tid & 31;
    const int warp = tid >> 5;
    const int wm = (warp & 1) * 32;
    const int wn = (warp >> 1) * 32;
    const int g  = lane >> 2;
    const int tg = lane & 3;

    float c[2][4][4];
#pragma unroll
    for (int i = 0; i < 2; i++)
#pragma unroll
        for (int j = 0; j < 4; j++)
#pragma unroll
            for (int r = 0; r < 4; r++) c[i][j][r] = 0.f;

    const int nk = K / AVBK;

    auto load_tile = [&](int k0, int buf) {
        float* Ad = As + buf * ASTG;
        float* Bd = Bs + buf * BSTG;
#pragma unroll
        for (int j = 0; j < 2; j++) {
            const int cidx = tid + j * 128;
            const int row  = cidx >> 2;
            const int kc   = (cidx & 3) << 2;
            cpa16(Ad + row * AASTR + kc,
                  Ab + (long long)(m0 + row) * lda + k0 + kc,
                  (m0 + row) < M);
        }
#pragma unroll
        for (int j = 0; j < 2; j++) {
            const int cidx = tid + j * 128;
            const int row  = cidx >> 4;
            const int col  = (cidx & 15) << 2;
            cpa16(Bd + row * BVSTR + col,
                  Bb + (long long)(k0 + row) * ldb + n0 + col,
                  (n0 + col) < N);
        }
        asm volatile("cp.async.commit_group;\n");
    };

    for (int s = 0; s < PF; s++) {
        if (s < nk) load_tile(s * AVBK, s);
        else        asm volatile("cp.async.commit_group;\n");
    }

    for (int it = 0; it < nk; it++) {
        if (it + PF < nk) load_tile((it + PF) * AVBK, (it + PF) & 3);
        else              asm volatile("cp.async.commit_group;\n");
        asm volatile("cp.async.wait_group %0;\n" :: "n"(PF));
        __syncthreads();

        const int buf = it & 3;
        const float* Ac = As + buf * ASTG;
        const float* Bc = Bs + buf * BSTG;

#pragma unroll
        for (int ks = 0; ks < AVBK; ks += 8) {
            uint32_t bf[4][2];
#pragma unroll
            for (int nt = 0; nt < 4; nt++) {
                const float* bp = Bc + (ks + tg) * BVSTR + wn + nt * 8 + g;
                bf[nt][0] = f2tf(bp[0]);
                bf[nt][1] = f2tf(bp[4 * BVSTR]);
            }
            uint32_t af[2][4];
#pragma unroll
            for (int mt = 0; mt < 2; mt++) {
                const float* ap = Ac + (wm + mt * 16 + g) * AASTR + ks + tg;
                af[mt][0] = f2tf(ap[0]);
                af[mt][1] = f2tf(ap[8 * AASTR]);
                af[mt][2] = f2tf(ap[4]);
                af[mt][3] = f2tf(ap[8 * AASTR + 4]);
            }
#pragma unroll
            for (int mt = 0; mt < 2; mt++)
#pragma unroll
                for (int nt = 0; nt < 4; nt++)
                    mma_tf32(c[mt][nt], af[mt], bf[nt]);
        }
        __syncthreads();
    }

#pragma unroll
    for (int mt = 0; mt < 2; mt++) {
#pragma unroll
        for (int r = 0; r < 2; r++) {
            const int gm = m0 + wm + mt * 16 + g + r * 8;
            if (gm >= M) continue;
            __half* crow = Cb + (long long)gm * ldc;
#pragma unroll
            for (int nt = 0; nt < 4; nt++) {
                const int gn = n0 + wn + nt * 8 + tg * 2;
                if (gn >= N) continue;
                *(__half2*)(crow + gn) =
                    __floats2half2_rn(c[mt][nt][r * 2 + 0], c[mt][nt][r * 2 + 1]);
            }
        }
    }
}

#define AV_SMEM (4 * (64 * AASTR + AVBK * BVSTR) * 4)

// ---------------- setup kernel: fill pointer tables ----------------
__global__ void setup_tabs(const float* hidden, const float* enc,
                           const float* Wq, const float* Wk, const float* Wv,
                           const float* Wqa, const float* Wka, const float* Wva,
                           const float* Wo, const float* Woa,
                           const float* bq, const float* bk, const float* bv,
                           const float* bqa, const float* bka, const float* bva,
                           const float* kd, const float* vd,
                           const float* ku, const float* vu)
{
    // conversion tables
    g_cS[0] = hidden; g_cD[0] = g_hH;
    g_cS[1] = enc;    g_cD[1] = g_hE;
    const float* Ws[8] = {Wq, Wk, Wv, Wqa, Wka, Wva, Wo, Woa};
    for (int i = 0; i < 8; i++) { g_cS[2 + i] = Ws[i]; g_cD[2 + i] = g_hW[i]; }
    g_cS[10] = kd; g_cD[10] = g_hdn[0];
    g_cS[11] = vd; g_cD[11] = g_hdn[1];
    g_cS[12] = ku; g_cD[12] = g_hup[0];
    g_cS[13] = vu; g_cD[13] = g_hup[1];

    // GEMM tables
    g_hA[0] = g_hH; g_hA[1] = g_hH;
    g_hB[0] = g_hW[1]; g_hB[1] = g_hW[2];
    g_tC[0] = g_Pk; g_tC[1] = g_Pv;
    g_tbias[0] = bk; g_tbias[1] = bv;
    g_hA[2] = g_hE; g_hA[3] = g_hE; g_hA[4] = g_hE;
    g_hB[2] = g_hW[3]; g_hB[3] = g_hW[4]; g_hB[4] = g_hW[5];
    g_tC[2] = g_Eq; g_tC[3] = g_Ek; g_tC[4] = g_Ev;
    g_tbias[2] = bqa; g_tbias[3] = bka; g_tbias[4] = bva;
    const __half* hm = g_hH + (long long)BLOCKL * DIMN;
    g_hA[5] = hm; g_hA[6] = hm;
    g_hB[5] = g_hdn[0]; g_hB[6] = g_hdn[1];
    g_tC[5] = g_DtP + 0 * (size_t)KSPLIT * CONDN * RANKN;
    g_tC[6] = g_DtP + 1 * (size_t)KSPLIT * CONDN * RANKN;
    g_tbias[5] = nullptr; g_tbias[6] = nullptr;
    g_hA[7] = g_Dth + 0 * (size_t)CONDN * RANKN;
    g_hA[8] = g_Dth + 1 * (size_t)CONDN * RANKN;
    g_hB[7] = g_hup[0]; g_hB[8] = g_hup[1];
    g_tC[7] = g_Pk + (long long)BLOCKL * DIMN;
    g_tC[8] = g_Pv + (long long)BLOCKL * DIMN;
    g_tbias[7] = nullptr; g_tbias[8] = nullptr;
}

// ---------------- fused f32->f16 conversion (all operands, one launch) ----------------
__global__ void conv_all()
{
    int idx = blockIdx.x * 256 + threadIdx.x;
    const int sz[14] = {C_HID, C_ENC, C_W, C_W, C_W, C_W, C_W, C_W, C_W, C_W,
                        C_LR, C_LR, C_LR, C_LR};
#pragma unroll
    for (int e = 0; e < 14; e++) {
        if (idx < sz[e]) {
            float4 v = ((const float4*)g_cS[e])[idx];
            __half2* d = (__half2*)g_cD[e];
            d[2 * idx + 0] = __floats2half2_rn(v.x, v.y);
            d[2 * idx + 1] = __floats2half2_rn(v.z, v.w);
            return;
        }
        idx -= sz[e];
    }
}

// ---------------- elementwise kernels ----------------
__global__ void build_qkv(const float* __restrict__ Pq, const float* __restrict__ Pk,
                          const float* __restrict__ Pv, const float* __restrict__ Eq,
                          const float* __restrict__ Ek, const float* __restrict__ Ev,
                          const float* __restrict__ rc, const float* __restrict__ rs,
                          const float* __restrict__ nqw, const float* __restrict__ nkw,
                          const float* __restrict__ naqw, const float* __restrict__ nakw,
                          __half* __restrict__ Qh, __half* __restrict__ Kh,
                          float* __restrict__ V)
{
    const int s = blockIdx.x;
    const int h = blockIdx.y;
    const int d = threadIdx.x;
    const bool needQ = (s < S_ENC + CONDN);   // rows >= 1536 are fully masked

    const float *sq, *sk, *sv, *wq, *wk;
    if (s < S_ENC) {
        const long long off = (long long)s * DIMN + h * HD;
        sq = Eq + off; sk = Ek + off; sv = Ev + off;
        wq = naqw; wk = nakw;
    } else {
        const long long off = (long long)(s - S_ENC) * DIMN + h * HD;
        sq = Pq + off; sk = Pk + off; sv = Pv + off;
        wq = nqw; wk = nkw;
    }
    float q = needQ ? sq[d] : 0.f;
    float k = sk[d], v = sv[d];

    float ssq = q * q, ssk = k * k;
#pragma unroll
    for (int o = 16; o; o >>= 1) {
        ssq += __shfl_xor_sync(0xffffffffu, ssq, o);
        ssk += __shfl_xor_sync(0xffffffffu, ssk, o);
    }
    __shared__ float shq[4], shk[4];
    const int w = d >> 5;
    if ((d & 31) == 0) { shq[w] = ssq; shk[w] = ssk; }
    __syncthreads();
    const float tq = shq[0] + shq[1] + shq[2] + shq[3];
    const float tk = shk[0] + shk[1] + shk[2] + shk[3];

    const float qn = q * rsqrtf(tq * (1.0f / HD) + 1e-6f) * wq[d];
    const float kn = k * rsqrtf(tk * (1.0f / HD) + 1e-6f) * wk[d];

    const float qp = __shfl_xor_sync(0xffffffffu, qn, 1);
    const float kp = __shfl_xor_sync(0xffffffffu, kn, 1);
    const float qr = (d & 1) ? qp : -qp;
    const float kr = (d & 1) ? kp : -kp;

    const float cc = rc[(long long)s * HD + d];
    const float sn = rs[(long long)s * HD + d];

    const long long o = ((long long)h * SEQ + s) * HD + d;
    if (needQ) Qh[o] = __float2half_rn(qn * cc + qr * sn);
    Kh[o] = __float2half_rn(kn * cc + kr * sn);
    V[o] = v;
}

// register-cached softmax: 1 global read + 1 global write per element
template <int NC>
__global__ void softmax_k(float* __restrict__ S)
{
    constexpr int PT = NC / 256;
    float* r = S + (long long)blockIdx.x * NC;
    const int tid = threadIdx.x;
    __shared__ float sh[8];

    float v[PT];
#pragma unroll
    for (int i = 0; i < PT; i++) v[i] = r[tid + i * 256];

    float m = v[0];
#pragma unroll
    for (int i = 1; i < PT; i++) m = fmaxf(m, v[i]);
#pragma unroll
    for (int o = 16; o; o >>= 1) m = fmaxf(m, __shfl_xor_sync(0xffffffffu, m, o));
    if ((tid & 31) == 0) sh[tid >> 5] = m;
    __syncthreads();
    float bm = sh[0];
#pragma unroll
    for (int i = 1; i < 8; i++) bm = fmaxf(bm, sh[i]);
    __syncthreads();

    float sum = 0.f;
#pragma unroll
    for (int i = 0; i < PT; i++) {
        v[i] = expf(v[i] - bm);
        sum += v[i];
    }
#pragma unroll
    for (int o = 16; o; o >>= 1) sum += __shfl_xor_sync(0xffffffffu, sum, o);
    if ((tid & 31) == 0) sh[tid >> 5] = sum;
    __syncthreads();
    float bs = 0.f;
#pragma unroll
    for (int i = 0; i < 8; i++) bs += sh[i];
    const float inv = 1.0f / bs;
#pragma unroll
    for (int i = 0; i < PT; i++) r[tid + i * 256] = v[i] * inv;
}

__global__ void mean_part(const float* __restrict__ V, float* __restrict__ P)
{
    const int h  = blockIdx.x;
    const int ch = blockIdx.y;
    const int d  = threadIdx.x;
    const float* base = V + ((long long)h * SEQ + ch * (SEQ / SCHUNK)) * HD + d;
    float s = 0.f;
#pragma unroll 4
    for (int i = 0; i < SEQ / SCHUNK; i++) s += base[(long long)i * HD];
    P[(size_t)ch * DIMN + h * HD + d] = s;
}

__global__ void mean_fin(const float* __restrict__ P, float* __restrict__ mean)
{
    const int j = blockIdx.x * 256 + threadIdx.x;
    float s = 0.f;
#pragma unroll
    for (int c = 0; c < SCHUNK; c++) s += P[(size_t)c * DIMN + j];
    mean[j] = s * (1.0f / SEQ);
}

__global__ void gemv_out(const float* __restrict__ mean, const float* __restrict__ Wo,
                         const float* __restrict__ bo, float* __restrict__ vec)
{
    const int j = blockIdx.x * 8 + (threadIdx.x >> 5);
    const int lane = threadIdx.x & 31;
    const float* w = Wo + (long long)j * DIMN;
    float s = 0.f;
    for (int d = lane; d < DIMN; d += 32) s += mean[d] * w[d];
#pragma unroll
    for (int o = 16; o; o >>= 1) s += __shfl_xor_sync(0xffffffffu, s, o);
    if (lane == 0) vec[j] = s + bo[j];
}

__global__ void fill_rows(const float* __restrict__ vec, float* __restrict__ out)
{
    const long long i = (long long)blockIdx.x * 256 + threadIdx.x;
    const float4 v = ((const float4*)vec)[i % (DIMN / 4)];
    ((float4*)out)[i] = v;
}

__global__ void reduce_splitk2(const float* __restrict__ P, __half* __restrict__ D)
{
    const int i = blockIdx.y;   // branch (k=0, v=1)
    const int j = blockIdx.x * 256 + threadIdx.x;
    const float* base = P + (size_t)i * KSPLIT * CONDN * RANKN + j;
    float s = 0.f;
#pragma unroll
    for (int z = 0; z < KSPLIT; z++) s += base[(size_t)z * CONDN * RANKN];
    D[(size_t)i * CONDN * RANKN + j] = __float2half_rn(s);
}

// ---------------- host-side launch helpers ----------------
#define NULLTAB nullptr, nullptr, nullptr, nullptr, 1

static void f16_big2(const __half* A, const __half* B, const float* bias, float* C,
                     int M, int N, int K, int lda, int ldb, int ldc,
                     long long sA, long long sB, long long sC, int batch,
                     float alpha, const float* aptr, float beta)
{
    dim3 g((N + 127) / 128, (M + 127) / 128, batch);
    gemm_f16<128, 128, 256, 4, 2, 8, 4, 2, false><<<g, 256, BIG2H_SMEM>>>(
        A, B, bias, C, NULLTAB, M, N, K, lda, ldb, ldc, sA, sB, sC, alpha, aptr, beta);
}

static void f16_big2_tab(const __half* const* tA, const __half* const* tB,
                         const float* const* tbias, float* const* tC,
                         int zcnt, int zdiv,
                         int M, int N, int K, int lda, int ldb, int ldc,
                         long long sA, long long sB, long long sC,
                         float alpha, const float* aptr, float beta)
{
    dim3 g((N + 127) / 128, (M + 127) / 128, zcnt);
    gemm_f16<128, 128, 256, 4, 2, 8, 4, 2, true><<<g, 256, BIG2H_SMEM>>>(
        nullptr, nullptr, nullptr, nullptr, tA, tB, tbias, tC, zdiv,
        M, N, K, lda, ldb, ldc, sA, sB, sC, alpha, aptr, beta);
}

static void f16_small(const __half* A, const __half* B, const float* bias, float* C,
                      int M, int N, int K, int lda, int ldb, int ldc,
                      long long sA, long long sB, long long sC, int batch,
                      float alpha, const float* aptr, float beta)
{
    dim3 g((N + 63) / 64, (M + 63) / 64, batch);
    gemm_f16<64, 64, 128, 4, 2, 4, 2, 4, false><<<g, 128, SMALLH_SMEM>>>(
        A, B, bias, C, NULLTAB, M, N, K, lda, ldb, ldc, sA, sB, sC, alpha, aptr, beta);
}

static void f16_small_tab(const __half* const* tA, const __half* const* tB,
                          const float* const* tbias, float* const* tC,
                          int zcnt, int zdiv,
                          int M, int N, int K, int lda, int ldb, int ldc,
                          long long sA, long long sB, long long sC,
                          float alpha, const float* aptr, float beta)
{
    dim3 g((N + 63) / 64, (M + 63) / 64, zcnt);
    gemm_f16<64, 64, 128, 4, 2, 4, 2, 4, true><<<g, 128, SMALLH_SMEM>>>(
        nullptr, nullptr, nullptr, nullptr, tA, tB, tbias, tC, zdiv,
        M, N, K, lda, ldb, ldc, sA, sB, sC, alpha, aptr, beta);
}

extern "C" void kernel_launch(void* const* d_in, const int* in_sizes, int n_in,
                              void* d_out, int out_size)
{
    const float* hidden = (const float*)d_in[0];
    const float* enc    = (const float*)d_in[1];
    const float* rc     = (const float*)d_in[2];
    const float* rs     = (const float*)d_in[3];
    const float* Wq  = (const float*)d_in[4];
    const float* Wk  = (const float*)d_in[5];
    const float* Wv  = (const float*)d_in[6];
    const float* Wqa = (const float*)d_in[7];
    const float* Wka = (const float*)d_in[8];
    const float* Wva = (const float*)d_in[9];
    const float* Wo  = (const float*)d_in[10];
    const float* Woa = (const float*)d_in[11];
    const float* bq  = (const float*)d_in[12];
    const float* bk  = (const float*)d_in[13];
    const float* bv  = (const float*)d_in[14];
    const float* bqa = (const float*)d_in[15];
    const float* bka = (const float*)d_in[16];
    const float* bva = (const float*)d_in[17];
    const float* bo  = (const float*)d_in[18];
    const float* boa = (const float*)d_in[19];
    const float* nqw  = (const float*)d_in[20];
    const float* nkw  = (const float*)d_in[21];
    const float* naqw = (const float*)d_in[22];
    const float* nakw = (const float*)d_in[23];
    const float* qd = (const float*)d_in[24];
    const float* kd = (const float*)d_in[25];
    const float* vd = (const float*)d_in[26];
    const float* qu = (const float*)d_in[27];
    const float* ku = (const float*)d_in[28];
    const float* vu = (const float*)d_in[29];
    const float* lw = (const float*)d_in[30];
    (void)qd; (void)qu;   // q-LoRA provably dead (only touches fully-masked rows)

    float *Pq, *Pk, *Pv, *Eq, *Ek, *Ev, *DtP, *V, *SA, *SB, *mnP, *mean, *vec;
    __half *hH, *hW, *Qh, *Kh, *Dth, *AOh;
    cudaGetSymbolAddress((void**)&Pq, g_Pq);
    cudaGetSymbolAddress((void**)&Pk, g_Pk);
    cudaGetSymbolAddress((void**)&Pv, g_Pv);
    cudaGetSymbolAddress((void**)&Eq, g_Eq);
    cudaGetSymbolAddress((void**)&Ek, g_Ek);
    cudaGetSymbolAddress((void**)&Ev, g_Ev);
    cudaGetSymbolAddress((void**)&DtP, g_DtP);
    cudaGetSymbolAddress((void**)&V,  g_V);
    cudaGetSymbolAddress((void**)&SA, g_SA);
    cudaGetSymbolAddress((void**)&SB, g_SB);
    cudaGetSymbolAddress((void**)&mnP, g_mnP);
    cudaGetSymbolAddress((void**)&mean, g_mean);
    cudaGetSymbolAddress((void**)&vec,  g_vec);
    cudaGetSymbolAddress((void**)&hH,  g_hH);
    cudaGetSymbolAddress((void**)&hW,  g_hW);
    cudaGetSymbolAddress((void**)&Qh,  g_Qh);
    cudaGetSymbolAddress((void**)&Kh,  g_Kh);
    cudaGetSymbolAddress((void**)&Dth, g_Dth);
    cudaGetSymbolAddress((void**)&AOh, g_AOh);

    const __half* const* tA;
    const __half* const* tB;
    const float* const* tbias;
    float* const* tC;
    {
        void *pA, *pB, *pb, *pC;
        cudaGetSymbolAddress(&pA, g_hA);
        cudaGetSymbolAddress(&pB, g_hB);
        cudaGetSymbolAddress(&pb, g_tbias);
        cudaGetSymbolAddress(&pC, g_tC);
        tA = (const __half* const*)pA;
        tB = (const __half* const*)pB;
        tbias = (const float* const*)pb;
        tC = (float* const*)pC;
    }

    float* out = (float*)d_out;

    // REQUIRED smem opt-ins (launches fail without them)
    cudaFuncSetAttribute(gemm_f16<128, 128, 256, 4, 2, 8, 4, 2, false>,
                         cudaFuncAttributeMaxDynamicSharedMemorySize, BIG2H_SMEM);
    cudaFuncSetAttribute(gemm_f16<128, 128, 256, 4, 2, 8, 4, 2, true>,
                         cudaFuncAttributeMaxDynamicSharedMemorySize, BIG2H_SMEM);
    cudaFuncSetAttribute(gemm_f16<64, 64, 128, 4, 2, 4, 2, 4, false>,
                         cudaFuncAttributeMaxDynamicSharedMemorySize, SMALLH_SMEM);
    cudaFuncSetAttribute(gemm_f16<64, 64, 128, 4, 2, 4, 2, 4, true>,
                         cudaFuncAttributeMaxDynamicSharedMemorySize, SMALLH_SMEM);
    cudaFuncSetAttribute(gemm_av,
                         cudaFuncAttributeMaxDynamicSharedMemorySize, AV_SMEM);

    // 0) fill tables, then convert ALL f16 operands in one fused launch
    setup_tabs<<<1, 1>>>(hidden, enc, Wq, Wk, Wv, Wqa, Wka, Wva, Wo, Woa,
                         bq, bk, bv, bqa, bka, bva, kd, vd, ku, vu);
    conv_all<<<C_TOTAL / 256, 256>>>();

    // 1) image k/v projections (batched, z=2, 128x128); Pq only rows [0,1024)
    f16_big2_tab(tA + 0, tB + 0, tbias + 0, tC + 0, 2, 1,
                 S_HID, DIMN, DIMN, DIMN, DIMN, DIMN, 0, 0, 0, 1.f, nullptr, 0.f);
    f16_big2(hH, hW + 0 * (long long)DIMN * DIMN, bq, Pq,
             CONDN, DIMN, DIMN, DIMN, DIMN, DIMN, 0, 0, 0, 1, 1.f, nullptr, 0.f);

    // 2) encoder projections (batched, z=3, 128x128)
    f16_big2_tab(tA + 2, tB + 2, tbias + 2, tC + 2, 3, 1,
                 S_ENC, DIMN, DIMN, DIMN, DIMN, DIMN, 0, 0, 0, 1.f, nullptr, 0.f);

    // 3) LoRA k/v only (q-LoRA dead); down N=64 -> SMALL, up -> 128x128
    f16_small_tab(tA + 5, tB + 5, tbias + 5, tC + 5, 2 * KSPLIT, KSPLIT,
                  CONDN, RANKN, DIMN / KSPLIT, DIMN, DIMN, RANKN,
                  DIMN / KSPLIT, DIMN / KSPLIT, (long long)CONDN * RANKN,
                  1.f, nullptr, 0.f);
    {
        dim3 rg((CONDN * RANKN) / 256, 2);
        reduce_splitk2<<<rg, 256>>>(DtP, Dth);
    }
    f16_big2_tab(tA + 7, tB + 7, tbias + 7, tC + 7, 2, 1,
                 CONDN, DIMN, RANKN, RANKN, RANKN, DIMN, 0, 0, 0, 1.f, lw, 1.f);

    // 4) heads + RMSNorm + RoPE; Q only for rows < 1536
    build_qkv<<<dim3(SEQ, HEADS), HD>>>(Pq, Pk, Pv, Eq, Ek, Ev, rc, rs,
                                        nqw, nkw, naqw, nakw, Qh, Kh, V);

    // 5) block A: encoder queries vs full keys (128x128)
    f16_big2(Qh, Kh, nullptr, SA, S_ENC, SEQ, HD, HD, HD, SEQ,
             (long long)SEQ * HD, (long long)SEQ * HD, (long long)S_ENC * SEQ, HEADS,
             ATTN_SCALE, nullptr, 0.f);
    softmax_k<SEQ><<<HEADS * S_ENC, 256>>>(SA);
    {
        dim3 g(HD / 64, S_ENC / 64, HEADS);
        gemm_av<<<g, 128, AV_SMEM>>>(SA, V, AOh, S_ENC, HD, SEQ, SEQ, HD, DIMN,
                                     (long long)S_ENC * SEQ, (long long)SEQ * HD, HD);
    }

    // 6) block B: cond queries vs cond keys (128x128)
    f16_big2(Qh + (long long)S_ENC * HD, Kh + (long long)S_ENC * HD, nullptr, SB,
             CONDN, CONDN, HD, HD, HD, CONDN,
             (long long)SEQ * HD, (long long)SEQ * HD, (long long)CONDN * CONDN, HEADS,
             ATTN_SCALE, nullptr, 0.f);
    softmax_k<CONDN><<<HEADS * CONDN, 256>>>(SB);
    {
        dim3 g(HD / 64, CONDN / 64, HEADS);
        gemm_av<<<g, 128, AV_SMEM>>>(SB, V + (long long)S_ENC * HD,
                                     AOh + (long long)S_ENC * DIMN,
                                     CONDN, HD, CONDN, CONDN, HD, DIMN,
                                     (long long)CONDN * CONDN, (long long)SEQ * HD, HD);
    }

    // 7) fully-masked rows -> uniform softmax -> mean of V; one out-proj row
    mean_part<<<dim3(HEADS, SCHUNK), HD>>>(V, mnP);
    mean_fin<<<DIMN / 256, 256>>>(mnP, mean);
    gemv_out<<<DIMN / 8, 256>>>(mean, Wo, bo, vec);

    // 8) output projections (hid -> 128x128, enc -> small)
    f16_big2(AOh + (long long)S_ENC * DIMN, hW + 6 * (long long)DIMN * DIMN, bo, out,
             CONDN, DIMN, DIMN, DIMN, DIMN, DIMN, 0, 0, 0, 1, 1.f, nullptr, 0.f);
    fill_rows<<<(NROWS_C * (DIMN / 4)) / 256, 256>>>(vec, out + (long long)CONDN * DIMN);
    f16_small(AOh, hW + 7 * (long long)DIMN * DIMN, boa, out + (long long)S_HID * DIMN,
              S_ENC, DIMN, DIMN, DIMN, DIMN, DIMN, 0, 0, 0, 1, 1.f, nullptr, 0.f);
}